// round 10
// baseline (speedup 1.0000x reference)
#include <cuda_runtime.h>
#include <cuda_bf16.h>
#include <stdint.h>
#include <math.h>

#define Dm   2048
#define Sm   512
#define Hn   16
#define HKVn 4
#define DHn  128
#define Fn   2048
#define En   8
#define QKVP 3072

// ---------------- scratch (device globals) ----------------
__device__ float g_qkv[Sm*QKVP];
__device__ float g_scores[Hn*Sm*Sm];
__device__ float g_h[Sm*Dm];
__device__ float g_x2f[Sm*Dm];
__device__ float g_gu[Sm*4096];
__device__ float g_sgu[Sm*4096];
__device__ float g_routed[Sm*Dm];
__device__ float g_shared[Sm*Dm];
__device__ int   g_topidx[Sm];
__device__ float g_topscore[Sm];
__device__ int   g_cnt[En];
__device__ int   g_list[En*Sm];

// activation bf16 hi/lo planes
__device__ __nv_bfloat16 x_h[Sm*Dm],  x_l[Sm*Dm];
__device__ __nv_bfloat16 at_h[Sm*Dm], at_l[Sm*Dm];
__device__ __nv_bfloat16 x2_h[Sm*Dm], x2_l[Sm*Dm];
__device__ __nv_bfloat16 ac_h[Sm*Dm], ac_l[Sm*Dm];
__device__ __nv_bfloat16 sa_h[Sm*Dm], sa_l[Sm*Dm];
// attention planes
__device__ __nv_bfloat16 q_h[Sm*Dm],  q_l[Sm*Dm];
__device__ __nv_bfloat16 k_h[Sm*512], k_l[Sm*512];
__device__ __nv_bfloat16 v_h[Sm*512], v_l[Sm*512];
__device__ __nv_bfloat16 p_h[Hn*Sm*Sm], p_l[Hn*Sm*Sm];

// ---------------- helpers ----------------
__device__ __forceinline__ uint32_t smem_u32(const void* p) {
    uint32_t a;
    asm("{ .reg .u64 t; cvta.to.shared.u64 t, %1; cvt.u32.u64 %0, t; }" : "=r"(a) : "l"(p));
    return a;
}
// a -> low element, b -> high element
__device__ __forceinline__ uint32_t pack_bf16x2(float a, float b) {
    uint32_t r;
    asm("cvt.rn.bf16x2.f32 %0, %1, %2;" : "=r"(r) : "f"(b), "f"(a));
    return r;
}
__device__ __forceinline__ void mma16816(float c[4], const uint32_t a[4], const uint32_t b[2]) {
    asm volatile(
        "mma.sync.aligned.m16n8k16.row.col.f32.bf16.bf16.f32 "
        "{%0,%1,%2,%3}, {%4,%5,%6,%7}, {%8,%9}, {%0,%1,%2,%3};"
        : "+f"(c[0]), "+f"(c[1]), "+f"(c[2]), "+f"(c[3])
        : "r"(a[0]), "r"(a[1]), "r"(a[2]), "r"(a[3]), "r"(b[0]), "r"(b[1]));
}
__device__ __forceinline__ void cpa16(uint32_t d, const void* s) {
    asm volatile("cp.async.cg.shared.global [%0], [%1], 16;" :: "r"(d), "l"(s));
}
#define CPA_COMMIT() asm volatile("cp.async.commit_group;" ::: "memory")
#define CPA_WAIT1()  asm volatile("cp.async.wait_group 1;" ::: "memory")
#define CPA_WAIT0()  asm volatile("cp.async.wait_group 0;" ::: "memory")
__device__ __forceinline__ void ldm_x4(uint32_t r[4], uint32_t a) {
    asm volatile("ldmatrix.sync.aligned.m8n8.x4.shared.b16 {%0,%1,%2,%3}, [%4];"
        : "=r"(r[0]), "=r"(r[1]), "=r"(r[2]), "=r"(r[3]) : "r"(a));
}
__device__ __forceinline__ void ldm_x4t(uint32_t r[4], uint32_t a) {
    asm volatile("ldmatrix.sync.aligned.m8n8.x4.trans.shared.b16 {%0,%1,%2,%3}, [%4];"
        : "=r"(r[0]), "=r"(r[1]), "=r"(r[2]), "=r"(r[3]) : "r"(a));
}
__device__ __forceinline__ void split_store(float v, __nv_bfloat16* ph, __nv_bfloat16* pl, size_t off) {
    __nv_bfloat16 h = __float2bfloat16(v);
    ph[off] = h;
    pl[off] = __float2bfloat16(v - __bfloat162float(h));
}

// =============== fp32-weight 3-pass HMMA GEMM, TMx128 tile, K=2048 ===============
// TM = 64 (256 thr, 2 CTA/SM) or 128 (512 thr, 1 CTA/SM).
#define KST 32
#define A_PITCH 40
#define BF32_PITCH 132
#define BF32_B (KST*BF32_PITCH*4)     // 16896
#define BB_PITCH 136
#define BB_PLANE_B (KST*BB_PITCH*2)   // 8704

template<int TM>
__global__ void __launch_bounds__(TM*4, 128/TM) tgemm_kernel(
    const __nv_bfloat16* __restrict__ aH, const __nv_bfloat16* __restrict__ aL,
    const float* __restrict__ B0, const float* __restrict__ B1, const float* __restrict__ B2,
    int ldb0, int ldb1, int ldb2, int ns1, int ns2,
    float* __restrict__ C, int ldc,
    const float* __restrict__ res, const float* __restrict__ rowscale, int gather)
{
    constexpr int THREADS   = TM * 4;
    constexpr int A_PLANE_B = TM * A_PITCH * 2;
    constexpr int A_BUF_B   = 2 * A_PLANE_B;
    constexpr int OFF_F0    = 2 * A_BUF_B;
    constexpr int OFF_F1    = OFF_F0 + BF32_B;
    constexpr int OFF_BH    = OFF_F1 + BF32_B;
    constexpr int OFF_BL    = OFF_BH + BB_PLANE_B;

    extern __shared__ char smc[];
    __shared__ int   tok[TM];
    __shared__ float scl[TM];
    int row0 = blockIdx.y * TM;
    int n0   = blockIdx.x * 128;
    int tid  = threadIdx.x;

    const float* Bsel; int ldbs; int ncol;
    if (n0 < ns1)      { Bsel = B0; ldbs = ldb0; ncol = n0; }
    else if (n0 < ns2) { Bsel = B1; ldbs = ldb1; ncol = n0 - ns1; }
    else               { Bsel = B2; ldbs = ldb2; ncol = n0 - ns2; }

    if (gather) {
        int e = blockIdx.z;
        int count = g_cnt[e];
        if (row0 >= count) return;
        Bsel += (size_t)e * 2048 * ldbs;
        if (tid < TM) {
            int r = row0 + tid;
            int t = (r < count) ? g_list[e * Sm + r] : -1;
            tok[tid] = t;
            scl[tid] = (t >= 0 && rowscale) ? rowscale[t] : 1.0f;
        }
    } else {
        if (tid < TM) { tok[tid] = row0 + tid; scl[tid] = 1.0f; }
    }
    __syncthreads();

    uint32_t smbase = smem_u32(smc);
    int lane = tid & 31, wid = tid >> 5;
    int gr = lane >> 2, tg = lane & 3;
    int wm = wid >> 2, wn = wid & 3;

    float acc[2][4][4];
#pragma unroll
    for (int i = 0; i < 2; i++)
#pragma unroll
        for (int j = 0; j < 4; j++)
#pragma unroll
            for (int r = 0; r < 4; r++) acc[i][j][r] = 0.f;

    int arow = tid >> 2, ach = tid & 3;
    int at = tok[arow];
    int agrow = at < 0 ? 0 : at;

    auto copy_stage = [&](int st) {
        uint32_t ab = smbase + ((st & 1) ? A_BUF_B : 0);
        uint32_t fb = smbase + ((st & 1) ? OFF_F1 : OFF_F0);
        int k0 = st * KST;
        cpa16(ab + (uint32_t)(arow * A_PITCH + ach * 8) * 2,
              aH + (size_t)agrow * 2048 + k0 + ach * 8);
        cpa16(ab + A_PLANE_B + (uint32_t)(arow * A_PITCH + ach * 8) * 2,
              aL + (size_t)agrow * 2048 + k0 + ach * 8);
#pragma unroll
        for (int it = 0; it < 1024 / THREADS; it++) {
            int chunk = it * THREADS + tid;
            int k = chunk >> 5, c4 = chunk & 31;
            cpa16(fb + (uint32_t)(k * BF32_PITCH + c4 * 4) * 4,
                  Bsel + (size_t)(k0 + k) * ldbs + ncol + c4 * 4);
        }
        CPA_COMMIT();
    };

    copy_stage(0);
    int lr = lane & 15;
    int lc8 = (lane & 16) >> 1;

    for (int st = 0; st < 64; st++) {
        CPA_WAIT0();
        __syncthreads();

        // ---- convert B fp32 -> bf16 hi/lo planes ----
        {
            const float* fb = (const float*)(smc + ((st & 1) ? OFF_F1 : OFF_F0));
            __nv_bfloat16* bh = (__nv_bfloat16*)(smc + OFF_BH);
            __nv_bfloat16* bl = (__nv_bfloat16*)(smc + OFF_BL);
#pragma unroll
            for (int it = 0; it < 1024 / THREADS; it++) {
                int chunk = it * THREADS + tid;
                int k = chunk >> 5, c4 = chunk & 31;
                float4 v = *(const float4*)(fb + k * BF32_PITCH + c4 * 4);
                uint32_t h01 = pack_bf16x2(v.x, v.y);
                uint32_t h23 = pack_bf16x2(v.z, v.w);
                uint32_t l01 = pack_bf16x2(v.x - __uint_as_float(h01 << 16),
                                           v.y - __uint_as_float(h01 & 0xffff0000u));
                uint32_t l23 = pack_bf16x2(v.z - __uint_as_float(h23 << 16),
                                           v.w - __uint_as_float(h23 & 0xffff0000u));
                int o = k * BB_PITCH + c4 * 4;
                *(uint2*)(bh + o) = make_uint2(h01, h23);
                *(uint2*)(bl + o) = make_uint2(l01, l23);
            }
        }
        if (st < 63) copy_stage(st + 1);
        __syncthreads();

        // ---- MMA: 2 k16 steps ----
        uint32_t ab = smbase + ((st & 1) ? A_BUF_B : 0);
        uint32_t AHb = ab, ALb = ab + A_PLANE_B;
        uint32_t BHb = smbase + OFF_BH, BLb = smbase + OFF_BL;
#pragma unroll
        for (int ks = 0; ks < 2; ks++) {
            uint32_t fAH[2][4], fAL[2][4], fBH[4][2], fBL[4][2];
#pragma unroll
            for (int mt = 0; mt < 2; mt++) {
                uint32_t ao = (uint32_t)((wm * 32 + mt * 16 + lr) * A_PITCH + ks * 16 + lc8) * 2;
                ldm_x4(fAH[mt], AHb + ao);
                ldm_x4(fAL[mt], ALb + ao);
            }
#pragma unroll
            for (int half = 0; half < 2; half++) {
                int brow = ks * 16 + lr;
                int bcol = wn * 32 + half * 16 + lc8;
                uint32_t bo = (uint32_t)(brow * BB_PITCH + bcol) * 2;
                uint32_t rH[4], rL[4];
                ldm_x4t(rH, BHb + bo);
                ldm_x4t(rL, BLb + bo);
                fBH[half*2][0] = rH[0]; fBH[half*2][1] = rH[1];
                fBH[half*2+1][0] = rH[2]; fBH[half*2+1][1] = rH[3];
                fBL[half*2][0] = rL[0]; fBL[half*2][1] = rL[1];
                fBL[half*2+1][0] = rL[2]; fBL[half*2+1][1] = rL[3];
            }
#pragma unroll
            for (int mt = 0; mt < 2; mt++)
#pragma unroll
                for (int nt = 0; nt < 4; nt++) {
                    mma16816(acc[mt][nt], fAH[mt], fBH[nt]);
                    mma16816(acc[mt][nt], fAH[mt], fBL[nt]);
                    mma16816(acc[mt][nt], fAL[mt], fBH[nt]);
                }
        }
    }

    // ---- epilogue ----
    __syncthreads();
#pragma unroll
    for (int mt = 0; mt < 2; mt++) {
        int r1 = wm * 32 + mt * 16 + gr;
        int r2 = r1 + 8;
        int t1 = tok[r1], t2 = tok[r2];
        float s1 = scl[r1], s2 = scl[r2];
#pragma unroll
        for (int nt = 0; nt < 4; nt++) {
            int col = n0 + wn * 32 + nt * 8 + tg * 2;
            if (t1 >= 0) {
                float2 o = make_float2(acc[mt][nt][0] * s1, acc[mt][nt][1] * s1);
                if (res) {
                    float2 rv = *(const float2*)(res + (size_t)t1 * ldc + col);
                    o.x += rv.x; o.y += rv.y;
                }
                *(float2*)(C + (size_t)t1 * ldc + col) = o;
            }
            if (t2 >= 0) {
                float2 o = make_float2(acc[mt][nt][2] * s2, acc[mt][nt][3] * s2);
                if (res) {
                    float2 rv = *(const float2*)(res + (size_t)t2 * ldc + col);
                    o.x += rv.x; o.y += rv.y;
                }
                *(float2*)(C + (size_t)t2 * ldc + col) = o;
            }
        }
    }
}

#define TG64_SMEM  (2*(2*64*A_PITCH*2)  + 2*BF32_B + 2*BB_PLANE_B)   // 71680
#define TG128_SMEM (2*(2*128*A_PITCH*2) + 2*BF32_B + 2*BB_PLANE_B)   // 92160

// =============== attention scores via HMMA (causal-skip) ===============
#define SC_SMEM (52224*2)

__global__ void __launch_bounds__(256, 2) scores_mma_kernel(
    const __nv_bfloat16* __restrict__ qh, const __nv_bfloat16* __restrict__ ql,
    const __nv_bfloat16* __restrict__ kh, const __nv_bfloat16* __restrict__ kl,
    float* __restrict__ sc)
{
    extern __shared__ __nv_bfloat16 smb[];
    int h = blockIdx.z;
    int row0 = blockIdx.y * 64;
    int n0 = blockIdx.x * 128;
    if (n0 >= row0 + 64) return;   // causal: block fully above diagonal
    int tid = threadIdx.x, lane = tid & 31, wid = tid >> 5;
    int gr = lane >> 2, tg = lane & 3;
    int wm = wid >> 2, wn = wid & 3;
    uint32_t base = smem_u32(smb);

#pragma unroll
    for (int pl = 0; pl < 2; pl++) {
        const __nv_bfloat16* src = pl ? ql : qh;
        uint32_t d0 = base + (pl ? 8704u : 0u) * 2;
#pragma unroll
        for (int it = 0; it < 4; it++) {
            int idx = it * 256 + tid;
            int r = idx >> 4, ch = idx & 15;
            cpa16(d0 + (uint32_t)(r * 136 + ch * 8) * 2,
                  src + (size_t)(row0 + r) * 2048 + h * 128 + ch * 8);
        }
    }
#pragma unroll
    for (int pl = 0; pl < 2; pl++) {
        const __nv_bfloat16* src = pl ? kl : kh;
        uint32_t d0 = base + (pl ? 34816u : 17408u) * 2;
#pragma unroll
        for (int it = 0; it < 8; it++) {
            int idx = it * 256 + tid;
            int r = idx >> 4, ch = idx & 15;
            cpa16(d0 + (uint32_t)(r * 136 + ch * 8) * 2,
                  src + (size_t)(n0 + r) * 512 + (h >> 2) * 128 + ch * 8);
        }
    }
    CPA_COMMIT(); CPA_WAIT0();
    __syncthreads();

    float acc[2][4][4];
#pragma unroll
    for (int i = 0; i < 2; i++)
#pragma unroll
        for (int j = 0; j < 4; j++)
#pragma unroll
            for (int r = 0; r < 4; r++) acc[i][j][r] = 0.f;

    int lr = lane & 15, lc8 = (lane & 16) >> 1;
    uint32_t QHb = base, QLb = base + 17408;
    uint32_t KHb = base + 34816, KLb = base + 69632;

#pragma unroll
    for (int ks = 0; ks < 8; ks++) {
        uint32_t fAH[2][4], fAL[2][4], fBH[4][2], fBL[4][2];
#pragma unroll
        for (int mt = 0; mt < 2; mt++) {
            uint32_t ao = (uint32_t)((wm * 32 + mt * 16 + lr) * 136 + ks * 16 + lc8) * 2;
            ldm_x4(fAH[mt], QHb + ao);
            ldm_x4(fAL[mt], QLb + ao);
        }
#pragma unroll
        for (int half = 0; half < 2; half++) {
            uint32_t bo = (uint32_t)((wn * 32 + half * 16 + lr) * 136 + ks * 16 + lc8) * 2;
            uint32_t rH[4], rL[4];
            ldm_x4(rH, KHb + bo);
            ldm_x4(rL, KLb + bo);
            fBH[half*2][0] = rH[0]; fBH[half*2][1] = rH[2];
            fBH[half*2+1][0] = rH[1]; fBH[half*2+1][1] = rH[3];
            fBL[half*2][0] = rL[0]; fBL[half*2][1] = rL[2];
            fBL[half*2+1][0] = rL[1]; fBL[half*2+1][1] = rL[3];
        }
#pragma unroll
        for (int mt = 0; mt < 2; mt++)
#pragma unroll
            for (int nt = 0; nt < 4; nt++) {
                mma16816(acc[mt][nt], fAH[mt], fBH[nt]);
                mma16816(acc[mt][nt], fAH[mt], fBL[nt]);
                mma16816(acc[mt][nt], fAL[mt], fBH[nt]);
            }
    }

    const float scale = 0.0883883476483184405f;
    float* out = sc + (size_t)h * Sm * Sm;
#pragma unroll
    for (int mt = 0; mt < 2; mt++) {
        int r1 = row0 + wm * 32 + mt * 16 + gr;
        int r2 = r1 + 8;
#pragma unroll
        for (int nt = 0; nt < 4; nt++) {
            int col = n0 + wn * 32 + nt * 8 + tg * 2;
            *(float2*)(out + (size_t)r1 * Sm + col) =
                make_float2(acc[mt][nt][0] * scale, acc[mt][nt][1] * scale);
            *(float2*)(out + (size_t)r2 * Sm + col) =
                make_float2(acc[mt][nt][2] * scale, acc[mt][nt][3] * scale);
        }
    }
}

// =============== PV via HMMA (causal-truncated K loop) ===============
#define PV_STAGE_B (26624*2)
#define PV_SMEM (2*PV_STAGE_B)

__global__ void __launch_bounds__(256, 2) pv_mma_kernel(
    const __nv_bfloat16* __restrict__ ph_, const __nv_bfloat16* __restrict__ pl_,
    const __nv_bfloat16* __restrict__ vh, const __nv_bfloat16* __restrict__ vl,
    __nv_bfloat16* __restrict__ outh, __nv_bfloat16* __restrict__ outl)
{
    extern __shared__ __nv_bfloat16 smb[];
    int h = blockIdx.y;
    int row0 = blockIdx.x * 64;
    int nst = blockIdx.x + 1;        // causal: p[i][j]=0 for j > i
    int kvoff = (h >> 2) * 128;
    int tid = threadIdx.x, lane = tid & 31, wid = tid >> 5;
    int gr = lane >> 2, tg = lane & 3;
    int wm = wid >> 2, wn = wid & 3;
    uint32_t smbase = smem_u32(smb);

    float acc[2][4][4];
#pragma unroll
    for (int i = 0; i < 2; i++)
#pragma unroll
        for (int j = 0; j < 4; j++)
#pragma unroll
            for (int r = 0; r < 4; r++) acc[i][j][r] = 0.f;

    auto copy_stage = [&](int st) {
        uint32_t base = smbase + (uint32_t)(st & 1) * PV_STAGE_B;
        int k0 = st * 64;
#pragma unroll
        for (int pl = 0; pl < 2; pl++) {
            const __nv_bfloat16* asrc = pl ? pl_ : ph_;
            uint32_t d0 = base + (pl ? 4608 : 0) * 2;
#pragma unroll
            for (int it = 0; it < 2; it++) {
                int idx = it * 256 + tid;
                int row = idx >> 3, ch = idx & 7;
                cpa16(d0 + (uint32_t)(row * 72 + ch * 8) * 2,
                      asrc + ((size_t)h * Sm + row0 + row) * Sm + k0 + ch * 8);
            }
        }
#pragma unroll
        for (int pl = 0; pl < 2; pl++) {
            const __nv_bfloat16* bsrc = pl ? vl : vh;
            uint32_t d0 = base + (pl ? 17920 : 9216) * 2;
#pragma unroll
            for (int it = 0; it < 4; it++) {
                int idx = it * 256 + tid;
                int row = idx >> 4, ch = idx & 15;
                cpa16(d0 + (uint32_t)(row * 136 + ch * 8) * 2,
                      bsrc + (size_t)(k0 + row) * 512 + kvoff + ch * 8);
            }
        }
        CPA_COMMIT();
    };

    copy_stage(0);
    int lr = lane & 15, lc8 = (lane & 16) >> 1;

    for (int st = 0; st < nst; st++) {
        if (st + 1 < nst) { copy_stage(st + 1); CPA_WAIT1(); }
        else              { CPA_WAIT0(); }
        __syncthreads();
        uint32_t base = smbase + (uint32_t)(st & 1) * PV_STAGE_B;
        uint32_t AHb = base, ALb = base + 9216;
        uint32_t BHb = base + 18432, BLb = base + 35840;
#pragma unroll
        for (int ks = 0; ks < 4; ks++) {
            uint32_t fAH[2][4], fAL[2][4], fBH[4][2], fBL[4][2];
#pragma unroll
            for (int mt = 0; mt < 2; mt++) {
                uint32_t ao = (uint32_t)((wm * 32 + mt * 16 + lr) * 72 + ks * 16 + lc8) * 2;
                ldm_x4(fAH[mt], AHb + ao);
                ldm_x4(fAL[mt], ALb + ao);
            }
#pragma unroll
            for (int half = 0; half < 2; half++) {
                uint32_t bo = (uint32_t)((ks * 16 + lr) * 136 + wn * 32 + half * 16 + lc8) * 2;
                uint32_t rH[4], rL[4];
                ldm_x4t(rH, BHb + bo);
                ldm_x4t(rL, BLb + bo);
                fBH[half*2][0] = rH[0]; fBH[half*2][1] = rH[1];
                fBH[half*2+1][0] = rH[2]; fBH[half*2+1][1] = rH[3];
                fBL[half*2][0] = rL[0]; fBL[half*2][1] = rL[1];
                fBL[half*2+1][0] = rL[2]; fBL[half*2+1][1] = rL[3];
            }
#pragma unroll
            for (int mt = 0; mt < 2; mt++)
#pragma unroll
                for (int nt = 0; nt < 4; nt++) {
                    mma16816(acc[mt][nt], fAH[mt], fBH[nt]);
                    mma16816(acc[mt][nt], fAH[mt], fBL[nt]);
                    mma16816(acc[mt][nt], fAL[mt], fBH[nt]);
                }
        }
        __syncthreads();
    }

#pragma unroll
    for (int mt = 0; mt < 2; mt++) {
        int r1 = row0 + wm * 32 + mt * 16 + gr;
        int r2 = r1 + 8;
#pragma unroll
        for (int nt = 0; nt < 4; nt++) {
            int col = h * 128 + wn * 32 + nt * 8 + tg * 2;
            float v0 = acc[mt][nt][0], v1 = acc[mt][nt][1];
            float v2 = acc[mt][nt][2], v3 = acc[mt][nt][3];
            uint32_t h01 = pack_bf16x2(v0, v1);
            uint32_t l01 = pack_bf16x2(v0 - __uint_as_float(h01 << 16),
                                       v1 - __uint_as_float(h01 & 0xffff0000u));
            uint32_t h23 = pack_bf16x2(v2, v3);
            uint32_t l23 = pack_bf16x2(v2 - __uint_as_float(h23 << 16),
                                       v3 - __uint_as_float(h23 & 0xffff0000u));
            *(uint32_t*)(outh + (size_t)r1 * 2048 + col) = h01;
            *(uint32_t*)(outl + (size_t)r1 * 2048 + col) = l01;
            *(uint32_t*)(outh + (size_t)r2 * 2048 + col) = h23;
            *(uint32_t*)(outl + (size_t)r2 * 2048 + col) = l23;
        }
    }
}

// ---------------- small kernels ----------------
__global__ void rmsnorm_kernel(const float* __restrict__ in, const float* __restrict__ w,
                               float* __restrict__ outf,
                               __nv_bfloat16* __restrict__ outh,
                               __nv_bfloat16* __restrict__ outl) {
    int t = blockIdx.x;
    const float* row = in + (size_t)t * Dm;
    float s = 0.f;
    for (int d = threadIdx.x; d < Dm; d += 256) { float v = row[d]; s += v * v; }
    __shared__ float red[256];
    red[threadIdx.x] = s; __syncthreads();
    for (int off = 128; off > 0; off >>= 1) {
        if (threadIdx.x < off) red[threadIdx.x] += red[threadIdx.x + off];
        __syncthreads();
    }
    float r = rsqrtf(red[0] / (float)Dm + 1e-5f);
    for (int d = threadIdx.x; d < Dm; d += 256) {
        float v = row[d] * r * w[d];
        if (outf) outf[(size_t)t * Dm + d] = v;
        split_store(v, outh, outl, (size_t)t * Dm + d);
    }
}

__global__ void rope_planes_kernel(const float* __restrict__ qkv, const int* __restrict__ pos_ids,
                                   __nv_bfloat16* qh, __nv_bfloat16* ql,
                                   __nv_bfloat16* kh, __nv_bfloat16* kl,
                                   __nv_bfloat16* vh, __nv_bfloat16* vl) {
    int t = blockIdx.x;
    float p = (float)pos_ids[t];
    for (int idx = threadIdx.x; idx < (Hn + HKVn) * 64; idx += blockDim.x) {
        int head = idx >> 6;
        int i = idx & 63;
        float inv = powf(500000.0f, -(float)i / 64.0f);
        float f = p * inv;
        float sn, cs;
        sincosf(f, &sn, &cs);
        if (head < Hn) {
            const float* src = qkv + (size_t)t * QKVP + head * DHn;
            float x1 = src[i], x2 = src[i + 64];
            size_t d = (size_t)t * Dm + head * DHn + i;
            split_store(x1 * cs - x2 * sn, qh, ql, d);
            split_store(x2 * cs + x1 * sn, qh, ql, d + 64);
        } else {
            int kvh = head - Hn;
            const float* src = qkv + (size_t)t * QKVP + 2048 + kvh * DHn;
            float x1 = src[i], x2 = src[i + 64];
            size_t d = (size_t)t * 512 + kvh * DHn + i;
            split_store(x1 * cs - x2 * sn, kh, kl, d);
            split_store(x2 * cs + x1 * sn, kh, kl, d + 64);
        }
    }
    for (int idx = threadIdx.x; idx < 512; idx += blockDim.x) {
        float v = qkv[(size_t)t * QKVP + 2560 + idx];
        split_store(v, vh, vl, (size_t)t * 512 + idx);
    }
}

__global__ void softmax_kernel(const float* __restrict__ sc, const int* __restrict__ mask,
                               __nv_bfloat16* __restrict__ ph, __nv_bfloat16* __restrict__ pl) {
    int i = blockIdx.x;
    int h = blockIdx.y;
    const float* row = sc + ((size_t)h * Sm + i) * Sm;
    int tid = threadIdx.x;
    int j0 = tid, j1 = tid + 256;
    float s0 = (j0 <= i && mask[j0] > 0) ? row[j0] : -1e9f;
    float s1 = (j1 <= i && mask[j1] > 0) ? row[j1] : -1e9f;
    __shared__ float red[256];
    red[tid] = fmaxf(s0, s1); __syncthreads();
    for (int off = 128; off > 0; off >>= 1) {
        if (tid < off) red[tid] = fmaxf(red[tid], red[tid + off]);
        __syncthreads();
    }
    float m = red[0];
    __syncthreads();
    float e0 = expf(s0 - m), e1 = expf(s1 - m);
    red[tid] = e0 + e1; __syncthreads();
    for (int off = 128; off > 0; off >>= 1) {
        if (tid < off) red[tid] += red[tid + off];
        __syncthreads();
    }
    float inv = 1.f / red[0];
    size_t base = ((size_t)h * Sm + i) * Sm;
    split_store(e0 * inv, ph, pl, base + j0);
    split_store(e1 * inv, ph, pl, base + j1);
}

__global__ void router_kernel(const float* __restrict__ x2, const float* __restrict__ rw,
                              int* __restrict__ topidx, float* __restrict__ topscore) {
    int t = blockIdx.x;
    int w = threadIdx.x >> 5, lane = threadIdx.x & 31;
    float s = 0.f;
    for (int d = lane; d < Dm; d += 32)
        s += x2[(size_t)t * Dm + d] * rw[d * En + w];
    for (int off = 16; off; off >>= 1) s += __shfl_down_sync(0xffffffff, s, off);
    __shared__ float logits[En];
    if (lane == 0) logits[w] = s;
    __syncthreads();
    if (threadIdx.x == 0) {
        int best = 0; float bv = logits[0];
        for (int e = 1; e < En; e++) if (logits[e] > bv) { bv = logits[e]; best = e; }
        topidx[t] = best;
        topscore[t] = 1.f / (1.f + expf(-bv));
    }
}

__global__ void dispatch_kernel(const int* __restrict__ topidx) {
    int t = threadIdx.x;
    if (t < En) g_cnt[t] = 0;
    __syncthreads();
    int e = topidx[t];
    int pos = atomicAdd(&g_cnt[e], 1);
    g_list[e * Sm + pos] = t;
}

__global__ void silumul_kernel(const float* __restrict__ gu,
                               __nv_bfloat16* __restrict__ outh,
                               __nv_bfloat16* __restrict__ outl) {
    int i = blockIdx.x * 256 + threadIdx.x;
    int t = i >> 11, j = i & 2047;
    float g = gu[(size_t)t * 4096 + j];
    float u = gu[(size_t)t * 4096 + 2048 + j];
    float a = (g / (1.f + expf(-g))) * u;
    split_store(a, outh, outl, (size_t)i);
}

__global__ void add3_kernel(const float* __restrict__ a, const float* __restrict__ b,
                            const float* __restrict__ c, float* __restrict__ out) {
    int i = blockIdx.x * 256 + threadIdx.x;
    out[i] = a[i] + b[i] + c[i];
}

// ---------------- launch ----------------
#define GSYM(p, s) cudaGetSymbolAddress((void**)&p, s)
#define NSBIG 0x40000000

extern "C" void kernel_launch(void* const* d_in, const int* in_sizes, int n_in,
                              void* d_out, int out_size) {
    const float* hidden   = (const float*)d_in[0];
    const int*   amask    = (const int*)  d_in[1];
    const int*   pos      = (const int*)  d_in[2];
    const float* attn_nw  = (const float*)d_in[3];
    const float* wq       = (const float*)d_in[4];
    const float* wk       = (const float*)d_in[5];
    const float* wv       = (const float*)d_in[6];
    const float* wo       = (const float*)d_in[7];
    const float* ffn_nw   = (const float*)d_in[8];
    const float* router_w = (const float*)d_in[9];
    const float* w_gate   = (const float*)d_in[10];
    const float* w_up     = (const float*)d_in[11];
    const float* w_down   = (const float*)d_in[12];
    const float* ws_gate  = (const float*)d_in[13];
    const float* ws_up    = (const float*)d_in[14];
    const float* ws_down  = (const float*)d_in[15];
    float* out = (float*)d_out;

    float *pqkv, *psc, *phf, *px2f, *pgu, *psgu, *prouted, *pshared, *pts;
    int *pti;
    __nv_bfloat16 *pxh, *pxl, *path, *patl, *px2h, *px2l, *pach, *pacl, *psah, *psal;
    __nv_bfloat16 *pqh, *pql, *pkh, *pkl, *pvh, *pvl, *pph, *ppl;
    GSYM(pqkv, g_qkv); GSYM(psc, g_scores); GSYM(phf, g_h); GSYM(px2f, g_x2f);
    GSYM(pgu, g_gu); GSYM(psgu, g_sgu); GSYM(prouted, g_routed); GSYM(pshared, g_shared);
    GSYM(pti, g_topidx); GSYM(pts, g_topscore);
    GSYM(pxh, x_h); GSYM(pxl, x_l); GSYM(path, at_h); GSYM(patl, at_l);
    GSYM(px2h, x2_h); GSYM(px2l, x2_l); GSYM(pach, ac_h); GSYM(pacl, ac_l);
    GSYM(psah, sa_h); GSYM(psal, sa_l);
    GSYM(pqh, q_h); GSYM(pql, q_l); GSYM(pkh, k_h); GSYM(pkl, k_l);
    GSYM(pvh, v_h); GSYM(pvl, v_l); GSYM(pph, p_h); GSYM(ppl, p_l);

    cudaFuncSetAttribute(tgemm_kernel<64>,  cudaFuncAttributeMaxDynamicSharedMemorySize, TG64_SMEM);
    cudaFuncSetAttribute(tgemm_kernel<128>, cudaFuncAttributeMaxDynamicSharedMemorySize, TG128_SMEM);
    cudaFuncSetAttribute(scores_mma_kernel, cudaFuncAttributeMaxDynamicSharedMemorySize, SC_SMEM);
    cudaFuncSetAttribute(pv_mma_kernel, cudaFuncAttributeMaxDynamicSharedMemorySize, PV_SMEM);

    // --- attention block ---
    rmsnorm_kernel<<<Sm, 256>>>(hidden, attn_nw, nullptr, pxh, pxl);
    tgemm_kernel<128><<<dim3(24, 4), 512, TG128_SMEM>>>(pxh, pxl, wq, wk, wv,
                                                2048, 512, 512, 2048, 2560,
                                                pqkv, 3072, nullptr, nullptr, 0);
    rope_planes_kernel<<<Sm, 256>>>(pqkv, pos, pqh, pql, pkh, pkl, pvh, pvl);
    scores_mma_kernel<<<dim3(4, 8, Hn), 256, SC_SMEM>>>(pqh, pql, pkh, pkl, psc);
    softmax_kernel<<<dim3(Sm, Hn), 256>>>(psc, amask, pph, ppl);
    pv_mma_kernel<<<dim3(8, Hn), 256, PV_SMEM>>>(pph, ppl, pvh, pvl, path, patl);
    tgemm_kernel<64><<<dim3(16, 8), 256, TG64_SMEM>>>(path, patl, wo, nullptr, nullptr,
                                                2048, 0, 0, NSBIG, NSBIG,
                                                phf, 2048, hidden, nullptr, 0);

    // --- MoE block ---
    rmsnorm_kernel<<<Sm, 256>>>(phf, ffn_nw, px2f, px2h, px2l);
    router_kernel<<<Sm, 256>>>(px2f, router_w, pti, pts);
    dispatch_kernel<<<1, Sm>>>(pti);
    tgemm_kernel<64><<<dim3(32, 8, En), 256, TG64_SMEM>>>(px2h, px2l, w_gate, w_up, nullptr,
                                                    2048, 2048, 0, 2048, NSBIG,
                                                    pgu, 4096, nullptr, pts, 1);
    silumul_kernel<<<(Sm * Dm) / 256, 256>>>(pgu, pach, pacl);
    tgemm_kernel<64><<<dim3(16, 8, En), 256, TG64_SMEM>>>(pach, pacl, w_down, nullptr, nullptr,
                                                    2048, 0, 0, NSBIG, NSBIG,
                                                    prouted, 2048, nullptr, nullptr, 1);

    // shared expert: gate|up fused
    tgemm_kernel<128><<<dim3(32, 4), 512, TG128_SMEM>>>(px2h, px2l, ws_gate, ws_up, nullptr,
                                                2048, 2048, 0, 2048, NSBIG,
                                                psgu, 4096, nullptr, nullptr, 0);
    silumul_kernel<<<(Sm * Dm) / 256, 256>>>(psgu, psah, psal);
    tgemm_kernel<64><<<dim3(16, 8), 256, TG64_SMEM>>>(psah, psal, ws_down, nullptr, nullptr,
                                                2048, 0, 0, NSBIG, NSBIG,
                                                pshared, 2048, nullptr, nullptr, 0);

    // final: out = h + routed + shared
    add3_kernel<<<(Sm * Dm) / 256, 256>>>(phf, prouted, pshared, out);
}

// round 11
// speedup vs baseline: 1.0275x; 1.0275x over previous
#include <cuda_runtime.h>
#include <cuda_bf16.h>
#include <stdint.h>
#include <math.h>

#define Dm   2048
#define Sm   512
#define Hn   16
#define HKVn 4
#define DHn  128
#define Fn   2048
#define En   8
#define QKVP 3072

// ---------------- scratch (device globals) ----------------
__device__ float g_qkv[Sm*QKVP];
__device__ float g_scores[Hn*Sm*Sm];
__device__ float g_h[Sm*Dm];
__device__ float g_x2f[Sm*Dm];
__device__ float g_gu[Sm*4096];
__device__ float g_sgu[Sm*4096];
__device__ float g_routed[Sm*Dm];
__device__ float g_shared[Sm*Dm];
__device__ int   g_topidx[Sm];
__device__ float g_topscore[Sm];
__device__ int   g_cnt[En];
__device__ int   g_list[En*Sm];

// activation bf16 hi/lo planes
__device__ __nv_bfloat16 x_h[Sm*Dm],  x_l[Sm*Dm];
__device__ __nv_bfloat16 at_h[Sm*Dm], at_l[Sm*Dm];
__device__ __nv_bfloat16 x2_h[Sm*Dm], x2_l[Sm*Dm];
__device__ __nv_bfloat16 ac_h[Sm*Dm], ac_l[Sm*Dm];
__device__ __nv_bfloat16 sa_h[Sm*Dm], sa_l[Sm*Dm];
// attention planes
__device__ __nv_bfloat16 q_h[Sm*Dm],  q_l[Sm*Dm];
__device__ __nv_bfloat16 k_h[Sm*512], k_l[Sm*512];
__device__ __nv_bfloat16 v_h[Sm*512], v_l[Sm*512];
__device__ __nv_bfloat16 p_h[Hn*Sm*Sm], p_l[Hn*Sm*Sm];

// ---------------- helpers ----------------
__device__ __forceinline__ uint32_t smem_u32(const void* p) {
    uint32_t a;
    asm("{ .reg .u64 t; cvta.to.shared.u64 t, %1; cvt.u32.u64 %0, t; }" : "=r"(a) : "l"(p));
    return a;
}
// a -> low element, b -> high element
__device__ __forceinline__ uint32_t pack_bf16x2(float a, float b) {
    uint32_t r;
    asm("cvt.rn.bf16x2.f32 %0, %1, %2;" : "=r"(r) : "f"(b), "f"(a));
    return r;
}
__device__ __forceinline__ void mma16816(float c[4], const uint32_t a[4], const uint32_t b[2]) {
    asm volatile(
        "mma.sync.aligned.m16n8k16.row.col.f32.bf16.bf16.f32 "
        "{%0,%1,%2,%3}, {%4,%5,%6,%7}, {%8,%9}, {%0,%1,%2,%3};"
        : "+f"(c[0]), "+f"(c[1]), "+f"(c[2]), "+f"(c[3])
        : "r"(a[0]), "r"(a[1]), "r"(a[2]), "r"(a[3]), "r"(b[0]), "r"(b[1]));
}
__device__ __forceinline__ void cpa16(uint32_t d, const void* s) {
    asm volatile("cp.async.cg.shared.global [%0], [%1], 16;" :: "r"(d), "l"(s));
}
#define CPA_COMMIT() asm volatile("cp.async.commit_group;" ::: "memory")
#define CPA_WAIT1()  asm volatile("cp.async.wait_group 1;" ::: "memory")
#define CPA_WAIT0()  asm volatile("cp.async.wait_group 0;" ::: "memory")
__device__ __forceinline__ void ldm_x4(uint32_t r[4], uint32_t a) {
    asm volatile("ldmatrix.sync.aligned.m8n8.x4.shared.b16 {%0,%1,%2,%3}, [%4];"
        : "=r"(r[0]), "=r"(r[1]), "=r"(r[2]), "=r"(r[3]) : "r"(a));
}
__device__ __forceinline__ void ldm_x4t(uint32_t r[4], uint32_t a) {
    asm volatile("ldmatrix.sync.aligned.m8n8.x4.trans.shared.b16 {%0,%1,%2,%3}, [%4];"
        : "=r"(r[0]), "=r"(r[1]), "=r"(r[2]), "=r"(r[3]) : "r"(a));
}
__device__ __forceinline__ void split_store(float v, __nv_bfloat16* ph, __nv_bfloat16* pl, size_t off) {
    __nv_bfloat16 h = __float2bfloat16(v);
    ph[off] = h;
    pl[off] = __float2bfloat16(v - __bfloat162float(h));
}

// =============== fp32-weight 3-pass HMMA GEMM, 64x128 tile, K=2048 ===============
#define KST 32
#define A_PITCH 40
#define A_PLANE_B (64*A_PITCH*2)      // 5120
#define A_BUF_B (2*A_PLANE_B)         // 10240
#define BF32_PITCH 132
#define BF32_B (KST*BF32_PITCH*4)     // 16896
#define BB_PITCH 136
#define BB_PLANE_B (KST*BB_PITCH*2)   // 8704
#define OFF_A0 0
#define OFF_A1 A_BUF_B
#define OFF_F0 (2*A_BUF_B)
#define OFF_F1 (OFF_F0 + BF32_B)
#define OFF_BH (OFF_F1 + BF32_B)
#define OFF_BL (OFF_BH + BB_PLANE_B)
#define TG_SMEM (OFF_BL + BB_PLANE_B)   // 71680

__global__ void __launch_bounds__(256, 2) tgemm_kernel(
    const __nv_bfloat16* __restrict__ aH, const __nv_bfloat16* __restrict__ aL,
    const float* __restrict__ B0, const float* __restrict__ B1, const float* __restrict__ B2,
    int ldb0, int ldb1, int ldb2, int ns1, int ns2,
    float* __restrict__ C, int ldc,
    const float* __restrict__ res, const float* __restrict__ rowscale, int gather)
{
    extern __shared__ char smc[];
    __shared__ int   tok[64];
    __shared__ float scl[64];
    int row0 = blockIdx.y * 64;
    int n0   = blockIdx.x * 128;
    int tid  = threadIdx.x;

    const float* Bsel; int ldbs; int ncol;
    if (n0 < ns1)      { Bsel = B0; ldbs = ldb0; ncol = n0; }
    else if (n0 < ns2) { Bsel = B1; ldbs = ldb1; ncol = n0 - ns1; }
    else               { Bsel = B2; ldbs = ldb2; ncol = n0 - ns2; }

    if (gather) {
        int e = blockIdx.z;
        int count = g_cnt[e];
        if (row0 >= count) return;
        Bsel += (size_t)e * 2048 * ldbs;
        if (tid < 64) {
            int r = row0 + tid;
            int t = (r < count) ? g_list[e * Sm + r] : -1;
            tok[tid] = t;
            scl[tid] = (t >= 0 && rowscale) ? rowscale[t] : 1.0f;
        }
    } else {
        if (tid < 64) { tok[tid] = row0 + tid; scl[tid] = 1.0f; }
    }
    __syncthreads();

    uint32_t smbase = smem_u32(smc);
    int lane = tid & 31, wid = tid >> 5;
    int gr = lane >> 2, tg = lane & 3;
    int wm = wid >> 2, wn = wid & 3;

    float acc[2][4][4];
#pragma unroll
    for (int i = 0; i < 2; i++)
#pragma unroll
        for (int j = 0; j < 4; j++)
#pragma unroll
            for (int r = 0; r < 4; r++) acc[i][j][r] = 0.f;

    int arow = tid >> 2, ach = tid & 3;
    int at = tok[arow];
    int agrow = at < 0 ? 0 : at;

    auto copy_stage = [&](int st) {
        uint32_t ab = smbase + ((st & 1) ? OFF_A1 : OFF_A0);
        uint32_t fb = smbase + ((st & 1) ? OFF_F1 : OFF_F0);
        int k0 = st * KST;
        cpa16(ab + (uint32_t)(arow * A_PITCH + ach * 8) * 2,
              aH + (size_t)agrow * 2048 + k0 + ach * 8);
        cpa16(ab + A_PLANE_B + (uint32_t)(arow * A_PITCH + ach * 8) * 2,
              aL + (size_t)agrow * 2048 + k0 + ach * 8);
#pragma unroll
        for (int it = 0; it < 4; it++) {
            int chunk = it * 256 + tid;
            int k = chunk >> 5, c4 = chunk & 31;
            cpa16(fb + (uint32_t)(k * BF32_PITCH + c4 * 4) * 4,
                  Bsel + (size_t)(k0 + k) * ldbs + ncol + c4 * 4);
        }
        CPA_COMMIT();
    };

    copy_stage(0);
    int lr = lane & 15;
    int lc8 = (lane & 16) >> 1;

    for (int st = 0; st < 64; st++) {
        CPA_WAIT0();
        __syncthreads();

        // ---- convert B fp32 -> bf16 hi/lo planes ----
        {
            const float* fb = (const float*)(smc + ((st & 1) ? OFF_F1 : OFF_F0));
            __nv_bfloat16* bh = (__nv_bfloat16*)(smc + OFF_BH);
            __nv_bfloat16* bl = (__nv_bfloat16*)(smc + OFF_BL);
#pragma unroll
            for (int it = 0; it < 4; it++) {
                int chunk = it * 256 + tid;
                int k = chunk >> 5, c4 = chunk & 31;
                float4 v = *(const float4*)(fb + k * BF32_PITCH + c4 * 4);
                uint32_t h01 = pack_bf16x2(v.x, v.y);
                uint32_t h23 = pack_bf16x2(v.z, v.w);
                uint32_t l01 = pack_bf16x2(v.x - __uint_as_float(h01 << 16),
                                           v.y - __uint_as_float(h01 & 0xffff0000u));
                uint32_t l23 = pack_bf16x2(v.z - __uint_as_float(h23 << 16),
                                           v.w - __uint_as_float(h23 & 0xffff0000u));
                int o = k * BB_PITCH + c4 * 4;
                *(uint2*)(bh + o) = make_uint2(h01, h23);
                *(uint2*)(bl + o) = make_uint2(l01, l23);
            }
        }
        if (st < 63) copy_stage(st + 1);
        __syncthreads();

        // ---- MMA: 2 k16 steps ----
        uint32_t ab = smbase + ((st & 1) ? OFF_A1 : OFF_A0);
        uint32_t AHb = ab, ALb = ab + A_PLANE_B;
        uint32_t BHb = smbase + OFF_BH, BLb = smbase + OFF_BL;
#pragma unroll
        for (int ks = 0; ks < 2; ks++) {
            uint32_t fAH[2][4], fAL[2][4], fBH[4][2], fBL[4][2];
#pragma unroll
            for (int mt = 0; mt < 2; mt++) {
                uint32_t ao = (uint32_t)((wm * 32 + mt * 16 + lr) * A_PITCH + ks * 16 + lc8) * 2;
                ldm_x4(fAH[mt], AHb + ao);
                ldm_x4(fAL[mt], ALb + ao);
            }
#pragma unroll
            for (int half = 0; half < 2; half++) {
                int brow = ks * 16 + lr;
                int bcol = wn * 32 + half * 16 + lc8;
                uint32_t bo = (uint32_t)(brow * BB_PITCH + bcol) * 2;
                uint32_t rH[4], rL[4];
                ldm_x4t(rH, BHb + bo);
                ldm_x4t(rL, BLb + bo);
                fBH[half*2][0] = rH[0]; fBH[half*2][1] = rH[1];
                fBH[half*2+1][0] = rH[2]; fBH[half*2+1][1] = rH[3];
                fBL[half*2][0] = rL[0]; fBL[half*2][1] = rL[1];
                fBL[half*2+1][0] = rL[2]; fBL[half*2+1][1] = rL[3];
            }
#pragma unroll
            for (int mt = 0; mt < 2; mt++)
#pragma unroll
                for (int nt = 0; nt < 4; nt++) {
                    mma16816(acc[mt][nt], fAH[mt], fBH[nt]);
                    mma16816(acc[mt][nt], fAH[mt], fBL[nt]);
                    mma16816(acc[mt][nt], fAL[mt], fBH[nt]);
                }
        }
    }

    // ---- epilogue ----
    __syncthreads();
#pragma unroll
    for (int mt = 0; mt < 2; mt++) {
        int r1 = wm * 32 + mt * 16 + gr;
        int r2 = r1 + 8;
        int t1 = tok[r1], t2 = tok[r2];
        float s1 = scl[r1], s2 = scl[r2];
#pragma unroll
        for (int nt = 0; nt < 4; nt++) {
            int col = n0 + wn * 32 + nt * 8 + tg * 2;
            if (t1 >= 0) {
                float2 o = make_float2(acc[mt][nt][0] * s1, acc[mt][nt][1] * s1);
                if (res) {
                    float2 rv = *(const float2*)(res + (size_t)t1 * ldc + col);
                    o.x += rv.x; o.y += rv.y;
                }
                *(float2*)(C + (size_t)t1 * ldc + col) = o;
            }
            if (t2 >= 0) {
                float2 o = make_float2(acc[mt][nt][2] * s2, acc[mt][nt][3] * s2);
                if (res) {
                    float2 rv = *(const float2*)(res + (size_t)t2 * ldc + col);
                    o.x += rv.x; o.y += rv.y;
                }
                *(float2*)(C + (size_t)t2 * ldc + col) = o;
            }
        }
    }
}

// =============== attention scores via HMMA (causal-skip) ===============
#define SC_SMEM (52224*2)

__global__ void __launch_bounds__(256, 2) scores_mma_kernel(
    const __nv_bfloat16* __restrict__ qh, const __nv_bfloat16* __restrict__ ql,
    const __nv_bfloat16* __restrict__ kh, const __nv_bfloat16* __restrict__ kl,
    float* __restrict__ sc)
{
    extern __shared__ __nv_bfloat16 smb[];
    int h = blockIdx.z;
    int row0 = blockIdx.y * 64;
    int n0 = blockIdx.x * 128;
    if (n0 >= row0 + 64) return;   // causal: block fully above diagonal
    int tid = threadIdx.x, lane = tid & 31, wid = tid >> 5;
    int gr = lane >> 2, tg = lane & 3;
    int wm = wid >> 2, wn = wid & 3;
    uint32_t base = smem_u32(smb);

#pragma unroll
    for (int pl = 0; pl < 2; pl++) {
        const __nv_bfloat16* src = pl ? ql : qh;
        uint32_t d0 = base + (pl ? 8704u : 0u) * 2;
#pragma unroll
        for (int it = 0; it < 4; it++) {
            int idx = it * 256 + tid;
            int r = idx >> 4, ch = idx & 15;
            cpa16(d0 + (uint32_t)(r * 136 + ch * 8) * 2,
                  src + (size_t)(row0 + r) * 2048 + h * 128 + ch * 8);
        }
    }
#pragma unroll
    for (int pl = 0; pl < 2; pl++) {
        const __nv_bfloat16* src = pl ? kl : kh;
        uint32_t d0 = base + (pl ? 34816u : 17408u) * 2;
#pragma unroll
        for (int it = 0; it < 8; it++) {
            int idx = it * 256 + tid;
            int r = idx >> 4, ch = idx & 15;
            cpa16(d0 + (uint32_t)(r * 136 + ch * 8) * 2,
                  src + (size_t)(n0 + r) * 512 + (h >> 2) * 128 + ch * 8);
        }
    }
    CPA_COMMIT(); CPA_WAIT0();
    __syncthreads();

    float acc[2][4][4];
#pragma unroll
    for (int i = 0; i < 2; i++)
#pragma unroll
        for (int j = 0; j < 4; j++)
#pragma unroll
            for (int r = 0; r < 4; r++) acc[i][j][r] = 0.f;

    int lr = lane & 15, lc8 = (lane & 16) >> 1;
    uint32_t QHb = base, QLb = base + 17408;
    uint32_t KHb = base + 34816, KLb = base + 69632;

#pragma unroll
    for (int ks = 0; ks < 8; ks++) {
        uint32_t fAH[2][4], fAL[2][4], fBH[4][2], fBL[4][2];
#pragma unroll
        for (int mt = 0; mt < 2; mt++) {
            uint32_t ao = (uint32_t)((wm * 32 + mt * 16 + lr) * 136 + ks * 16 + lc8) * 2;
            ldm_x4(fAH[mt], QHb + ao);
            ldm_x4(fAL[mt], QLb + ao);
        }
#pragma unroll
        for (int half = 0; half < 2; half++) {
            uint32_t bo = (uint32_t)((wn * 32 + half * 16 + lr) * 136 + ks * 16 + lc8) * 2;
            uint32_t rH[4], rL[4];
            ldm_x4(rH, KHb + bo);
            ldm_x4(rL, KLb + bo);
            fBH[half*2][0] = rH[0]; fBH[half*2][1] = rH[2];
            fBH[half*2+1][0] = rH[1]; fBH[half*2+1][1] = rH[3];
            fBL[half*2][0] = rL[0]; fBL[half*2][1] = rL[2];
            fBL[half*2+1][0] = rL[1]; fBL[half*2+1][1] = rL[3];
        }
#pragma unroll
        for (int mt = 0; mt < 2; mt++)
#pragma unroll
            for (int nt = 0; nt < 4; nt++) {
                mma16816(acc[mt][nt], fAH[mt], fBH[nt]);
                mma16816(acc[mt][nt], fAH[mt], fBL[nt]);
                mma16816(acc[mt][nt], fAL[mt], fBH[nt]);
            }
    }

    const float scale = 0.0883883476483184405f;
    float* out = sc + (size_t)h * Sm * Sm;
#pragma unroll
    for (int mt = 0; mt < 2; mt++) {
        int r1 = row0 + wm * 32 + mt * 16 + gr;
        int r2 = r1 + 8;
#pragma unroll
        for (int nt = 0; nt < 4; nt++) {
            int col = n0 + wn * 32 + nt * 8 + tg * 2;
            *(float2*)(out + (size_t)r1 * Sm + col) =
                make_float2(acc[mt][nt][0] * scale, acc[mt][nt][1] * scale);
            *(float2*)(out + (size_t)r2 * Sm + col) =
                make_float2(acc[mt][nt][2] * scale, acc[mt][nt][3] * scale);
        }
    }
}

// =============== PV via HMMA (causal-truncated K loop) ===============
#define PV_STAGE_B (26624*2)
#define PV_SMEM (2*PV_STAGE_B)

__global__ void __launch_bounds__(256, 2) pv_mma_kernel(
    const __nv_bfloat16* __restrict__ ph_, const __nv_bfloat16* __restrict__ pl_,
    const __nv_bfloat16* __restrict__ vh, const __nv_bfloat16* __restrict__ vl,
    __nv_bfloat16* __restrict__ outh, __nv_bfloat16* __restrict__ outl)
{
    extern __shared__ __nv_bfloat16 smb[];
    int h = blockIdx.y;
    int row0 = blockIdx.x * 64;
    int nst = blockIdx.x + 1;        // causal: p[i][j]=0 for j > i
    int kvoff = (h >> 2) * 128;
    int tid = threadIdx.x, lane = tid & 31, wid = tid >> 5;
    int gr = lane >> 2, tg = lane & 3;
    int wm = wid >> 2, wn = wid & 3;
    uint32_t smbase = smem_u32(smb);

    float acc[2][4][4];
#pragma unroll
    for (int i = 0; i < 2; i++)
#pragma unroll
        for (int j = 0; j < 4; j++)
#pragma unroll
            for (int r = 0; r < 4; r++) acc[i][j][r] = 0.f;

    auto copy_stage = [&](int st) {
        uint32_t base = smbase + (uint32_t)(st & 1) * PV_STAGE_B;
        int k0 = st * 64;
#pragma unroll
        for (int pl = 0; pl < 2; pl++) {
            const __nv_bfloat16* asrc = pl ? pl_ : ph_;
            uint32_t d0 = base + (pl ? 4608 : 0) * 2;
#pragma unroll
            for (int it = 0; it < 2; it++) {
                int idx = it * 256 + tid;
                int row = idx >> 3, ch = idx & 7;
                cpa16(d0 + (uint32_t)(row * 72 + ch * 8) * 2,
                      asrc + ((size_t)h * Sm + row0 + row) * Sm + k0 + ch * 8);
            }
        }
#pragma unroll
        for (int pl = 0; pl < 2; pl++) {
            const __nv_bfloat16* bsrc = pl ? vl : vh;
            uint32_t d0 = base + (pl ? 17920 : 9216) * 2;
#pragma unroll
            for (int it = 0; it < 4; it++) {
                int idx = it * 256 + tid;
                int row = idx >> 4, ch = idx & 15;
                cpa16(d0 + (uint32_t)(row * 136 + ch * 8) * 2,
                      bsrc + (size_t)(k0 + row) * 512 + kvoff + ch * 8);
            }
        }
        CPA_COMMIT();
    };

    copy_stage(0);
    int lr = lane & 15, lc8 = (lane & 16) >> 1;

    for (int st = 0; st < nst; st++) {
        if (st + 1 < nst) { copy_stage(st + 1); CPA_WAIT1(); }
        else              { CPA_WAIT0(); }
        __syncthreads();
        uint32_t base = smbase + (uint32_t)(st & 1) * PV_STAGE_B;
        uint32_t AHb = base, ALb = base + 9216;
        uint32_t BHb = base + 18432, BLb = base + 35840;
#pragma unroll
        for (int ks = 0; ks < 4; ks++) {
            uint32_t fAH[2][4], fAL[2][4], fBH[4][2], fBL[4][2];
#pragma unroll
            for (int mt = 0; mt < 2; mt++) {
                uint32_t ao = (uint32_t)((wm * 32 + mt * 16 + lr) * 72 + ks * 16 + lc8) * 2;
                ldm_x4(fAH[mt], AHb + ao);
                ldm_x4(fAL[mt], ALb + ao);
            }
#pragma unroll
            for (int half = 0; half < 2; half++) {
                uint32_t bo = (uint32_t)((ks * 16 + lr) * 136 + wn * 32 + half * 16 + lc8) * 2;
                uint32_t rH[4], rL[4];
                ldm_x4t(rH, BHb + bo);
                ldm_x4t(rL, BLb + bo);
                fBH[half*2][0] = rH[0]; fBH[half*2][1] = rH[1];
                fBH[half*2+1][0] = rH[2]; fBH[half*2+1][1] = rH[3];
                fBL[half*2][0] = rL[0]; fBL[half*2][1] = rL[1];
                fBL[half*2+1][0] = rL[2]; fBL[half*2+1][1] = rL[3];
            }
#pragma unroll
            for (int mt = 0; mt < 2; mt++)
#pragma unroll
                for (int nt = 0; nt < 4; nt++) {
                    mma16816(acc[mt][nt], fAH[mt], fBH[nt]);
                    mma16816(acc[mt][nt], fAH[mt], fBL[nt]);
                    mma16816(acc[mt][nt], fAL[mt], fBH[nt]);
                }
        }
        __syncthreads();
    }

#pragma unroll
    for (int mt = 0; mt < 2; mt++) {
        int r1 = row0 + wm * 32 + mt * 16 + gr;
        int r2 = r1 + 8;
#pragma unroll
        for (int nt = 0; nt < 4; nt++) {
            int col = h * 128 + wn * 32 + nt * 8 + tg * 2;
            float v0 = acc[mt][nt][0], v1 = acc[mt][nt][1];
            float v2 = acc[mt][nt][2], v3 = acc[mt][nt][3];
            uint32_t h01 = pack_bf16x2(v0, v1);
            uint32_t l01 = pack_bf16x2(v0 - __uint_as_float(h01 << 16),
                                       v1 - __uint_as_float(h01 & 0xffff0000u));
            uint32_t h23 = pack_bf16x2(v2, v3);
            uint32_t l23 = pack_bf16x2(v2 - __uint_as_float(h23 << 16),
                                       v3 - __uint_as_float(h23 & 0xffff0000u));
            *(uint32_t*)(outh + (size_t)r1 * 2048 + col) = h01;
            *(uint32_t*)(outl + (size_t)r1 * 2048 + col) = l01;
            *(uint32_t*)(outh + (size_t)r2 * 2048 + col) = h23;
            *(uint32_t*)(outl + (size_t)r2 * 2048 + col) = l23;
        }
    }
}

// ---------------- small kernels ----------------
__global__ void rmsnorm_kernel(const float* __restrict__ in, const float* __restrict__ w,
                               float* __restrict__ outf,
                               __nv_bfloat16* __restrict__ outh,
                               __nv_bfloat16* __restrict__ outl) {
    int t = blockIdx.x;
    const float* row = in + (size_t)t * Dm;
    float s = 0.f;
    for (int d = threadIdx.x; d < Dm; d += 256) { float v = row[d]; s += v * v; }
    __shared__ float red[256];
    red[threadIdx.x] = s; __syncthreads();
    for (int off = 128; off > 0; off >>= 1) {
        if (threadIdx.x < off) red[threadIdx.x] += red[threadIdx.x + off];
        __syncthreads();
    }
    float r = rsqrtf(red[0] / (float)Dm + 1e-5f);
    for (int d = threadIdx.x; d < Dm; d += 256) {
        float v = row[d] * r * w[d];
        if (outf) outf[(size_t)t * Dm + d] = v;
        split_store(v, outh, outl, (size_t)t * Dm + d);
    }
}

__global__ void rope_planes_kernel(const float* __restrict__ qkv, const int* __restrict__ pos_ids,
                                   __nv_bfloat16* qh, __nv_bfloat16* ql,
                                   __nv_bfloat16* kh, __nv_bfloat16* kl,
                                   __nv_bfloat16* vh, __nv_bfloat16* vl) {
    int t = blockIdx.x;
    float p = (float)pos_ids[t];
    for (int idx = threadIdx.x; idx < (Hn + HKVn) * 64; idx += blockDim.x) {
        int head = idx >> 6;
        int i = idx & 63;
        float inv = powf(500000.0f, -(float)i / 64.0f);
        float f = p * inv;
        float sn, cs;
        sincosf(f, &sn, &cs);
        if (head < Hn) {
            const float* src = qkv + (size_t)t * QKVP + head * DHn;
            float x1 = src[i], x2 = src[i + 64];
            size_t d = (size_t)t * Dm + head * DHn + i;
            split_store(x1 * cs - x2 * sn, qh, ql, d);
            split_store(x2 * cs + x1 * sn, qh, ql, d + 64);
        } else {
            int kvh = head - Hn;
            const float* src = qkv + (size_t)t * QKVP + 2048 + kvh * DHn;
            float x1 = src[i], x2 = src[i + 64];
            size_t d = (size_t)t * 512 + kvh * DHn + i;
            split_store(x1 * cs - x2 * sn, kh, kl, d);
            split_store(x2 * cs + x1 * sn, kh, kl, d + 64);
        }
    }
    for (int idx = threadIdx.x; idx < 512; idx += blockDim.x) {
        float v = qkv[(size_t)t * QKVP + 2560 + idx];
        split_store(v, vh, vl, (size_t)t * 512 + idx);
    }
}

__global__ void softmax_kernel(const float* __restrict__ sc, const int* __restrict__ mask,
                               __nv_bfloat16* __restrict__ ph, __nv_bfloat16* __restrict__ pl) {
    int i = blockIdx.x;
    int h = blockIdx.y;
    const float* row = sc + ((size_t)h * Sm + i) * Sm;
    int tid = threadIdx.x;
    int j0 = tid, j1 = tid + 256;
    float s0 = (j0 <= i && mask[j0] > 0) ? row[j0] : -1e9f;
    float s1 = (j1 <= i && mask[j1] > 0) ? row[j1] : -1e9f;
    __shared__ float red[256];
    red[tid] = fmaxf(s0, s1); __syncthreads();
    for (int off = 128; off > 0; off >>= 1) {
        if (tid < off) red[tid] = fmaxf(red[tid], red[tid + off]);
        __syncthreads();
    }
    float m = red[0];
    __syncthreads();
    float e0 = expf(s0 - m), e1 = expf(s1 - m);
    red[tid] = e0 + e1; __syncthreads();
    for (int off = 128; off > 0; off >>= 1) {
        if (tid < off) red[tid] += red[tid + off];
        __syncthreads();
    }
    float inv = 1.f / red[0];
    size_t base = ((size_t)h * Sm + i) * Sm;
    split_store(e0 * inv, ph, pl, base + j0);
    split_store(e1 * inv, ph, pl, base + j1);
}

__global__ void router_kernel(const float* __restrict__ x2, const float* __restrict__ rw,
                              int* __restrict__ topidx, float* __restrict__ topscore) {
    int t = blockIdx.x;
    int w = threadIdx.x >> 5, lane = threadIdx.x & 31;
    float s = 0.f;
    for (int d = lane; d < Dm; d += 32)
        s += x2[(size_t)t * Dm + d] * rw[d * En + w];
    for (int off = 16; off; off >>= 1) s += __shfl_down_sync(0xffffffff, s, off);
    __shared__ float logits[En];
    if (lane == 0) logits[w] = s;
    __syncthreads();
    if (threadIdx.x == 0) {
        int best = 0; float bv = logits[0];
        for (int e = 1; e < En; e++) if (logits[e] > bv) { bv = logits[e]; best = e; }
        topidx[t] = best;
        topscore[t] = 1.f / (1.f + expf(-bv));
    }
}

__global__ void dispatch_kernel(const int* __restrict__ topidx) {
    int t = threadIdx.x;
    if (t < En) g_cnt[t] = 0;
    __syncthreads();
    int e = topidx[t];
    int pos = atomicAdd(&g_cnt[e], 1);
    g_list[e * Sm + pos] = t;
}

__global__ void silumul_kernel(const float* __restrict__ gu,
                               __nv_bfloat16* __restrict__ outh,
                               __nv_bfloat16* __restrict__ outl) {
    int i = blockIdx.x * 256 + threadIdx.x;
    int t = i >> 11, j = i & 2047;
    float g = gu[(size_t)t * 4096 + j];
    float u = gu[(size_t)t * 4096 + 2048 + j];
    float a = (g / (1.f + expf(-g))) * u;
    split_store(a, outh, outl, (size_t)i);
}

__global__ void add3_kernel(const float* __restrict__ a, const float* __restrict__ b,
                            const float* __restrict__ c, float* __restrict__ out) {
    int i = blockIdx.x * 256 + threadIdx.x;
    out[i] = a[i] + b[i] + c[i];
}

// ---------------- launch ----------------
#define GSYM(p, s) cudaGetSymbolAddress((void**)&p, s)
#define NSBIG 0x40000000

extern "C" void kernel_launch(void* const* d_in, const int* in_sizes, int n_in,
                              void* d_out, int out_size) {
    const float* hidden   = (const float*)d_in[0];
    const int*   amask    = (const int*)  d_in[1];
    const int*   pos      = (const int*)  d_in[2];
    const float* attn_nw  = (const float*)d_in[3];
    const float* wq       = (const float*)d_in[4];
    const float* wk       = (const float*)d_in[5];
    const float* wv       = (const float*)d_in[6];
    const float* wo       = (const float*)d_in[7];
    const float* ffn_nw   = (const float*)d_in[8];
    const float* router_w = (const float*)d_in[9];
    const float* w_gate   = (const float*)d_in[10];
    const float* w_up     = (const float*)d_in[11];
    const float* w_down   = (const float*)d_in[12];
    const float* ws_gate  = (const float*)d_in[13];
    const float* ws_up    = (const float*)d_in[14];
    const float* ws_down  = (const float*)d_in[15];
    float* out = (float*)d_out;

    float *pqkv, *psc, *phf, *px2f, *pgu, *psgu, *prouted, *pshared, *pts;
    int *pti;
    __nv_bfloat16 *pxh, *pxl, *path, *patl, *px2h, *px2l, *pach, *pacl, *psah, *psal;
    __nv_bfloat16 *pqh, *pql, *pkh, *pkl, *pvh, *pvl, *pph, *ppl;
    GSYM(pqkv, g_qkv); GSYM(psc, g_scores); GSYM(phf, g_h); GSYM(px2f, g_x2f);
    GSYM(pgu, g_gu); GSYM(psgu, g_sgu); GSYM(prouted, g_routed); GSYM(pshared, g_shared);
    GSYM(pti, g_topidx); GSYM(pts, g_topscore);
    GSYM(pxh, x_h); GSYM(pxl, x_l); GSYM(path, at_h); GSYM(patl, at_l);
    GSYM(px2h, x2_h); GSYM(px2l, x2_l); GSYM(pach, ac_h); GSYM(pacl, ac_l);
    GSYM(psah, sa_h); GSYM(psal, sa_l);
    GSYM(pqh, q_h); GSYM(pql, q_l); GSYM(pkh, k_h); GSYM(pkl, k_l);
    GSYM(pvh, v_h); GSYM(pvl, v_l); GSYM(pph, p_h); GSYM(ppl, p_l);

    cudaFuncSetAttribute(tgemm_kernel, cudaFuncAttributeMaxDynamicSharedMemorySize, TG_SMEM);
    cudaFuncSetAttribute(scores_mma_kernel, cudaFuncAttributeMaxDynamicSharedMemorySize, SC_SMEM);
    cudaFuncSetAttribute(pv_mma_kernel, cudaFuncAttributeMaxDynamicSharedMemorySize, PV_SMEM);

    // --- attention block ---
    rmsnorm_kernel<<<Sm, 256>>>(hidden, attn_nw, nullptr, pxh, pxl);
    tgemm_kernel<<<dim3(24, 8), 256, TG_SMEM>>>(pxh, pxl, wq, wk, wv,
                                                2048, 512, 512, 2048, 2560,
                                                pqkv, 3072, nullptr, nullptr, 0);
    rope_planes_kernel<<<Sm, 256>>>(pqkv, pos, pqh, pql, pkh, pkl, pvh, pvl);
    scores_mma_kernel<<<dim3(4, 8, Hn), 256, SC_SMEM>>>(pqh, pql, pkh, pkl, psc);
    softmax_kernel<<<dim3(Sm, Hn), 256>>>(psc, amask, pph, ppl);
    pv_mma_kernel<<<dim3(8, Hn), 256, PV_SMEM>>>(pph, ppl, pvh, pvl, path, patl);
    tgemm_kernel<<<dim3(16, 8), 256, TG_SMEM>>>(path, patl, wo, nullptr, nullptr,
                                                2048, 0, 0, NSBIG, NSBIG,
                                                phf, 2048, hidden, nullptr, 0);

    // --- MoE block ---
    rmsnorm_kernel<<<Sm, 256>>>(phf, ffn_nw, px2f, px2h, px2l);
    router_kernel<<<Sm, 256>>>(px2f, router_w, pti, pts);
    dispatch_kernel<<<1, Sm>>>(pti);
    tgemm_kernel<<<dim3(32, 8, En), 256, TG_SMEM>>>(px2h, px2l, w_gate, w_up, nullptr,
                                                    2048, 2048, 0, 2048, NSBIG,
                                                    pgu, 4096, nullptr, pts, 1);
    silumul_kernel<<<(Sm * Dm) / 256, 256>>>(pgu, pach, pacl);
    tgemm_kernel<<<dim3(16, 8, En), 256, TG_SMEM>>>(pach, pacl, w_down, nullptr, nullptr,
                                                    2048, 0, 0, NSBIG, NSBIG,
                                                    prouted, 2048, nullptr, nullptr, 1);

    // shared expert: gate|up fused
    tgemm_kernel<<<dim3(32, 8), 256, TG_SMEM>>>(px2h, px2l, ws_gate, ws_up, nullptr,
                                                2048, 2048, 0, 2048, NSBIG,
                                                psgu, 4096, nullptr, nullptr, 0);
    silumul_kernel<<<(Sm * Dm) / 256, 256>>>(psgu, psah, psal);
    tgemm_kernel<<<dim3(16, 8), 256, TG_SMEM>>>(psah, psal, ws_down, nullptr, nullptr,
                                                2048, 0, 0, NSBIG, NSBIG,
                                                pshared, 2048, nullptr, nullptr, 0);

    // final: out = h + routed + shared
    add3_kernel<<<(Sm * Dm) / 256, 256>>>(phf, prouted, pshared, out);
}

// round 12
// speedup vs baseline: 1.2808x; 1.2466x over previous
#include <cuda_runtime.h>
#include <cuda_bf16.h>
#include <stdint.h>
#include <math.h>

#define Dm   2048
#define Sm   512
#define Hn   16
#define HKVn 4
#define DHn  128
#define Fn   2048
#define En   8
#define QKVP 3072

// ---------------- scratch (device globals) ----------------
__device__ float g_qkv[Sm*QKVP];
__device__ float g_scores[Hn*Sm*Sm];
__device__ float g_h[Sm*Dm];
__device__ float g_x2f[Sm*Dm];
__device__ float g_gu[Sm*4096];
__device__ float g_sgu[Sm*4096];
__device__ float g_routed[Sm*Dm];
__device__ float g_shared[Sm*Dm];
__device__ int   g_topidx[Sm];
__device__ float g_topscore[Sm];
__device__ int   g_cnt[En];
__device__ int   g_list[En*Sm];

// activation bf16 hi/lo planes
__device__ __nv_bfloat16 x_h[Sm*Dm],  x_l[Sm*Dm];
__device__ __nv_bfloat16 at_h[Sm*Dm], at_l[Sm*Dm];
__device__ __nv_bfloat16 x2_h[Sm*Dm], x2_l[Sm*Dm];
__device__ __nv_bfloat16 ac_h[Sm*Dm], ac_l[Sm*Dm];
__device__ __nv_bfloat16 sa_h[Sm*Dm], sa_l[Sm*Dm];
// attention planes
__device__ __nv_bfloat16 q_h[Sm*Dm],  q_l[Sm*Dm];
__device__ __nv_bfloat16 k_h[Sm*512], k_l[Sm*512];
__device__ __nv_bfloat16 v_h[Sm*512], v_l[Sm*512];
__device__ __nv_bfloat16 p_h[Hn*Sm*Sm], p_l[Hn*Sm*Sm];

// ---------------- helpers ----------------
__device__ __forceinline__ uint32_t smem_u32(const void* p) {
    uint32_t a;
    asm("{ .reg .u64 t; cvta.to.shared.u64 t, %1; cvt.u32.u64 %0, t; }" : "=r"(a) : "l"(p));
    return a;
}
// a -> low element, b -> high element
__device__ __forceinline__ uint32_t pack_bf16x2(float a, float b) {
    uint32_t r;
    asm("cvt.rn.bf16x2.f32 %0, %1, %2;" : "=r"(r) : "f"(b), "f"(a));
    return r;
}
__device__ __forceinline__ void mma16816(float c[4], const uint32_t a[4], const uint32_t b[2]) {
    asm volatile(
        "mma.sync.aligned.m16n8k16.row.col.f32.bf16.bf16.f32 "
        "{%0,%1,%2,%3}, {%4,%5,%6,%7}, {%8,%9}, {%0,%1,%2,%3};"
        : "+f"(c[0]), "+f"(c[1]), "+f"(c[2]), "+f"(c[3])
        : "r"(a[0]), "r"(a[1]), "r"(a[2]), "r"(a[3]), "r"(b[0]), "r"(b[1]));
}
__device__ __forceinline__ void cpa16(uint32_t d, const void* s) {
    asm volatile("cp.async.cg.shared.global [%0], [%1], 16;" :: "r"(d), "l"(s));
}
#define CPA_COMMIT() asm volatile("cp.async.commit_group;" ::: "memory")
#define CPA_WAIT1()  asm volatile("cp.async.wait_group 1;" ::: "memory")
#define CPA_WAIT0()  asm volatile("cp.async.wait_group 0;" ::: "memory")
__device__ __forceinline__ void ldm_x4(uint32_t r[4], uint32_t a) {
    asm volatile("ldmatrix.sync.aligned.m8n8.x4.shared.b16 {%0,%1,%2,%3}, [%4];"
        : "=r"(r[0]), "=r"(r[1]), "=r"(r[2]), "=r"(r[3]) : "r"(a));
}
__device__ __forceinline__ void ldm_x4t(uint32_t r[4], uint32_t a) {
    asm volatile("ldmatrix.sync.aligned.m8n8.x4.trans.shared.b16 {%0,%1,%2,%3}, [%4];"
        : "=r"(r[0]), "=r"(r[1]), "=r"(r[2]), "=r"(r[3]) : "r"(a));
}
__device__ __forceinline__ void split_store(float v, __nv_bfloat16* ph, __nv_bfloat16* pl, size_t off) {
    __nv_bfloat16 h = __float2bfloat16(v);
    ph[off] = h;
    pl[off] = __float2bfloat16(v - __bfloat162float(h));
}

// =============== fp32-weight 3-pass HMMA GEMM, 64x128 tile, K=2048 ===============
// B: LDG fp32 -> regs (1-stage prefetch) -> convert -> STS bf16 hi/lo (double buf)
// A: cp.async bf16 planes (triple buf). ONE barrier per 32-k stage.
#define KST 32
#define A_PITCH 40
#define A_PLANE_B (64*A_PITCH*2)      // 5120
#define A_BUF_B (2*A_PLANE_B)         // 10240 (hi+lo)
#define BB_PITCH 136
#define BB_PLANE_B (KST*BB_PITCH*2)   // 8704
#define OFF_BB (3*A_BUF_B)            // 30720
#define TG_SMEM (OFF_BB + 2*2*BB_PLANE_B)  // 65536

__global__ void __launch_bounds__(256, 2) tgemm_kernel(
    const __nv_bfloat16* __restrict__ aH, const __nv_bfloat16* __restrict__ aL,
    const float* __restrict__ B0, const float* __restrict__ B1,
    int ldb0, int ldb1, int ns1,
    float* __restrict__ C, int ldc,
    const float* __restrict__ res, const float* __restrict__ rowscale, int mode,
    const __nv_bfloat16* __restrict__ sAh, const __nv_bfloat16* __restrict__ sAl,
    const float* __restrict__ sB0, const float* __restrict__ sB1,
    float* __restrict__ sC)
{
    extern __shared__ char smc[];
    __shared__ int   tok[64];
    __shared__ float scl[64];
    int row0 = blockIdx.y * 64;
    int n0   = blockIdx.x * 128;
    int tid  = threadIdx.x;

    int gather = mode;
    if (mode == 1 && blockIdx.z == En) {
        // shared-expert branch: dense rows, alternate A/B/C
        aH = sAh; aL = sAl; B0 = sB0; B1 = sB1; C = sC;
        rowscale = nullptr;
        gather = 0;
    }

    const float* Bsel; int ldbs; int ncol;
    if (n0 < ns1) { Bsel = B0; ldbs = ldb0; ncol = n0; }
    else          { Bsel = B1; ldbs = ldb1; ncol = n0 - ns1; }

    if (gather) {
        int e = blockIdx.z;
        int count = g_cnt[e];
        if (row0 >= count) return;
        Bsel += (size_t)e * 2048 * ldbs;
        if (tid < 64) {
            int r = row0 + tid;
            int t = (r < count) ? g_list[e * Sm + r] : -1;
            tok[tid] = t;
            scl[tid] = (t >= 0 && rowscale) ? rowscale[t] : 1.0f;
        }
    } else {
        if (tid < 64) { tok[tid] = row0 + tid; scl[tid] = 1.0f; }
    }
    __syncthreads();

    uint32_t smbase = smem_u32(smc);
    int lane = tid & 31, wid = tid >> 5;
    int gr = lane >> 2, tg = lane & 3;
    int wm = wid >> 2, wn = wid & 3;

    float acc[2][4][4];
#pragma unroll
    for (int i = 0; i < 2; i++)
#pragma unroll
        for (int j = 0; j < 4; j++)
#pragma unroll
            for (int r = 0; r < 4; r++) acc[i][j][r] = 0.f;

    int arow = tid >> 2, ach = tid & 3;
    int at = tok[arow];
    int agrow = at < 0 ? 0 : at;

    // B chunk mapping: chunk = it*256+tid -> k = chunk>>5 (0..31), c4 = chunk&31
    int bk[4], bc[4];
#pragma unroll
    for (int it = 0; it < 4; it++) {
        int chunk = it * 256 + tid;
        bk[it] = chunk >> 5;
        bc[it] = (chunk & 31) * 4;
    }

    auto copy_A = [&](int st) {
        uint32_t ab = smbase + (uint32_t)(st % 3) * A_BUF_B;
        int k0 = st * KST;
        cpa16(ab + (uint32_t)(arow * A_PITCH + ach * 8) * 2,
              aH + (size_t)agrow * 2048 + k0 + ach * 8);
        cpa16(ab + A_PLANE_B + (uint32_t)(arow * A_PITCH + ach * 8) * 2,
              aL + (size_t)agrow * 2048 + k0 + ach * 8);
        CPA_COMMIT();
    };

    float4 va[4];
    auto ldg_B = [&](int st) {
        int k0 = st * KST;
#pragma unroll
        for (int it = 0; it < 4; it++)
            va[it] = *(const float4*)(Bsel + (size_t)(k0 + bk[it]) * ldbs + ncol + bc[it]);
    };

    // prologue
    ldg_B(0);
    copy_A(0);

    int lr = lane & 15;
    int lc8 = (lane & 16) >> 1;

    for (int st = 0; st < 64; st++) {
        // convert B(st) from regs -> BB[st&1]
        {
            __nv_bfloat16* bh = (__nv_bfloat16*)(smc + OFF_BB + (st & 1) * (2 * BB_PLANE_B));
            __nv_bfloat16* bl = (__nv_bfloat16*)((char*)bh + BB_PLANE_B);
#pragma unroll
            for (int it = 0; it < 4; it++) {
                float4 v = va[it];
                uint32_t h01 = pack_bf16x2(v.x, v.y);
                uint32_t h23 = pack_bf16x2(v.z, v.w);
                uint32_t l01 = pack_bf16x2(v.x - __uint_as_float(h01 << 16),
                                           v.y - __uint_as_float(h01 & 0xffff0000u));
                uint32_t l23 = pack_bf16x2(v.z - __uint_as_float(h23 << 16),
                                           v.w - __uint_as_float(h23 & 0xffff0000u));
                int o = bk[it] * BB_PITCH + bc[it];
                *(uint2*)(bh + o) = make_uint2(h01, h23);
                *(uint2*)(bl + o) = make_uint2(l01, l23);
            }
        }
        if (st < 63) {
            ldg_B(st + 1);
            copy_A(st + 1);
            CPA_WAIT1();          // A(st) arrived; A(st+1) may be in flight
        } else {
            CPA_WAIT0();
        }
        __syncthreads();          // BB[st&1] + A(st) visible to all

        // ---- MMA: 2 k16 steps ----
        uint32_t ab = smbase + (uint32_t)(st % 3) * A_BUF_B;
        uint32_t AHb = ab, ALb = ab + A_PLANE_B;
        uint32_t BHb = smbase + OFF_BB + (uint32_t)(st & 1) * (2 * BB_PLANE_B);
        uint32_t BLb = BHb + BB_PLANE_B;
#pragma unroll
        for (int ks = 0; ks < 2; ks++) {
            uint32_t fAH[2][4], fAL[2][4], fBH[4][2], fBL[4][2];
#pragma unroll
            for (int mt = 0; mt < 2; mt++) {
                uint32_t ao = (uint32_t)((wm * 32 + mt * 16 + lr) * A_PITCH + ks * 16 + lc8) * 2;
                ldm_x4(fAH[mt], AHb + ao);
                ldm_x4(fAL[mt], ALb + ao);
            }
#pragma unroll
            for (int half = 0; half < 2; half++) {
                int brow = ks * 16 + lr;
                int bcol = wn * 32 + half * 16 + lc8;
                uint32_t bo = (uint32_t)(brow * BB_PITCH + bcol) * 2;
                uint32_t rH[4], rL[4];
                ldm_x4t(rH, BHb + bo);
                ldm_x4t(rL, BLb + bo);
                fBH[half*2][0] = rH[0]; fBH[half*2][1] = rH[1];
                fBH[half*2+1][0] = rH[2]; fBH[half*2+1][1] = rH[3];
                fBL[half*2][0] = rL[0]; fBL[half*2][1] = rL[1];
                fBL[half*2+1][0] = rL[2]; fBL[half*2+1][1] = rL[3];
            }
#pragma unroll
            for (int mt = 0; mt < 2; mt++)
#pragma unroll
                for (int nt = 0; nt < 4; nt++) {
                    mma16816(acc[mt][nt], fAH[mt], fBH[nt]);
                    mma16816(acc[mt][nt], fAH[mt], fBL[nt]);
                    mma16816(acc[mt][nt], fAL[mt], fBH[nt]);
                }
        }
    }

    // ---- epilogue ----
#pragma unroll
    for (int mt = 0; mt < 2; mt++) {
        int r1 = wm * 32 + mt * 16 + gr;
        int r2 = r1 + 8;
        int t1 = tok[r1], t2 = tok[r2];
        float s1 = scl[r1], s2 = scl[r2];
#pragma unroll
        for (int nt = 0; nt < 4; nt++) {
            int col = n0 + wn * 32 + nt * 8 + tg * 2;
            if (t1 >= 0) {
                float2 o = make_float2(acc[mt][nt][0] * s1, acc[mt][nt][1] * s1);
                if (res) {
                    float2 rv = *(const float2*)(res + (size_t)t1 * ldc + col);
                    o.x += rv.x; o.y += rv.y;
                }
                *(float2*)(C + (size_t)t1 * ldc + col) = o;
            }
            if (t2 >= 0) {
                float2 o = make_float2(acc[mt][nt][2] * s2, acc[mt][nt][3] * s2);
                if (res) {
                    float2 rv = *(const float2*)(res + (size_t)t2 * ldc + col);
                    o.x += rv.x; o.y += rv.y;
                }
                *(float2*)(C + (size_t)t2 * ldc + col) = o;
            }
        }
    }
}

// =============== attention scores via HMMA (causal-skip) ===============
#define SC_SMEM (52224*2)

__global__ void __launch_bounds__(256, 2) scores_mma_kernel(
    const __nv_bfloat16* __restrict__ qh, const __nv_bfloat16* __restrict__ ql,
    const __nv_bfloat16* __restrict__ kh, const __nv_bfloat16* __restrict__ kl,
    float* __restrict__ sc)
{
    extern __shared__ __nv_bfloat16 smb[];
    int h = blockIdx.z;
    int row0 = blockIdx.y * 64;
    int n0 = blockIdx.x * 128;
    if (n0 >= row0 + 64) return;
    int tid = threadIdx.x, lane = tid & 31, wid = tid >> 5;
    int gr = lane >> 2, tg = lane & 3;
    int wm = wid >> 2, wn = wid & 3;
    uint32_t base = smem_u32(smb);

#pragma unroll
    for (int pl = 0; pl < 2; pl++) {
        const __nv_bfloat16* src = pl ? ql : qh;
        uint32_t d0 = base + (pl ? 8704u : 0u) * 2;
#pragma unroll
        for (int it = 0; it < 4; it++) {
            int idx = it * 256 + tid;
            int r = idx >> 4, ch = idx & 15;
            cpa16(d0 + (uint32_t)(r * 136 + ch * 8) * 2,
                  src + (size_t)(row0 + r) * 2048 + h * 128 + ch * 8);
        }
    }
#pragma unroll
    for (int pl = 0; pl < 2; pl++) {
        const __nv_bfloat16* src = pl ? kl : kh;
        uint32_t d0 = base + (pl ? 34816u : 17408u) * 2;
#pragma unroll
        for (int it = 0; it < 8; it++) {
            int idx = it * 256 + tid;
            int r = idx >> 4, ch = idx & 15;
            cpa16(d0 + (uint32_t)(r * 136 + ch * 8) * 2,
                  src + (size_t)(n0 + r) * 512 + (h >> 2) * 128 + ch * 8);
        }
    }
    CPA_COMMIT(); CPA_WAIT0();
    __syncthreads();

    float acc[2][4][4];
#pragma unroll
    for (int i = 0; i < 2; i++)
#pragma unroll
        for (int j = 0; j < 4; j++)
#pragma unroll
            for (int r = 0; r < 4; r++) acc[i][j][r] = 0.f;

    int lr = lane & 15, lc8 = (lane & 16) >> 1;
    uint32_t QHb = base, QLb = base + 17408;
    uint32_t KHb = base + 34816, KLb = base + 69632;

#pragma unroll
    for (int ks = 0; ks < 8; ks++) {
        uint32_t fAH[2][4], fAL[2][4], fBH[4][2], fBL[4][2];
#pragma unroll
        for (int mt = 0; mt < 2; mt++) {
            uint32_t ao = (uint32_t)((wm * 32 + mt * 16 + lr) * 136 + ks * 16 + lc8) * 2;
            ldm_x4(fAH[mt], QHb + ao);
            ldm_x4(fAL[mt], QLb + ao);
        }
#pragma unroll
        for (int half = 0; half < 2; half++) {
            uint32_t bo = (uint32_t)((wn * 32 + half * 16 + lr) * 136 + ks * 16 + lc8) * 2;
            uint32_t rH[4], rL[4];
            ldm_x4(rH, KHb + bo);
            ldm_x4(rL, KLb + bo);
            fBH[half*2][0] = rH[0]; fBH[half*2][1] = rH[2];
            fBH[half*2+1][0] = rH[1]; fBH[half*2+1][1] = rH[3];
            fBL[half*2][0] = rL[0]; fBL[half*2][1] = rL[2];
            fBL[half*2+1][0] = rL[1]; fBL[half*2+1][1] = rL[3];
        }
#pragma unroll
        for (int mt = 0; mt < 2; mt++)
#pragma unroll
            for (int nt = 0; nt < 4; nt++) {
                mma16816(acc[mt][nt], fAH[mt], fBH[nt]);
                mma16816(acc[mt][nt], fAH[mt], fBL[nt]);
                mma16816(acc[mt][nt], fAL[mt], fBH[nt]);
            }
    }

    const float scale = 0.0883883476483184405f;
    float* out = sc + (size_t)h * Sm * Sm;
#pragma unroll
    for (int mt = 0; mt < 2; mt++) {
        int r1 = row0 + wm * 32 + mt * 16 + gr;
        int r2 = r1 + 8;
#pragma unroll
        for (int nt = 0; nt < 4; nt++) {
            int col = n0 + wn * 32 + nt * 8 + tg * 2;
            *(float2*)(out + (size_t)r1 * Sm + col) =
                make_float2(acc[mt][nt][0] * scale, acc[mt][nt][1] * scale);
            *(float2*)(out + (size_t)r2 * Sm + col) =
                make_float2(acc[mt][nt][2] * scale, acc[mt][nt][3] * scale);
        }
    }
}

// =============== PV via HMMA (causal-truncated K loop) ===============
#define PV_STAGE_B (26624*2)
#define PV_SMEM (2*PV_STAGE_B)

__global__ void __launch_bounds__(256, 2) pv_mma_kernel(
    const __nv_bfloat16* __restrict__ ph_, const __nv_bfloat16* __restrict__ pl_,
    const __nv_bfloat16* __restrict__ vh, const __nv_bfloat16* __restrict__ vl,
    __nv_bfloat16* __restrict__ outh, __nv_bfloat16* __restrict__ outl)
{
    extern __shared__ __nv_bfloat16 smb[];
    int h = blockIdx.y;
    int row0 = blockIdx.x * 64;
    int nst = blockIdx.x + 1;
    int kvoff = (h >> 2) * 128;
    int tid = threadIdx.x, lane = tid & 31, wid = tid >> 5;
    int gr = lane >> 2, tg = lane & 3;
    int wm = wid >> 2, wn = wid & 3;
    uint32_t smbase = smem_u32(smb);

    float acc[2][4][4];
#pragma unroll
    for (int i = 0; i < 2; i++)
#pragma unroll
        for (int j = 0; j < 4; j++)
#pragma unroll
            for (int r = 0; r < 4; r++) acc[i][j][r] = 0.f;

    auto copy_stage = [&](int st) {
        uint32_t base = smbase + (uint32_t)(st & 1) * PV_STAGE_B;
        int k0 = st * 64;
#pragma unroll
        for (int pl = 0; pl < 2; pl++) {
            const __nv_bfloat16* asrc = pl ? pl_ : ph_;
            uint32_t d0 = base + (pl ? 4608 : 0) * 2;
#pragma unroll
            for (int it = 0; it < 2; it++) {
                int idx = it * 256 + tid;
                int row = idx >> 3, ch = idx & 7;
                cpa16(d0 + (uint32_t)(row * 72 + ch * 8) * 2,
                      asrc + ((size_t)h * Sm + row0 + row) * Sm + k0 + ch * 8);
            }
        }
#pragma unroll
        for (int pl = 0; pl < 2; pl++) {
            const __nv_bfloat16* bsrc = pl ? vl : vh;
            uint32_t d0 = base + (pl ? 17920 : 9216) * 2;
#pragma unroll
            for (int it = 0; it < 4; it++) {
                int idx = it * 256 + tid;
                int row = idx >> 4, ch = idx & 15;
                cpa16(d0 + (uint32_t)(row * 136 + ch * 8) * 2,
                      bsrc + (size_t)(k0 + row) * 512 + kvoff + ch * 8);
            }
        }
        CPA_COMMIT();
    };

    copy_stage(0);
    int lr = lane & 15, lc8 = (lane & 16) >> 1;

    for (int st = 0; st < nst; st++) {
        if (st + 1 < nst) { copy_stage(st + 1); CPA_WAIT1(); }
        else              { CPA_WAIT0(); }
        __syncthreads();
        uint32_t base = smbase + (uint32_t)(st & 1) * PV_STAGE_B;
        uint32_t AHb = base, ALb = base + 9216;
        uint32_t BHb = base + 18432, BLb = base + 35840;
#pragma unroll
        for (int ks = 0; ks < 4; ks++) {
            uint32_t fAH[2][4], fAL[2][4], fBH[4][2], fBL[4][2];
#pragma unroll
            for (int mt = 0; mt < 2; mt++) {
                uint32_t ao = (uint32_t)((wm * 32 + mt * 16 + lr) * 72 + ks * 16 + lc8) * 2;
                ldm_x4(fAH[mt], AHb + ao);
                ldm_x4(fAL[mt], ALb + ao);
            }
#pragma unroll
            for (int half = 0; half < 2; half++) {
                uint32_t bo = (uint32_t)((ks * 16 + lr) * 136 + wn * 32 + half * 16 + lc8) * 2;
                uint32_t rH[4], rL[4];
                ldm_x4t(rH, BHb + bo);
                ldm_x4t(rL, BLb + bo);
                fBH[half*2][0] = rH[0]; fBH[half*2][1] = rH[1];
                fBH[half*2+1][0] = rH[2]; fBH[half*2+1][1] = rH[3];
                fBL[half*2][0] = rL[0]; fBL[half*2][1] = rL[1];
                fBL[half*2+1][0] = rL[2]; fBL[half*2+1][1] = rL[3];
            }
#pragma unroll
            for (int mt = 0; mt < 2; mt++)
#pragma unroll
                for (int nt = 0; nt < 4; nt++) {
                    mma16816(acc[mt][nt], fAH[mt], fBH[nt]);
                    mma16816(acc[mt][nt], fAH[mt], fBL[nt]);
                    mma16816(acc[mt][nt], fAL[mt], fBH[nt]);
                }
        }
        __syncthreads();
    }

#pragma unroll
    for (int mt = 0; mt < 2; mt++) {
        int r1 = row0 + wm * 32 + mt * 16 + gr;
        int r2 = r1 + 8;
#pragma unroll
        for (int nt = 0; nt < 4; nt++) {
            int col = h * 128 + wn * 32 + nt * 8 + tg * 2;
            float v0 = acc[mt][nt][0], v1 = acc[mt][nt][1];
            float v2 = acc[mt][nt][2], v3 = acc[mt][nt][3];
            uint32_t h01 = pack_bf16x2(v0, v1);
            uint32_t l01 = pack_bf16x2(v0 - __uint_as_float(h01 << 16),
                                       v1 - __uint_as_float(h01 & 0xffff0000u));
            uint32_t h23 = pack_bf16x2(v2, v3);
            uint32_t l23 = pack_bf16x2(v2 - __uint_as_float(h23 << 16),
                                       v3 - __uint_as_float(h23 & 0xffff0000u));
            *(uint32_t*)(outh + (size_t)r1 * 2048 + col) = h01;
            *(uint32_t*)(outl + (size_t)r1 * 2048 + col) = l01;
            *(uint32_t*)(outh + (size_t)r2 * 2048 + col) = h23;
            *(uint32_t*)(outl + (size_t)r2 * 2048 + col) = l23;
        }
    }
}

// ---------------- small kernels ----------------
__global__ void rmsnorm_kernel(const float* __restrict__ in, const float* __restrict__ w,
                               float* __restrict__ outf,
                               __nv_bfloat16* __restrict__ outh,
                               __nv_bfloat16* __restrict__ outl) {
    int t = blockIdx.x;
    const float* row = in + (size_t)t * Dm;
    float s = 0.f;
    for (int d = threadIdx.x; d < Dm; d += 256) { float v = row[d]; s += v * v; }
    __shared__ float red[256];
    red[threadIdx.x] = s; __syncthreads();
    for (int off = 128; off > 0; off >>= 1) {
        if (threadIdx.x < off) red[threadIdx.x] += red[threadIdx.x + off];
        __syncthreads();
    }
    float r = rsqrtf(red[0] / (float)Dm + 1e-5f);
    for (int d = threadIdx.x; d < Dm; d += 256) {
        float v = row[d] * r * w[d];
        if (outf) outf[(size_t)t * Dm + d] = v;
        split_store(v, outh, outl, (size_t)t * Dm + d);
    }
}

__global__ void rope_planes_kernel(const float* __restrict__ qkv, const int* __restrict__ pos_ids,
                                   __nv_bfloat16* qh, __nv_bfloat16* ql,
                                   __nv_bfloat16* kh, __nv_bfloat16* kl,
                                   __nv_bfloat16* vh, __nv_bfloat16* vl) {
    int t = blockIdx.x;
    float p = (float)pos_ids[t];
    for (int idx = threadIdx.x; idx < (Hn + HKVn) * 64; idx += blockDim.x) {
        int head = idx >> 6;
        int i = idx & 63;
        float inv = powf(500000.0f, -(float)i / 64.0f);
        float f = p * inv;
        float sn, cs;
        sincosf(f, &sn, &cs);
        if (head < Hn) {
            const float* src = qkv + (size_t)t * QKVP + head * DHn;
            float x1 = src[i], x2 = src[i + 64];
            size_t d = (size_t)t * Dm + head * DHn + i;
            split_store(x1 * cs - x2 * sn, qh, ql, d);
            split_store(x2 * cs + x1 * sn, qh, ql, d + 64);
        } else {
            int kvh = head - Hn;
            const float* src = qkv + (size_t)t * QKVP + 2048 + kvh * DHn;
            float x1 = src[i], x2 = src[i + 64];
            size_t d = (size_t)t * 512 + kvh * DHn + i;
            split_store(x1 * cs - x2 * sn, kh, kl, d);
            split_store(x2 * cs + x1 * sn, kh, kl, d + 64);
        }
    }
    for (int idx = threadIdx.x; idx < 512; idx += blockDim.x) {
        float v = qkv[(size_t)t * QKVP + 2560 + idx];
        split_store(v, vh, vl, (size_t)t * 512 + idx);
    }
}

__global__ void softmax_kernel(const float* __restrict__ sc, const int* __restrict__ mask,
                               __nv_bfloat16* __restrict__ ph, __nv_bfloat16* __restrict__ pl) {
    int i = blockIdx.x;
    int h = blockIdx.y;
    const float* row = sc + ((size_t)h * Sm + i) * Sm;
    int tid = threadIdx.x;
    int j0 = tid, j1 = tid + 256;
    float s0 = (j0 <= i && mask[j0] > 0) ? row[j0] : -1e9f;
    float s1 = (j1 <= i && mask[j1] > 0) ? row[j1] : -1e9f;
    __shared__ float red[256];
    red[tid] = fmaxf(s0, s1); __syncthreads();
    for (int off = 128; off > 0; off >>= 1) {
        if (tid < off) red[tid] = fmaxf(red[tid], red[tid + off]);
        __syncthreads();
    }
    float m = red[0];
    __syncthreads();
    float e0 = expf(s0 - m), e1 = expf(s1 - m);
    red[tid] = e0 + e1; __syncthreads();
    for (int off = 128; off > 0; off >>= 1) {
        if (tid < off) red[tid] += red[tid + off];
        __syncthreads();
    }
    float inv = 1.f / red[0];
    size_t base = ((size_t)h * Sm + i) * Sm;
    split_store(e0 * inv, ph, pl, base + j0);
    split_store(e1 * inv, ph, pl, base + j1);
}

__global__ void router_kernel(const float* __restrict__ x2, const float* __restrict__ rw,
                              int* __restrict__ topidx, float* __restrict__ topscore) {
    int t = blockIdx.x;
    int w = threadIdx.x >> 5, lane = threadIdx.x & 31;
    float s = 0.f;
    for (int d = lane; d < Dm; d += 32)
        s += x2[(size_t)t * Dm + d] * rw[d * En + w];
    for (int off = 16; off; off >>= 1) s += __shfl_down_sync(0xffffffff, s, off);
    __shared__ float logits[En];
    if (lane == 0) logits[w] = s;
    __syncthreads();
    if (threadIdx.x == 0) {
        int best = 0; float bv = logits[0];
        for (int e = 1; e < En; e++) if (logits[e] > bv) { bv = logits[e]; best = e; }
        topidx[t] = best;
        topscore[t] = 1.f / (1.f + expf(-bv));
    }
}

__global__ void dispatch_kernel(const int* __restrict__ topidx) {
    int t = threadIdx.x;
    if (t < En) g_cnt[t] = 0;
    __syncthreads();
    int e = topidx[t];
    int pos = atomicAdd(&g_cnt[e], 1);
    g_list[e * Sm + pos] = t;
}

// combined silu-mul for expert gu and shared sgu
__global__ void silumul2_kernel(const float* __restrict__ gu, const float* __restrict__ sgu,
                                __nv_bfloat16* __restrict__ ah, __nv_bfloat16* __restrict__ al,
                                __nv_bfloat16* __restrict__ sh, __nv_bfloat16* __restrict__ sl) {
    int i = blockIdx.x * 256 + threadIdx.x;
    const float* src = gu;
    __nv_bfloat16* oh = ah;
    __nv_bfloat16* ol = al;
    int j = i;
    if (i >= Sm * Dm) {
        j = i - Sm * Dm;
        src = sgu; oh = sh; ol = sl;
    }
    int t = j >> 11, c = j & 2047;
    float g = src[(size_t)t * 4096 + c];
    float u = src[(size_t)t * 4096 + 2048 + c];
    float a = (g / (1.f + expf(-g))) * u;
    split_store(a, oh, ol, (size_t)j);
}

__global__ void add3_kernel(const float* __restrict__ a, const float* __restrict__ b,
                            const float* __restrict__ c, float* __restrict__ out) {
    int i = blockIdx.x * 256 + threadIdx.x;
    out[i] = a[i] + b[i] + c[i];
}

// ---------------- launch ----------------
#define GSYM(p, s) cudaGetSymbolAddress((void**)&p, s)
#define NSBIG 0x40000000

extern "C" void kernel_launch(void* const* d_in, const int* in_sizes, int n_in,
                              void* d_out, int out_size) {
    const float* hidden   = (const float*)d_in[0];
    const int*   amask    = (const int*)  d_in[1];
    const int*   pos      = (const int*)  d_in[2];
    const float* attn_nw  = (const float*)d_in[3];
    const float* wq       = (const float*)d_in[4];
    const float* wk       = (const float*)d_in[5];
    const float* wv       = (const float*)d_in[6];
    const float* wo       = (const float*)d_in[7];
    const float* ffn_nw   = (const float*)d_in[8];
    const float* router_w = (const float*)d_in[9];
    const float* w_gate   = (const float*)d_in[10];
    const float* w_up     = (const float*)d_in[11];
    const float* w_down   = (const float*)d_in[12];
    const float* ws_gate  = (const float*)d_in[13];
    const float* ws_up    = (const float*)d_in[14];
    const float* ws_down  = (const float*)d_in[15];
    float* out = (float*)d_out;

    float *pqkv, *psc, *phf, *px2f, *pgu, *psgu, *prouted, *pshared, *pts;
    int *pti;
    __nv_bfloat16 *pxh, *pxl, *path, *patl, *px2h, *px2l, *pach, *pacl, *psah, *psal;
    __nv_bfloat16 *pqh, *pql, *pkh, *pkl, *pvh, *pvl, *pph, *ppl;
    GSYM(pqkv, g_qkv); GSYM(psc, g_scores); GSYM(phf, g_h); GSYM(px2f, g_x2f);
    GSYM(pgu, g_gu); GSYM(psgu, g_sgu); GSYM(prouted, g_routed); GSYM(pshared, g_shared);
    GSYM(pti, g_topidx); GSYM(pts, g_topscore);
    GSYM(pxh, x_h); GSYM(pxl, x_l); GSYM(path, at_h); GSYM(patl, at_l);
    GSYM(px2h, x2_h); GSYM(px2l, x2_l); GSYM(pach, ac_h); GSYM(pacl, ac_l);
    GSYM(psah, sa_h); GSYM(psal, sa_l);
    GSYM(pqh, q_h); GSYM(pql, q_l); GSYM(pkh, k_h); GSYM(pkl, k_l);
    GSYM(pvh, v_h); GSYM(pvl, v_l); GSYM(pph, p_h); GSYM(ppl, p_l);

    cudaFuncSetAttribute(tgemm_kernel, cudaFuncAttributeMaxDynamicSharedMemorySize, TG_SMEM);
    cudaFuncSetAttribute(scores_mma_kernel, cudaFuncAttributeMaxDynamicSharedMemorySize, SC_SMEM);
    cudaFuncSetAttribute(pv_mma_kernel, cudaFuncAttributeMaxDynamicSharedMemorySize, PV_SMEM);

    // --- attention block ---
    rmsnorm_kernel<<<Sm, 256>>>(hidden, attn_nw, nullptr, pxh, pxl);
    // fused QKV: n<2048 -> wq; else wk|wv glued via ns-split (wk cols 0..511, wv 512..1023 handled by two regions)
    tgemm_kernel<<<dim3(16, 8), 256, TG_SMEM>>>(pxh, pxl, wq, nullptr, 2048, 0, NSBIG,
                                                pqkv, 3072, nullptr, nullptr, 0,
                                                nullptr, nullptr, nullptr, nullptr, nullptr);
    tgemm_kernel<<<dim3(8, 8), 256, TG_SMEM>>>(pxh, pxl, wk, wv, 512, 512, 512,
                                               pqkv + 2048, 3072, nullptr, nullptr, 0,
                                               nullptr, nullptr, nullptr, nullptr, nullptr);
    rope_planes_kernel<<<Sm, 256>>>(pqkv, pos, pqh, pql, pkh, pkl, pvh, pvl);
    scores_mma_kernel<<<dim3(4, 8, Hn), 256, SC_SMEM>>>(pqh, pql, pkh, pkl, psc);
    softmax_kernel<<<dim3(Sm, Hn), 256>>>(psc, amask, pph, ppl);
    pv_mma_kernel<<<dim3(8, Hn), 256, PV_SMEM>>>(pph, ppl, pvh, pvl, path, patl);
    tgemm_kernel<<<dim3(16, 8), 256, TG_SMEM>>>(path, patl, wo, nullptr, 2048, 0, NSBIG,
                                                phf, 2048, hidden, nullptr, 0,
                                                nullptr, nullptr, nullptr, nullptr, nullptr);

    // --- MoE block ---
    rmsnorm_kernel<<<Sm, 256>>>(phf, ffn_nw, px2f, px2h, px2l);
    router_kernel<<<Sm, 256>>>(px2f, router_w, pti, pts);
    dispatch_kernel<<<1, Sm>>>(pti);
    // combined: z<8 expert gate|up (gathered, scaled); z=8 shared gate|up (dense)
    tgemm_kernel<<<dim3(32, 8, En + 1), 256, TG_SMEM>>>(px2h, px2l, w_gate, w_up,
                                                        2048, 2048, 2048,
                                                        pgu, 4096, nullptr, pts, 1,
                                                        px2h, px2l, ws_gate, ws_up, psgu);
    silumul2_kernel<<<(2 * Sm * Dm) / 256, 256>>>(pgu, psgu, pach, pacl, psah, psal);
    // combined: z<8 expert down (gathered); z=8 shared down (dense)
    tgemm_kernel<<<dim3(16, 8, En + 1), 256, TG_SMEM>>>(pach, pacl, w_down, nullptr,
                                                        2048, 0, NSBIG,
                                                        prouted, 2048, nullptr, nullptr, 1,
                                                        psah, psal, ws_down, nullptr, pshared);

    // final: out = h + routed + shared
    add3_kernel<<<(Sm * Dm) / 256, 256>>>(phf, prouted, pshared, out);
}

// round 13
// speedup vs baseline: 1.3190x; 1.0298x over previous
#include <cuda_runtime.h>
#include <cuda_bf16.h>
#include <stdint.h>
#include <math.h>

#define Dm   2048
#define Sm   512
#define Hn   16
#define HKVn 4
#define DHn  128
#define Fn   2048
#define En   8
#define QKVP 3072

// ---------------- scratch (device globals) ----------------
__device__ float g_qkv[Sm*QKVP];
__device__ float g_scores[Hn*Sm*Sm];
__device__ float g_h[Sm*Dm];
__device__ float g_x2f[Sm*Dm];
__device__ float g_gu[Sm*4096];
__device__ float g_sgu[Sm*4096];
__device__ float g_routed[Sm*Dm];
__device__ float g_shared[Sm*Dm];
__device__ int   g_topidx[Sm];
__device__ float g_topscore[Sm];
__device__ int   g_cnt[En];
__device__ int   g_list[En*Sm];

// activation bf16 hi/lo planes
__device__ __nv_bfloat16 x_h[Sm*Dm],  x_l[Sm*Dm];
__device__ __nv_bfloat16 at_h[Sm*Dm], at_l[Sm*Dm];
__device__ __nv_bfloat16 x2_h[Sm*Dm], x2_l[Sm*Dm];
__device__ __nv_bfloat16 ac_h[Sm*Dm], ac_l[Sm*Dm];
__device__ __nv_bfloat16 sa_h[Sm*Dm], sa_l[Sm*Dm];
// attention planes
__device__ __nv_bfloat16 q_h[Sm*Dm],  q_l[Sm*Dm];
__device__ __nv_bfloat16 k_h[Sm*512], k_l[Sm*512];
__device__ __nv_bfloat16 v_h[Sm*512], v_l[Sm*512];
__device__ __nv_bfloat16 p_h[Hn*Sm*Sm], p_l[Hn*Sm*Sm];

// ---------------- helpers ----------------
__device__ __forceinline__ uint32_t smem_u32(const void* p) {
    uint32_t a;
    asm("{ .reg .u64 t; cvta.to.shared.u64 t, %1; cvt.u32.u64 %0, t; }" : "=r"(a) : "l"(p));
    return a;
}
// a -> low element, b -> high element
__device__ __forceinline__ uint32_t pack_bf16x2(float a, float b) {
    uint32_t r;
    asm("cvt.rn.bf16x2.f32 %0, %1, %2;" : "=r"(r) : "f"(b), "f"(a));
    return r;
}
__device__ __forceinline__ void mma16816(float c[4], const uint32_t a[4], const uint32_t b[2]) {
    asm volatile(
        "mma.sync.aligned.m16n8k16.row.col.f32.bf16.bf16.f32 "
        "{%0,%1,%2,%3}, {%4,%5,%6,%7}, {%8,%9}, {%0,%1,%2,%3};"
        : "+f"(c[0]), "+f"(c[1]), "+f"(c[2]), "+f"(c[3])
        : "r"(a[0]), "r"(a[1]), "r"(a[2]), "r"(a[3]), "r"(b[0]), "r"(b[1]));
}
__device__ __forceinline__ void cpa16(uint32_t d, const void* s) {
    asm volatile("cp.async.cg.shared.global [%0], [%1], 16;" :: "r"(d), "l"(s));
}
#define CPA_COMMIT() asm volatile("cp.async.commit_group;" ::: "memory")
#define CPA_WAIT1()  asm volatile("cp.async.wait_group 1;" ::: "memory")
#define CPA_WAIT0()  asm volatile("cp.async.wait_group 0;" ::: "memory")
__device__ __forceinline__ void ldm_x4(uint32_t r[4], uint32_t a) {
    asm volatile("ldmatrix.sync.aligned.m8n8.x4.shared.b16 {%0,%1,%2,%3}, [%4];"
        : "=r"(r[0]), "=r"(r[1]), "=r"(r[2]), "=r"(r[3]) : "r"(a));
}
__device__ __forceinline__ void ldm_x4t(uint32_t r[4], uint32_t a) {
    asm volatile("ldmatrix.sync.aligned.m8n8.x4.trans.shared.b16 {%0,%1,%2,%3}, [%4];"
        : "=r"(r[0]), "=r"(r[1]), "=r"(r[2]), "=r"(r[3]) : "r"(a));
}
__device__ __forceinline__ void split_store(float v, __nv_bfloat16* ph, __nv_bfloat16* pl, size_t off) {
    __nv_bfloat16 h = __float2bfloat16(v);
    ph[off] = h;
    pl[off] = __float2bfloat16(v - __bfloat162float(h));
}

// =============== fp32-weight 3-pass HMMA GEMM, 64x128 tile, K=2048 ===============
// B: LDG fp32 -> regs (1-stage prefetch) -> convert -> STS bf16 hi/lo (double buf)
// A: cp.async bf16 planes (triple buf). ONE barrier per 32-k stage.
#define KST 32
#define A_PITCH 40
#define A_PLANE_B (64*A_PITCH*2)      // 5120
#define A_BUF_B (2*A_PLANE_B)         // 10240 (hi+lo)
#define BB_PITCH 136
#define BB_PLANE_B (KST*BB_PITCH*2)   // 8704
#define OFF_BB (3*A_BUF_B)            // 30720
#define TG_SMEM (OFF_BB + 2*2*BB_PLANE_B)  // 65536

__global__ void __launch_bounds__(256, 2) tgemm_kernel(
    const __nv_bfloat16* __restrict__ aH, const __nv_bfloat16* __restrict__ aL,
    const float* __restrict__ B0, const float* __restrict__ B1, const float* __restrict__ B2,
    int ldb0, int ldb1, int ldb2, int ns1, int ns2,
    float* __restrict__ C, int ldc,
    const float* __restrict__ res, const float* __restrict__ rowscale, int mode,
    const __nv_bfloat16* __restrict__ sAh, const __nv_bfloat16* __restrict__ sAl,
    const float* __restrict__ sB0, const float* __restrict__ sB1,
    float* __restrict__ sC)
{
    extern __shared__ char smc[];
    __shared__ int   tok[64];
    __shared__ float scl[64];
    int row0 = blockIdx.y * 64;
    int n0   = blockIdx.x * 128;
    int tid  = threadIdx.x;

    int gather = mode;
    if (mode == 1 && blockIdx.z == En) {
        // shared-expert branch: dense rows, alternate A/B/C
        aH = sAh; aL = sAl; B0 = sB0; B1 = sB1; C = sC;
        rowscale = nullptr;
        gather = 0;
    }

    const float* Bsel; int ldbs; int ncol;
    if (n0 < ns1)      { Bsel = B0; ldbs = ldb0; ncol = n0; }
    else if (n0 < ns2) { Bsel = B1; ldbs = ldb1; ncol = n0 - ns1; }
    else               { Bsel = B2; ldbs = ldb2; ncol = n0 - ns2; }

    if (gather) {
        int e = blockIdx.z;
        int count = g_cnt[e];
        if (row0 >= count) return;
        Bsel += (size_t)e * 2048 * ldbs;
        if (tid < 64) {
            int r = row0 + tid;
            int t = (r < count) ? g_list[e * Sm + r] : -1;
            tok[tid] = t;
            scl[tid] = (t >= 0 && rowscale) ? rowscale[t] : 1.0f;
        }
    } else {
        if (tid < 64) { tok[tid] = row0 + tid; scl[tid] = 1.0f; }
    }
    __syncthreads();

    uint32_t smbase = smem_u32(smc);
    int lane = tid & 31, wid = tid >> 5;
    int gr = lane >> 2, tg = lane & 3;
    int wm = wid >> 2, wn = wid & 3;

    float acc[2][4][4];
#pragma unroll
    for (int i = 0; i < 2; i++)
#pragma unroll
        for (int j = 0; j < 4; j++)
#pragma unroll
            for (int r = 0; r < 4; r++) acc[i][j][r] = 0.f;

    int arow = tid >> 2, ach = tid & 3;
    int at = tok[arow];
    int agrow = at < 0 ? 0 : at;

    int bk[4], bc[4];
#pragma unroll
    for (int it = 0; it < 4; it++) {
        int chunk = it * 256 + tid;
        bk[it] = chunk >> 5;
        bc[it] = (chunk & 31) * 4;
    }

    auto copy_A = [&](int st) {
        uint32_t ab = smbase + (uint32_t)(st % 3) * A_BUF_B;
        int k0 = st * KST;
        cpa16(ab + (uint32_t)(arow * A_PITCH + ach * 8) * 2,
              aH + (size_t)agrow * 2048 + k0 + ach * 8);
        cpa16(ab + A_PLANE_B + (uint32_t)(arow * A_PITCH + ach * 8) * 2,
              aL + (size_t)agrow * 2048 + k0 + ach * 8);
        CPA_COMMIT();
    };

    float4 va[4];
    auto ldg_B = [&](int st) {
        int k0 = st * KST;
#pragma unroll
        for (int it = 0; it < 4; it++)
            va[it] = *(const float4*)(Bsel + (size_t)(k0 + bk[it]) * ldbs + ncol + bc[it]);
    };

    ldg_B(0);
    copy_A(0);

    int lr = lane & 15;
    int lc8 = (lane & 16) >> 1;

    for (int st = 0; st < 64; st++) {
        // convert B(st) from regs -> BB[st&1]
        {
            __nv_bfloat16* bh = (__nv_bfloat16*)(smc + OFF_BB + (st & 1) * (2 * BB_PLANE_B));
            __nv_bfloat16* bl = (__nv_bfloat16*)((char*)bh + BB_PLANE_B);
#pragma unroll
            for (int it = 0; it < 4; it++) {
                float4 v = va[it];
                uint32_t h01 = pack_bf16x2(v.x, v.y);
                uint32_t h23 = pack_bf16x2(v.z, v.w);
                uint32_t l01 = pack_bf16x2(v.x - __uint_as_float(h01 << 16),
                                           v.y - __uint_as_float(h01 & 0xffff0000u));
                uint32_t l23 = pack_bf16x2(v.z - __uint_as_float(h23 << 16),
                                           v.w - __uint_as_float(h23 & 0xffff0000u));
                int o = bk[it] * BB_PITCH + bc[it];
                *(uint2*)(bh + o) = make_uint2(h01, h23);
                *(uint2*)(bl + o) = make_uint2(l01, l23);
            }
        }
        if (st < 63) {
            ldg_B(st + 1);
            copy_A(st + 1);
            CPA_WAIT1();
        } else {
            CPA_WAIT0();
        }
        __syncthreads();

        // ---- MMA: 2 k16 steps ----
        uint32_t ab = smbase + (uint32_t)(st % 3) * A_BUF_B;
        uint32_t AHb = ab, ALb = ab + A_PLANE_B;
        uint32_t BHb = smbase + OFF_BB + (uint32_t)(st & 1) * (2 * BB_PLANE_B);
        uint32_t BLb = BHb + BB_PLANE_B;
#pragma unroll
        for (int ks = 0; ks < 2; ks++) {
            uint32_t fAH[2][4], fAL[2][4], fBH[4][2], fBL[4][2];
#pragma unroll
            for (int mt = 0; mt < 2; mt++) {
                uint32_t ao = (uint32_t)((wm * 32 + mt * 16 + lr) * A_PITCH + ks * 16 + lc8) * 2;
                ldm_x4(fAH[mt], AHb + ao);
                ldm_x4(fAL[mt], ALb + ao);
            }
#pragma unroll
            for (int half = 0; half < 2; half++) {
                int brow = ks * 16 + lr;
                int bcol = wn * 32 + half * 16 + lc8;
                uint32_t bo = (uint32_t)(brow * BB_PITCH + bcol) * 2;
                uint32_t rH[4], rL[4];
                ldm_x4t(rH, BHb + bo);
                ldm_x4t(rL, BLb + bo);
                fBH[half*2][0] = rH[0]; fBH[half*2][1] = rH[1];
                fBH[half*2+1][0] = rH[2]; fBH[half*2+1][1] = rH[3];
                fBL[half*2][0] = rL[0]; fBL[half*2][1] = rL[1];
                fBL[half*2+1][0] = rL[2]; fBL[half*2+1][1] = rL[3];
            }
#pragma unroll
            for (int mt = 0; mt < 2; mt++)
#pragma unroll
                for (int nt = 0; nt < 4; nt++) {
                    mma16816(acc[mt][nt], fAH[mt], fBH[nt]);
                    mma16816(acc[mt][nt], fAH[mt], fBL[nt]);
                    mma16816(acc[mt][nt], fAL[mt], fBH[nt]);
                }
        }
    }

    // ---- epilogue ----
#pragma unroll
    for (int mt = 0; mt < 2; mt++) {
        int r1 = wm * 32 + mt * 16 + gr;
        int r2 = r1 + 8;
        int t1 = tok[r1], t2 = tok[r2];
        float s1 = scl[r1], s2 = scl[r2];
#pragma unroll
        for (int nt = 0; nt < 4; nt++) {
            int col = n0 + wn * 32 + nt * 8 + tg * 2;
            if (t1 >= 0) {
                float2 o = make_float2(acc[mt][nt][0] * s1, acc[mt][nt][1] * s1);
                if (res) {
                    float2 rv = *(const float2*)(res + (size_t)t1 * ldc + col);
                    o.x += rv.x; o.y += rv.y;
                }
                *(float2*)(C + (size_t)t1 * ldc + col) = o;
            }
            if (t2 >= 0) {
                float2 o = make_float2(acc[mt][nt][2] * s2, acc[mt][nt][3] * s2);
                if (res) {
                    float2 rv = *(const float2*)(res + (size_t)t2 * ldc + col);
                    o.x += rv.x; o.y += rv.y;
                }
                *(float2*)(C + (size_t)t2 * ldc + col) = o;
            }
        }
    }
}

// =============== attention scores via HMMA (causal-skip) ===============
#define SC_SMEM (52224*2)

__global__ void __launch_bounds__(256, 2) scores_mma_kernel(
    const __nv_bfloat16* __restrict__ qh, const __nv_bfloat16* __restrict__ ql,
    const __nv_bfloat16* __restrict__ kh, const __nv_bfloat16* __restrict__ kl,
    float* __restrict__ sc)
{
    extern __shared__ __nv_bfloat16 smb[];
    int h = blockIdx.z;
    int row0 = blockIdx.y * 64;
    int n0 = blockIdx.x * 128;
    if (n0 >= row0 + 64) return;
    int tid = threadIdx.x, lane = tid & 31, wid = tid >> 5;
    int gr = lane >> 2, tg = lane & 3;
    int wm = wid >> 2, wn = wid & 3;
    uint32_t base = smem_u32(smb);

#pragma unroll
    for (int pl = 0; pl < 2; pl++) {
        const __nv_bfloat16* src = pl ? ql : qh;
        uint32_t d0 = base + (pl ? 8704u : 0u) * 2;
#pragma unroll
        for (int it = 0; it < 4; it++) {
            int idx = it * 256 + tid;
            int r = idx >> 4, ch = idx & 15;
            cpa16(d0 + (uint32_t)(r * 136 + ch * 8) * 2,
                  src + (size_t)(row0 + r) * 2048 + h * 128 + ch * 8);
        }
    }
#pragma unroll
    for (int pl = 0; pl < 2; pl++) {
        const __nv_bfloat16* src = pl ? kl : kh;
        uint32_t d0 = base + (pl ? 34816u : 17408u) * 2;
#pragma unroll
        for (int it = 0; it < 8; it++) {
            int idx = it * 256 + tid;
            int r = idx >> 4, ch = idx & 15;
            cpa16(d0 + (uint32_t)(r * 136 + ch * 8) * 2,
                  src + (size_t)(n0 + r) * 512 + (h >> 2) * 128 + ch * 8);
        }
    }
    CPA_COMMIT(); CPA_WAIT0();
    __syncthreads();

    float acc[2][4][4];
#pragma unroll
    for (int i = 0; i < 2; i++)
#pragma unroll
        for (int j = 0; j < 4; j++)
#pragma unroll
            for (int r = 0; r < 4; r++) acc[i][j][r] = 0.f;

    int lr = lane & 15, lc8 = (lane & 16) >> 1;
    uint32_t QHb = base, QLb = base + 17408;
    uint32_t KHb = base + 34816, KLb = base + 69632;

#pragma unroll
    for (int ks = 0; ks < 8; ks++) {
        uint32_t fAH[2][4], fAL[2][4], fBH[4][2], fBL[4][2];
#pragma unroll
        for (int mt = 0; mt < 2; mt++) {
            uint32_t ao = (uint32_t)((wm * 32 + mt * 16 + lr) * 136 + ks * 16 + lc8) * 2;
            ldm_x4(fAH[mt], QHb + ao);
            ldm_x4(fAL[mt], QLb + ao);
        }
#pragma unroll
        for (int half = 0; half < 2; half++) {
            uint32_t bo = (uint32_t)((wn * 32 + half * 16 + lr) * 136 + ks * 16 + lc8) * 2;
            uint32_t rH[4], rL[4];
            ldm_x4(rH, KHb + bo);
            ldm_x4(rL, KLb + bo);
            fBH[half*2][0] = rH[0]; fBH[half*2][1] = rH[2];
            fBH[half*2+1][0] = rH[1]; fBH[half*2+1][1] = rH[3];
            fBL[half*2][0] = rL[0]; fBL[half*2][1] = rL[2];
            fBL[half*2+1][0] = rL[1]; fBL[half*2+1][1] = rL[3];
        }
#pragma unroll
        for (int mt = 0; mt < 2; mt++)
#pragma unroll
            for (int nt = 0; nt < 4; nt++) {
                mma16816(acc[mt][nt], fAH[mt], fBH[nt]);
                mma16816(acc[mt][nt], fAH[mt], fBL[nt]);
                mma16816(acc[mt][nt], fAL[mt], fBH[nt]);
            }
    }

    const float scale = 0.0883883476483184405f;
    float* out = sc + (size_t)h * Sm * Sm;
#pragma unroll
    for (int mt = 0; mt < 2; mt++) {
        int r1 = row0 + wm * 32 + mt * 16 + gr;
        int r2 = r1 + 8;
#pragma unroll
        for (int nt = 0; nt < 4; nt++) {
            int col = n0 + wn * 32 + nt * 8 + tg * 2;
            *(float2*)(out + (size_t)r1 * Sm + col) =
                make_float2(acc[mt][nt][0] * scale, acc[mt][nt][1] * scale);
            *(float2*)(out + (size_t)r2 * Sm + col) =
                make_float2(acc[mt][nt][2] * scale, acc[mt][nt][3] * scale);
        }
    }
}

// =============== PV via HMMA (causal-truncated K loop) ===============
#define PV_STAGE_B (26624*2)
#define PV_SMEM (2*PV_STAGE_B)

__global__ void __launch_bounds__(256, 2) pv_mma_kernel(
    const __nv_bfloat16* __restrict__ ph_, const __nv_bfloat16* __restrict__ pl_,
    const __nv_bfloat16* __restrict__ vh, const __nv_bfloat16* __restrict__ vl,
    __nv_bfloat16* __restrict__ outh, __nv_bfloat16* __restrict__ outl)
{
    extern __shared__ __nv_bfloat16 smb[];
    int h = blockIdx.y;
    int row0 = blockIdx.x * 64;
    int nst = blockIdx.x + 1;
    int kvoff = (h >> 2) * 128;
    int tid = threadIdx.x, lane = tid & 31, wid = tid >> 5;
    int gr = lane >> 2, tg = lane & 3;
    int wm = wid >> 2, wn = wid & 3;
    uint32_t smbase = smem_u32(smb);

    float acc[2][4][4];
#pragma unroll
    for (int i = 0; i < 2; i++)
#pragma unroll
        for (int j = 0; j < 4; j++)
#pragma unroll
            for (int r = 0; r < 4; r++) acc[i][j][r] = 0.f;

    auto copy_stage = [&](int st) {
        uint32_t base = smbase + (uint32_t)(st & 1) * PV_STAGE_B;
        int k0 = st * 64;
#pragma unroll
        for (int pl = 0; pl < 2; pl++) {
            const __nv_bfloat16* asrc = pl ? pl_ : ph_;
            uint32_t d0 = base + (pl ? 4608 : 0) * 2;
#pragma unroll
            for (int it = 0; it < 2; it++) {
                int idx = it * 256 + tid;
                int row = idx >> 3, ch = idx & 7;
                cpa16(d0 + (uint32_t)(row * 72 + ch * 8) * 2,
                      asrc + ((size_t)h * Sm + row0 + row) * Sm + k0 + ch * 8);
            }
        }
#pragma unroll
        for (int pl = 0; pl < 2; pl++) {
            const __nv_bfloat16* bsrc = pl ? vl : vh;
            uint32_t d0 = base + (pl ? 17920 : 9216) * 2;
#pragma unroll
            for (int it = 0; it < 4; it++) {
                int idx = it * 256 + tid;
                int row = idx >> 4, ch = idx & 15;
                cpa16(d0 + (uint32_t)(row * 136 + ch * 8) * 2,
                      bsrc + (size_t)(k0 + row) * 512 + kvoff + ch * 8);
            }
        }
        CPA_COMMIT();
    };

    copy_stage(0);
    int lr = lane & 15, lc8 = (lane & 16) >> 1;

    for (int st = 0; st < nst; st++) {
        if (st + 1 < nst) { copy_stage(st + 1); CPA_WAIT1(); }
        else              { CPA_WAIT0(); }
        __syncthreads();
        uint32_t base = smbase + (uint32_t)(st & 1) * PV_STAGE_B;
        uint32_t AHb = base, ALb = base + 9216;
        uint32_t BHb = base + 18432, BLb = base + 35840;
#pragma unroll
        for (int ks = 0; ks < 4; ks++) {
            uint32_t fAH[2][4], fAL[2][4], fBH[4][2], fBL[4][2];
#pragma unroll
            for (int mt = 0; mt < 2; mt++) {
                uint32_t ao = (uint32_t)((wm * 32 + mt * 16 + lr) * 72 + ks * 16 + lc8) * 2;
                ldm_x4(fAH[mt], AHb + ao);
                ldm_x4(fAL[mt], ALb + ao);
            }
#pragma unroll
            for (int half = 0; half < 2; half++) {
                uint32_t bo = (uint32_t)((ks * 16 + lr) * 136 + wn * 32 + half * 16 + lc8) * 2;
                uint32_t rH[4], rL[4];
                ldm_x4t(rH, BHb + bo);
                ldm_x4t(rL, BLb + bo);
                fBH[half*2][0] = rH[0]; fBH[half*2][1] = rH[1];
                fBH[half*2+1][0] = rH[2]; fBH[half*2+1][1] = rH[3];
                fBL[half*2][0] = rL[0]; fBL[half*2][1] = rL[1];
                fBL[half*2+1][0] = rL[2]; fBL[half*2+1][1] = rL[3];
            }
#pragma unroll
            for (int mt = 0; mt < 2; mt++)
#pragma unroll
                for (int nt = 0; nt < 4; nt++) {
                    mma16816(acc[mt][nt], fAH[mt], fBH[nt]);
                    mma16816(acc[mt][nt], fAH[mt], fBL[nt]);
                    mma16816(acc[mt][nt], fAL[mt], fBH[nt]);
                }
        }
        __syncthreads();
    }

#pragma unroll
    for (int mt = 0; mt < 2; mt++) {
        int r1 = row0 + wm * 32 + mt * 16 + gr;
        int r2 = r1 + 8;
#pragma unroll
        for (int nt = 0; nt < 4; nt++) {
            int col = h * 128 + wn * 32 + nt * 8 + tg * 2;
            float v0 = acc[mt][nt][0], v1 = acc[mt][nt][1];
            float v2 = acc[mt][nt][2], v3 = acc[mt][nt][3];
            uint32_t h01 = pack_bf16x2(v0, v1);
            uint32_t l01 = pack_bf16x2(v0 - __uint_as_float(h01 << 16),
                                       v1 - __uint_as_float(h01 & 0xffff0000u));
            uint32_t h23 = pack_bf16x2(v2, v3);
            uint32_t l23 = pack_bf16x2(v2 - __uint_as_float(h23 << 16),
                                       v3 - __uint_as_float(h23 & 0xffff0000u));
            *(uint32_t*)(outh + (size_t)r1 * 2048 + col) = h01;
            *(uint32_t*)(outl + (size_t)r1 * 2048 + col) = l01;
            *(uint32_t*)(outh + (size_t)r2 * 2048 + col) = h23;
            *(uint32_t*)(outl + (size_t)r2 * 2048 + col) = l23;
        }
    }
}

// ---------------- small kernels ----------------
__global__ void rmsnorm_kernel(const float* __restrict__ in, const float* __restrict__ w,
                               float* __restrict__ outf,
                               __nv_bfloat16* __restrict__ outh,
                               __nv_bfloat16* __restrict__ outl) {
    int t = blockIdx.x;
    const float* row = in + (size_t)t * Dm;
    float s = 0.f;
    for (int d = threadIdx.x; d < Dm; d += 256) { float v = row[d]; s += v * v; }
    __shared__ float red[256];
    red[threadIdx.x] = s; __syncthreads();
    for (int off = 128; off > 0; off >>= 1) {
        if (threadIdx.x < off) red[threadIdx.x] += red[threadIdx.x + off];
        __syncthreads();
    }
    float r = rsqrtf(red[0] / (float)Dm + 1e-5f);
    for (int d = threadIdx.x; d < Dm; d += 256) {
        float v = row[d] * r * w[d];
        if (outf) outf[(size_t)t * Dm + d] = v;
        split_store(v, outh, outl, (size_t)t * Dm + d);
    }
}

// log2(500000)/64
#define ROPE_C 0.29580575889569022f

__global__ void rope_planes_kernel(const float* __restrict__ qkv, const int* __restrict__ pos_ids,
                                   __nv_bfloat16* qh, __nv_bfloat16* ql,
                                   __nv_bfloat16* kh, __nv_bfloat16* kl,
                                   __nv_bfloat16* vh, __nv_bfloat16* vl) {
    int t = blockIdx.x;
    float p = (float)pos_ids[t];
    for (int idx = threadIdx.x; idx < (Hn + HKVn) * 64; idx += blockDim.x) {
        int head = idx >> 6;
        int i = idx & 63;
        float inv = exp2f(-(float)i * ROPE_C);
        float f = p * inv;
        float sn, cs;
        sincosf(f, &sn, &cs);
        if (head < Hn) {
            const float* src = qkv + (size_t)t * QKVP + head * DHn;
            float x1 = src[i], x2 = src[i + 64];
            size_t d = (size_t)t * Dm + head * DHn + i;
            split_store(x1 * cs - x2 * sn, qh, ql, d);
            split_store(x2 * cs + x1 * sn, qh, ql, d + 64);
        } else {
            int kvh = head - Hn;
            const float* src = qkv + (size_t)t * QKVP + 2048 + kvh * DHn;
            float x1 = src[i], x2 = src[i + 64];
            size_t d = (size_t)t * 512 + kvh * DHn + i;
            split_store(x1 * cs - x2 * sn, kh, kl, d);
            split_store(x2 * cs + x1 * sn, kh, kl, d + 64);
        }
    }
    for (int idx = threadIdx.x; idx < 512; idx += blockDim.x) {
        float v = qkv[(size_t)t * QKVP + 2560 + idx];
        split_store(v, vh, vl, (size_t)t * 512 + idx);
    }
}

__global__ void softmax_kernel(const float* __restrict__ sc, const int* __restrict__ mask,
                               __nv_bfloat16* __restrict__ ph, __nv_bfloat16* __restrict__ pl) {
    int i = blockIdx.x;
    int h = blockIdx.y;
    int row_end = (i & ~63) + 64;   // pv only reads j < row_end
    const float* row = sc + ((size_t)h * Sm + i) * Sm;
    int tid = threadIdx.x;
    int j0 = tid, j1 = tid + 256;
    float s0 = (j0 <= i && mask[j0] > 0) ? row[j0] : -1e9f;
    float s1 = (j1 <= i && mask[j1] > 0) ? row[j1] : -1e9f;
    __shared__ float red[256];
    red[tid] = fmaxf(s0, s1); __syncthreads();
    for (int off = 128; off > 0; off >>= 1) {
        if (tid < off) red[tid] = fmaxf(red[tid], red[tid + off]);
        __syncthreads();
    }
    float m = red[0];
    __syncthreads();
    float e0 = expf(s0 - m), e1 = expf(s1 - m);
    red[tid] = e0 + e1; __syncthreads();
    for (int off = 128; off > 0; off >>= 1) {
        if (tid < off) red[tid] += red[tid + off];
        __syncthreads();
    }
    float inv = 1.f / red[0];
    size_t base = ((size_t)h * Sm + i) * Sm;
    if (j0 < row_end) split_store(e0 * inv, ph, pl, base + j0);
    if (j1 < row_end) split_store(e1 * inv, ph, pl, base + j1);
}

__global__ void router_kernel(const float* __restrict__ x2, const float* __restrict__ rw,
                              int* __restrict__ topidx, float* __restrict__ topscore) {
    int t = blockIdx.x;
    int w = threadIdx.x >> 5, lane = threadIdx.x & 31;
    float s = 0.f;
    for (int d = lane; d < Dm; d += 32)
        s += x2[(size_t)t * Dm + d] * rw[d * En + w];
    for (int off = 16; off; off >>= 1) s += __shfl_down_sync(0xffffffff, s, off);
    __shared__ float logits[En];
    if (lane == 0) logits[w] = s;
    __syncthreads();
    if (threadIdx.x == 0) {
        int best = 0; float bv = logits[0];
        for (int e = 1; e < En; e++) if (logits[e] > bv) { bv = logits[e]; best = e; }
        topidx[t] = best;
        topscore[t] = 1.f / (1.f + expf(-bv));
    }
}

__global__ void dispatch_kernel(const int* __restrict__ topidx) {
    int t = threadIdx.x;
    if (t < En) g_cnt[t] = 0;
    __syncthreads();
    int e = topidx[t];
    int pos = atomicAdd(&g_cnt[e], 1);
    g_list[e * Sm + pos] = t;
}

// combined silu-mul for expert gu and shared sgu
__global__ void silumul2_kernel(const float* __restrict__ gu, const float* __restrict__ sgu,
                                __nv_bfloat16* __restrict__ ah, __nv_bfloat16* __restrict__ al,
                                __nv_bfloat16* __restrict__ sh, __nv_bfloat16* __restrict__ sl) {
    int i = blockIdx.x * 256 + threadIdx.x;
    const float* src = gu;
    __nv_bfloat16* oh = ah;
    __nv_bfloat16* ol = al;
    int j = i;
    if (i >= Sm * Dm) {
        j = i - Sm * Dm;
        src = sgu; oh = sh; ol = sl;
    }
    int t = j >> 11, c = j & 2047;
    float g = src[(size_t)t * 4096 + c];
    float u = src[(size_t)t * 4096 + 2048 + c];
    float a = (g / (1.f + expf(-g))) * u;
    split_store(a, oh, ol, (size_t)j);
}

__global__ void add3_kernel(const float* __restrict__ a, const float* __restrict__ b,
                            const float* __restrict__ c, float* __restrict__ out) {
    int i = blockIdx.x * 256 + threadIdx.x;
    out[i] = a[i] + b[i] + c[i];
}

// ---------------- launch ----------------
#define GSYM(p, s) cudaGetSymbolAddress((void**)&p, s)
#define NSBIG 0x40000000

extern "C" void kernel_launch(void* const* d_in, const int* in_sizes, int n_in,
                              void* d_out, int out_size) {
    const float* hidden   = (const float*)d_in[0];
    const int*   amask    = (const int*)  d_in[1];
    const int*   pos      = (const int*)  d_in[2];
    const float* attn_nw  = (const float*)d_in[3];
    const float* wq       = (const float*)d_in[4];
    const float* wk       = (const float*)d_in[5];
    const float* wv       = (const float*)d_in[6];
    const float* wo       = (const float*)d_in[7];
    const float* ffn_nw   = (const float*)d_in[8];
    const float* router_w = (const float*)d_in[9];
    const float* w_gate   = (const float*)d_in[10];
    const float* w_up     = (const float*)d_in[11];
    const float* w_down   = (const float*)d_in[12];
    const float* ws_gate  = (const float*)d_in[13];
    const float* ws_up    = (const float*)d_in[14];
    const float* ws_down  = (const float*)d_in[15];
    float* out = (float*)d_out;

    float *pqkv, *psc, *phf, *px2f, *pgu, *psgu, *prouted, *pshared, *pts;
    int *pti;
    __nv_bfloat16 *pxh, *pxl, *path, *patl, *px2h, *px2l, *pach, *pacl, *psah, *psal;
    __nv_bfloat16 *pqh, *pql, *pkh, *pkl, *pvh, *pvl, *pph, *ppl;
    GSYM(pqkv, g_qkv); GSYM(psc, g_scores); GSYM(phf, g_h); GSYM(px2f, g_x2f);
    GSYM(pgu, g_gu); GSYM(psgu, g_sgu); GSYM(prouted, g_routed); GSYM(pshared, g_shared);
    GSYM(pti, g_topidx); GSYM(pts, g_topscore);
    GSYM(pxh, x_h); GSYM(pxl, x_l); GSYM(path, at_h); GSYM(patl, at_l);
    GSYM(px2h, x2_h); GSYM(px2l, x2_l); GSYM(pach, ac_h); GSYM(pacl, ac_l);
    GSYM(psah, sa_h); GSYM(psal, sa_l);
    GSYM(pqh, q_h); GSYM(pql, q_l); GSYM(pkh, k_h); GSYM(pkl, k_l);
    GSYM(pvh, v_h); GSYM(pvl, v_l); GSYM(pph, p_h); GSYM(ppl, p_l);

    cudaFuncSetAttribute(tgemm_kernel, cudaFuncAttributeMaxDynamicSharedMemorySize, TG_SMEM);
    cudaFuncSetAttribute(scores_mma_kernel, cudaFuncAttributeMaxDynamicSharedMemorySize, SC_SMEM);
    cudaFuncSetAttribute(pv_mma_kernel, cudaFuncAttributeMaxDynamicSharedMemorySize, PV_SMEM);

    // --- attention block ---
    rmsnorm_kernel<<<Sm, 256>>>(hidden, attn_nw, nullptr, pxh, pxl);
    // fused QKV single launch: n<2048 -> wq, n<2560 -> wk, else wv
    tgemm_kernel<<<dim3(24, 8), 256, TG_SMEM>>>(pxh, pxl, wq, wk, wv,
                                                2048, 512, 512, 2048, 2560,
                                                pqkv, 3072, nullptr, nullptr, 0,
                                                nullptr, nullptr, nullptr, nullptr, nullptr);
    rope_planes_kernel<<<Sm, 256>>>(pqkv, pos, pqh, pql, pkh, pkl, pvh, pvl);
    scores_mma_kernel<<<dim3(4, 8, Hn), 256, SC_SMEM>>>(pqh, pql, pkh, pkl, psc);
    softmax_kernel<<<dim3(Sm, Hn), 256>>>(psc, amask, pph, ppl);
    pv_mma_kernel<<<dim3(8, Hn), 256, PV_SMEM>>>(pph, ppl, pvh, pvl, path, patl);
    tgemm_kernel<<<dim3(16, 8), 256, TG_SMEM>>>(path, patl, wo, nullptr, nullptr,
                                                2048, 0, 0, NSBIG, NSBIG,
                                                phf, 2048, hidden, nullptr, 0,
                                                nullptr, nullptr, nullptr, nullptr, nullptr);

    // --- MoE block ---
    rmsnorm_kernel<<<Sm, 256>>>(phf, ffn_nw, px2f, px2h, px2l);
    router_kernel<<<Sm, 256>>>(px2f, router_w, pti, pts);
    dispatch_kernel<<<1, Sm>>>(pti);
    // combined: z<8 expert gate|up (gathered, scaled); z=8 shared gate|up (dense)
    tgemm_kernel<<<dim3(32, 8, En + 1), 256, TG_SMEM>>>(px2h, px2l, w_gate, w_up, nullptr,
                                                        2048, 2048, 0, 2048, NSBIG,
                                                        pgu, 4096, nullptr, pts, 1,
                                                        px2h, px2l, ws_gate, ws_up, psgu);
    silumul2_kernel<<<(2 * Sm * Dm) / 256, 256>>>(pgu, psgu, pach, pacl, psah, psal);
    // combined: z<8 expert down (gathered); z=8 shared down (dense)
    tgemm_kernel<<<dim3(16, 8, En + 1), 256, TG_SMEM>>>(pach, pacl, w_down, nullptr, nullptr,
                                                        2048, 0, 0, NSBIG, NSBIG,
                                                        prouted, 2048, nullptr, nullptr, 1,
                                                        psah, psal, ws_down, nullptr, pshared);

    // final: out = h + routed + shared
    add3_kernel<<<(Sm * Dm) / 256, 256>>>(phf, prouted, pshared, out);
}

// round 14
// speedup vs baseline: 1.5277x; 1.1582x over previous
#include <cuda_runtime.h>
#include <cuda_fp16.h>
#include <stdint.h>
#include <math.h>

#define Dm   2048
#define Sm   512
#define Hn   16
#define HKVn 4
#define DHn  128
#define Fn   2048
#define En   8
#define QKVP 3072

// ---------------- scratch (device globals) ----------------
__device__ float g_qkv[Sm*QKVP];
__device__ float g_scores[Hn*Sm*Sm];
__device__ float g_h[Sm*Dm];
__device__ float g_x2f[Sm*Dm];
__device__ float g_gu[Sm*4096];
__device__ float g_sgu[Sm*4096];
__device__ float g_routed[Sm*Dm];
__device__ float g_shared[Sm*Dm];
__device__ int   g_topidx[Sm];
__device__ float g_topscore[Sm];
__device__ int   g_cnt[En];
__device__ int   g_list[En*Sm];

// activation fp16 hi/lo planes (A-side operands get hi+lo; B-side get hi only)
__device__ __half x_h[Sm*Dm],  x_l[Sm*Dm];
__device__ __half at_h[Sm*Dm], at_l[Sm*Dm];
__device__ __half x2_h[Sm*Dm], x2_l[Sm*Dm];
__device__ __half ac_h[Sm*Dm], ac_l[Sm*Dm];
__device__ __half sa_h[Sm*Dm], sa_l[Sm*Dm];
__device__ __half q_h[Sm*Dm],  q_l[Sm*Dm];
__device__ __half k_h[Sm*512];
__device__ __half v_h[Sm*512];
__device__ __half p_h[Hn*Sm*Sm], p_l[Hn*Sm*Sm];

// ---------------- helpers ----------------
__device__ __forceinline__ uint32_t smem_u32(const void* p) {
    uint32_t a;
    asm("{ .reg .u64 t; cvta.to.shared.u64 t, %1; cvt.u32.u64 %0, t; }" : "=r"(a) : "l"(p));
    return a;
}
// a -> low element, b -> high element
__device__ __forceinline__ uint32_t pack_f16x2(float a, float b) {
    __half2 h = __floats2half2_rn(a, b);
    return *(uint32_t*)&h;
}
__device__ __forceinline__ void mma16816(float c[4], const uint32_t a[4], const uint32_t b[2]) {
    asm volatile(
        "mma.sync.aligned.m16n8k16.row.col.f32.f16.f16.f32 "
        "{%0,%1,%2,%3}, {%4,%5,%6,%7}, {%8,%9}, {%0,%1,%2,%3};"
        : "+f"(c[0]), "+f"(c[1]), "+f"(c[2]), "+f"(c[3])
        : "r"(a[0]), "r"(a[1]), "r"(a[2]), "r"(a[3]), "r"(b[0]), "r"(b[1]));
}
__device__ __forceinline__ void cpa16(uint32_t d, const void* s) {
    asm volatile("cp.async.cg.shared.global [%0], [%1], 16;" :: "r"(d), "l"(s));
}
#define CPA_COMMIT() asm volatile("cp.async.commit_group;" ::: "memory")
#define CPA_WAIT1()  asm volatile("cp.async.wait_group 1;" ::: "memory")
#define CPA_WAIT0()  asm volatile("cp.async.wait_group 0;" ::: "memory")
__device__ __forceinline__ void ldm_x4(uint32_t r[4], uint32_t a) {
    asm volatile("ldmatrix.sync.aligned.m8n8.x4.shared.b16 {%0,%1,%2,%3}, [%4];"
        : "=r"(r[0]), "=r"(r[1]), "=r"(r[2]), "=r"(r[3]) : "r"(a));
}
__device__ __forceinline__ void ldm_x4t(uint32_t r[4], uint32_t a) {
    asm volatile("ldmatrix.sync.aligned.m8n8.x4.trans.shared.b16 {%0,%1,%2,%3}, [%4];"
        : "=r"(r[0]), "=r"(r[1]), "=r"(r[2]), "=r"(r[3]) : "r"(a));
}
__device__ __forceinline__ void split_store(float v, __half* ph, __half* pl, size_t off) {
    __half h = __float2half_rn(v);
    ph[off] = h;
    pl[off] = __float2half_rn(v - __half2float(h));
}

// =============== fp16 2-pass HMMA GEMM, 64x128 tile, K=2048 ===============
// B: LDG fp32 -> regs (1-stage prefetch) -> convert -> STS fp16 hi plane (double buf)
// A: cp.async fp16 hi/lo planes (triple buf). ONE barrier per 32-k stage.
#define KST 32
#define A_PITCH 40
#define A_PLANE_B (64*A_PITCH*2)      // 5120
#define A_BUF_B (2*A_PLANE_B)         // 10240 (hi+lo)
#define BB_PITCH 136
#define BB_PLANE_B (KST*BB_PITCH*2)   // 8704
#define OFF_BB (3*A_BUF_B)            // 30720
#define TG_SMEM (OFF_BB + 2*BB_PLANE_B)  // 48128

__global__ void __launch_bounds__(256, 2) tgemm_kernel(
    const __half* __restrict__ aH, const __half* __restrict__ aL,
    const float* __restrict__ B0, const float* __restrict__ B1, const float* __restrict__ B2,
    int ldb0, int ldb1, int ldb2, int ns1, int ns2,
    float* __restrict__ C, int ldc,
    const float* __restrict__ res, const float* __restrict__ rowscale, int mode,
    const __half* __restrict__ sAh, const __half* __restrict__ sAl,
    const float* __restrict__ sB0, const float* __restrict__ sB1,
    float* __restrict__ sC)
{
    extern __shared__ char smc[];
    __shared__ int   tok[64];
    __shared__ float scl[64];
    int row0 = blockIdx.y * 64;
    int n0   = blockIdx.x * 128;
    int tid  = threadIdx.x;

    int gather = mode;
    if (mode == 1 && blockIdx.z == En) {
        aH = sAh; aL = sAl; B0 = sB0; B1 = sB1; C = sC;
        rowscale = nullptr;
        gather = 0;
    }

    const float* Bsel; int ldbs; int ncol;
    if (n0 < ns1)      { Bsel = B0; ldbs = ldb0; ncol = n0; }
    else if (n0 < ns2) { Bsel = B1; ldbs = ldb1; ncol = n0 - ns1; }
    else               { Bsel = B2; ldbs = ldb2; ncol = n0 - ns2; }

    if (gather) {
        int e = blockIdx.z;
        int count = g_cnt[e];
        if (row0 >= count) return;
        Bsel += (size_t)e * 2048 * ldbs;
        if (tid < 64) {
            int r = row0 + tid;
            int t = (r < count) ? g_list[e * Sm + r] : -1;
            tok[tid] = t;
            scl[tid] = (t >= 0 && rowscale) ? rowscale[t] : 1.0f;
        }
    } else {
        if (tid < 64) { tok[tid] = row0 + tid; scl[tid] = 1.0f; }
    }
    __syncthreads();

    uint32_t smbase = smem_u32(smc);
    int lane = tid & 31, wid = tid >> 5;
    int gr = lane >> 2, tg = lane & 3;
    int wm = wid >> 2, wn = wid & 3;

    float acc[2][4][4];
#pragma unroll
    for (int i = 0; i < 2; i++)
#pragma unroll
        for (int j = 0; j < 4; j++)
#pragma unroll
            for (int r = 0; r < 4; r++) acc[i][j][r] = 0.f;

    int arow = tid >> 2, ach = tid & 3;
    int at = tok[arow];
    int agrow = at < 0 ? 0 : at;

    int bk[4], bc[4];
#pragma unroll
    for (int it = 0; it < 4; it++) {
        int chunk = it * 256 + tid;
        bk[it] = chunk >> 5;
        bc[it] = (chunk & 31) * 4;
    }

    auto copy_A = [&](int st) {
        uint32_t ab = smbase + (uint32_t)(st % 3) * A_BUF_B;
        int k0 = st * KST;
        cpa16(ab + (uint32_t)(arow * A_PITCH + ach * 8) * 2,
              aH + (size_t)agrow * 2048 + k0 + ach * 8);
        cpa16(ab + A_PLANE_B + (uint32_t)(arow * A_PITCH + ach * 8) * 2,
              aL + (size_t)agrow * 2048 + k0 + ach * 8);
        CPA_COMMIT();
    };

    float4 va[4];
    auto ldg_B = [&](int st) {
        int k0 = st * KST;
#pragma unroll
        for (int it = 0; it < 4; it++)
            va[it] = *(const float4*)(Bsel + (size_t)(k0 + bk[it]) * ldbs + ncol + bc[it]);
    };

    ldg_B(0);
    copy_A(0);

    int lr = lane & 15;
    int lc8 = (lane & 16) >> 1;

    for (int st = 0; st < 64; st++) {
        // convert B(st) from regs -> BB[st&1] (fp16 hi only)
        {
            __half* bh = (__half*)(smc + OFF_BB + (st & 1) * BB_PLANE_B);
#pragma unroll
            for (int it = 0; it < 4; it++) {
                float4 v = va[it];
                uint32_t h01 = pack_f16x2(v.x, v.y);
                uint32_t h23 = pack_f16x2(v.z, v.w);
                int o = bk[it] * BB_PITCH + bc[it];
                *(uint2*)(bh + o) = make_uint2(h01, h23);
            }
        }
        if (st < 63) {
            ldg_B(st + 1);
            copy_A(st + 1);
            CPA_WAIT1();
        } else {
            CPA_WAIT0();
        }
        __syncthreads();

        // ---- MMA: 2 k16 steps, 2 passes ----
        uint32_t ab = smbase + (uint32_t)(st % 3) * A_BUF_B;
        uint32_t AHb = ab, ALb = ab + A_PLANE_B;
        uint32_t BHb = smbase + OFF_BB + (uint32_t)(st & 1) * BB_PLANE_B;
#pragma unroll
        for (int ks = 0; ks < 2; ks++) {
            uint32_t fAH[2][4], fAL[2][4], fBH[4][2];
#pragma unroll
            for (int mt = 0; mt < 2; mt++) {
                uint32_t ao = (uint32_t)((wm * 32 + mt * 16 + lr) * A_PITCH + ks * 16 + lc8) * 2;
                ldm_x4(fAH[mt], AHb + ao);
                ldm_x4(fAL[mt], ALb + ao);
            }
#pragma unroll
            for (int half = 0; half < 2; half++) {
                int brow = ks * 16 + lr;
                int bcol = wn * 32 + half * 16 + lc8;
                uint32_t bo = (uint32_t)(brow * BB_PITCH + bcol) * 2;
                uint32_t rH[4];
                ldm_x4t(rH, BHb + bo);
                fBH[half*2][0] = rH[0]; fBH[half*2][1] = rH[1];
                fBH[half*2+1][0] = rH[2]; fBH[half*2+1][1] = rH[3];
            }
#pragma unroll
            for (int mt = 0; mt < 2; mt++)
#pragma unroll
                for (int nt = 0; nt < 4; nt++) {
                    mma16816(acc[mt][nt], fAH[mt], fBH[nt]);
                    mma16816(acc[mt][nt], fAL[mt], fBH[nt]);
                }
        }
    }

    // ---- epilogue ----
#pragma unroll
    for (int mt = 0; mt < 2; mt++) {
        int r1 = wm * 32 + mt * 16 + gr;
        int r2 = r1 + 8;
        int t1 = tok[r1], t2 = tok[r2];
        float s1 = scl[r1], s2 = scl[r2];
#pragma unroll
        for (int nt = 0; nt < 4; nt++) {
            int col = n0 + wn * 32 + nt * 8 + tg * 2;
            if (t1 >= 0) {
                float2 o = make_float2(acc[mt][nt][0] * s1, acc[mt][nt][1] * s1);
                if (res) {
                    float2 rv = *(const float2*)(res + (size_t)t1 * ldc + col);
                    o.x += rv.x; o.y += rv.y;
                }
                *(float2*)(C + (size_t)t1 * ldc + col) = o;
            }
            if (t2 >= 0) {
                float2 o = make_float2(acc[mt][nt][2] * s2, acc[mt][nt][3] * s2);
                if (res) {
                    float2 rv = *(const float2*)(res + (size_t)t2 * ldc + col);
                    o.x += rv.x; o.y += rv.y;
                }
                *(float2*)(C + (size_t)t2 * ldc + col) = o;
            }
        }
    }
}

// =============== attention scores via HMMA (causal-skip, fp16 2-pass) ===============
// smem elems: QH[64][136]@0, QL@8704, KH[128][136]@17408 ; total 34816 elems
#define SC_SMEM (34816*2)

__global__ void __launch_bounds__(256, 2) scores_mma_kernel(
    const __half* __restrict__ qh, const __half* __restrict__ ql,
    const __half* __restrict__ kh,
    float* __restrict__ sc)
{
    extern __shared__ __half smb[];
    int h = blockIdx.z;
    int row0 = blockIdx.y * 64;
    int n0 = blockIdx.x * 128;
    if (n0 >= row0 + 64) return;
    int tid = threadIdx.x, lane = tid & 31, wid = tid >> 5;
    int gr = lane >> 2, tg = lane & 3;
    int wm = wid >> 2, wn = wid & 3;
    uint32_t base = smem_u32(smb);

#pragma unroll
    for (int pl = 0; pl < 2; pl++) {
        const __half* src = pl ? ql : qh;
        uint32_t d0 = base + (pl ? 8704u : 0u) * 2;
#pragma unroll
        for (int it = 0; it < 4; it++) {
            int idx = it * 256 + tid;
            int r = idx >> 4, ch = idx & 15;
            cpa16(d0 + (uint32_t)(r * 136 + ch * 8) * 2,
                  src + (size_t)(row0 + r) * 2048 + h * 128 + ch * 8);
        }
    }
    {
        uint32_t d0 = base + 17408u * 2;
#pragma unroll
        for (int it = 0; it < 8; it++) {
            int idx = it * 256 + tid;
            int r = idx >> 4, ch = idx & 15;
            cpa16(d0 + (uint32_t)(r * 136 + ch * 8) * 2,
                  kh + (size_t)(n0 + r) * 512 + (h >> 2) * 128 + ch * 8);
        }
    }
    CPA_COMMIT(); CPA_WAIT0();
    __syncthreads();

    float acc[2][4][4];
#pragma unroll
    for (int i = 0; i < 2; i++)
#pragma unroll
        for (int j = 0; j < 4; j++)
#pragma unroll
            for (int r = 0; r < 4; r++) acc[i][j][r] = 0.f;

    int lr = lane & 15, lc8 = (lane & 16) >> 1;
    uint32_t QHb = base, QLb = base + 17408;
    uint32_t KHb = base + 34816;

#pragma unroll
    for (int ks = 0; ks < 8; ks++) {
        uint32_t fAH[2][4], fAL[2][4], fBH[4][2];
#pragma unroll
        for (int mt = 0; mt < 2; mt++) {
            uint32_t ao = (uint32_t)((wm * 32 + mt * 16 + lr) * 136 + ks * 16 + lc8) * 2;
            ldm_x4(fAH[mt], QHb + ao);
            ldm_x4(fAL[mt], QLb + ao);
        }
#pragma unroll
        for (int half = 0; half < 2; half++) {
            uint32_t bo = (uint32_t)((wn * 32 + half * 16 + lr) * 136 + ks * 16 + lc8) * 2;
            uint32_t rH[4];
            ldm_x4(rH, KHb + bo);
            fBH[half*2][0] = rH[0]; fBH[half*2][1] = rH[2];
            fBH[half*2+1][0] = rH[1]; fBH[half*2+1][1] = rH[3];
        }
#pragma unroll
        for (int mt = 0; mt < 2; mt++)
#pragma unroll
            for (int nt = 0; nt < 4; nt++) {
                mma16816(acc[mt][nt], fAH[mt], fBH[nt]);
                mma16816(acc[mt][nt], fAL[mt], fBH[nt]);
            }
    }

    const float scale = 0.0883883476483184405f;
    float* out = sc + (size_t)h * Sm * Sm;
#pragma unroll
    for (int mt = 0; mt < 2; mt++) {
        int r1 = row0 + wm * 32 + mt * 16 + gr;
        int r2 = r1 + 8;
#pragma unroll
        for (int nt = 0; nt < 4; nt++) {
            int col = n0 + wn * 32 + nt * 8 + tg * 2;
            *(float2*)(out + (size_t)r1 * Sm + col) =
                make_float2(acc[mt][nt][0] * scale, acc[mt][nt][1] * scale);
            *(float2*)(out + (size_t)r2 * Sm + col) =
                make_float2(acc[mt][nt][2] * scale, acc[mt][nt][3] * scale);
        }
    }
}

// =============== PV via HMMA (causal-truncated, fp16 2-pass) ===============
// stage elems: PH[64][72]@0, PL@4608, VH[64][136]@9216 ; 17920 elems = 35840 B
#define PV_STAGE_B (17920*2)
#define PV_SMEM (2*PV_STAGE_B)

__global__ void __launch_bounds__(256, 2) pv_mma_kernel(
    const __half* __restrict__ ph_, const __half* __restrict__ pl_,
    const __half* __restrict__ vh,
    __half* __restrict__ outh, __half* __restrict__ outl)
{
    extern __shared__ __half smb[];
    int h = blockIdx.y;
    int row0 = blockIdx.x * 64;
    int nst = blockIdx.x + 1;
    int kvoff = (h >> 2) * 128;
    int tid = threadIdx.x, lane = tid & 31, wid = tid >> 5;
    int gr = lane >> 2, tg = lane & 3;
    int wm = wid >> 2, wn = wid & 3;
    uint32_t smbase = smem_u32(smb);

    float acc[2][4][4];
#pragma unroll
    for (int i = 0; i < 2; i++)
#pragma unroll
        for (int j = 0; j < 4; j++)
#pragma unroll
            for (int r = 0; r < 4; r++) acc[i][j][r] = 0.f;

    auto copy_stage = [&](int st) {
        uint32_t base = smbase + (uint32_t)(st & 1) * PV_STAGE_B;
        int k0 = st * 64;
#pragma unroll
        for (int pl = 0; pl < 2; pl++) {
            const __half* asrc = pl ? pl_ : ph_;
            uint32_t d0 = base + (pl ? 4608 : 0) * 2;
#pragma unroll
            for (int it = 0; it < 2; it++) {
                int idx = it * 256 + tid;
                int row = idx >> 3, ch = idx & 7;
                cpa16(d0 + (uint32_t)(row * 72 + ch * 8) * 2,
                      asrc + ((size_t)h * Sm + row0 + row) * Sm + k0 + ch * 8);
            }
        }
        {
            uint32_t d0 = base + 9216 * 2;
#pragma unroll
            for (int it = 0; it < 4; it++) {
                int idx = it * 256 + tid;
                int row = idx >> 4, ch = idx & 15;
                cpa16(d0 + (uint32_t)(row * 136 + ch * 8) * 2,
                      vh + (size_t)(k0 + row) * 512 + kvoff + ch * 8);
            }
        }
        CPA_COMMIT();
    };

    copy_stage(0);
    int lr = lane & 15, lc8 = (lane & 16) >> 1;

    for (int st = 0; st < nst; st++) {
        if (st + 1 < nst) { copy_stage(st + 1); CPA_WAIT1(); }
        else              { CPA_WAIT0(); }
        __syncthreads();
        uint32_t base = smbase + (uint32_t)(st & 1) * PV_STAGE_B;
        uint32_t AHb = base, ALb = base + 9216;
        uint32_t BHb = base + 18432;
#pragma unroll
        for (int ks = 0; ks < 4; ks++) {
            uint32_t fAH[2][4], fAL[2][4], fBH[4][2];
#pragma unroll
            for (int mt = 0; mt < 2; mt++) {
                uint32_t ao = (uint32_t)((wm * 32 + mt * 16 + lr) * 72 + ks * 16 + lc8) * 2;
                ldm_x4(fAH[mt], AHb + ao);
                ldm_x4(fAL[mt], ALb + ao);
            }
#pragma unroll
            for (int half = 0; half < 2; half++) {
                uint32_t bo = (uint32_t)((ks * 16 + lr) * 136 + wn * 32 + half * 16 + lc8) * 2;
                uint32_t rH[4];
                ldm_x4t(rH, BHb + bo);
                fBH[half*2][0] = rH[0]; fBH[half*2][1] = rH[1];
                fBH[half*2+1][0] = rH[2]; fBH[half*2+1][1] = rH[3];
            }
#pragma unroll
            for (int mt = 0; mt < 2; mt++)
#pragma unroll
                for (int nt = 0; nt < 4; nt++) {
                    mma16816(acc[mt][nt], fAH[mt], fBH[nt]);
                    mma16816(acc[mt][nt], fAL[mt], fBH[nt]);
                }
        }
        __syncthreads();
    }

#pragma unroll
    for (int mt = 0; mt < 2; mt++) {
        int r1 = row0 + wm * 32 + mt * 16 + gr;
        int r2 = r1 + 8;
#pragma unroll
        for (int nt = 0; nt < 4; nt++) {
            int col = h * 128 + wn * 32 + nt * 8 + tg * 2;
            float v0 = acc[mt][nt][0], v1 = acc[mt][nt][1];
            float v2 = acc[mt][nt][2], v3 = acc[mt][nt][3];
            __half2 hh1 = __floats2half2_rn(v0, v1);
            __half2 ll1 = __floats2half2_rn(v0 - __half2float(__low2half(hh1)),
                                            v1 - __half2float(__high2half(hh1)));
            __half2 hh2 = __floats2half2_rn(v2, v3);
            __half2 ll2 = __floats2half2_rn(v2 - __half2float(__low2half(hh2)),
                                            v3 - __half2float(__high2half(hh2)));
            *(__half2*)(outh + (size_t)r1 * 2048 + col) = hh1;
            *(__half2*)(outl + (size_t)r1 * 2048 + col) = ll1;
            *(__half2*)(outh + (size_t)r2 * 2048 + col) = hh2;
            *(__half2*)(outl + (size_t)r2 * 2048 + col) = ll2;
        }
    }
}

// ---------------- small kernels ----------------
__global__ void rmsnorm_kernel(const float* __restrict__ in, const float* __restrict__ w,
                               float* __restrict__ outf,
                               __half* __restrict__ outh, __half* __restrict__ outl) {
    int t = blockIdx.x;
    const float* row = in + (size_t)t * Dm;
    float s = 0.f;
    for (int d = threadIdx.x; d < Dm; d += 256) { float v = row[d]; s += v * v; }
    __shared__ float red[256];
    red[threadIdx.x] = s; __syncthreads();
    for (int off = 128; off > 0; off >>= 1) {
        if (threadIdx.x < off) red[threadIdx.x] += red[threadIdx.x + off];
        __syncthreads();
    }
    float r = rsqrtf(red[0] / (float)Dm + 1e-5f);
    for (int d = threadIdx.x; d < Dm; d += 256) {
        float v = row[d] * r * w[d];
        if (outf) outf[(size_t)t * Dm + d] = v;
        split_store(v, outh, outl, (size_t)t * Dm + d);
    }
}

// log2(500000)/64
#define ROPE_C 0.29580575889569022f

__global__ void rope_planes_kernel(const float* __restrict__ qkv, const int* __restrict__ pos_ids,
                                   __half* qh, __half* ql, __half* kh, __half* vh) {
    int t = blockIdx.x;
    float p = (float)pos_ids[t];
    for (int idx = threadIdx.x; idx < (Hn + HKVn) * 64; idx += blockDim.x) {
        int head = idx >> 6;
        int i = idx & 63;
        float inv = exp2f(-(float)i * ROPE_C);
        float f = p * inv;
        float sn, cs;
        sincosf(f, &sn, &cs);
        if (head < Hn) {
            const float* src = qkv + (size_t)t * QKVP + head * DHn;
            float x1 = src[i], x2 = src[i + 64];
            size_t d = (size_t)t * Dm + head * DHn + i;
            split_store(x1 * cs - x2 * sn, qh, ql, d);
            split_store(x2 * cs + x1 * sn, qh, ql, d + 64);
        } else {
            int kvh = head - Hn;
            const float* src = qkv + (size_t)t * QKVP + 2048 + kvh * DHn;
            float x1 = src[i], x2 = src[i + 64];
            size_t d = (size_t)t * 512 + kvh * DHn + i;
            kh[d]      = __float2half_rn(x1 * cs - x2 * sn);
            kh[d + 64] = __float2half_rn(x2 * cs + x1 * sn);
        }
    }
    for (int idx = threadIdx.x; idx < 512; idx += blockDim.x) {
        vh[(size_t)t * 512 + idx] = __float2half_rn(qkv[(size_t)t * QKVP + 2560 + idx]);
    }
}

__global__ void softmax_kernel(const float* __restrict__ sc, const int* __restrict__ mask,
                               __half* __restrict__ ph, __half* __restrict__ pl) {
    int i = blockIdx.x;
    int h = blockIdx.y;
    int row_end = (i & ~63) + 64;   // pv only reads j < row_end
    const float* row = sc + ((size_t)h * Sm + i) * Sm;
    int tid = threadIdx.x;
    int j0 = tid, j1 = tid + 256;
    float s0 = (j0 <= i && mask[j0] > 0) ? row[j0] : -1e9f;
    float s1 = (j1 <= i && mask[j1] > 0) ? row[j1] : -1e9f;
    __shared__ float red[256];
    red[tid] = fmaxf(s0, s1); __syncthreads();
    for (int off = 128; off > 0; off >>= 1) {
        if (tid < off) red[tid] = fmaxf(red[tid], red[tid + off]);
        __syncthreads();
    }
    float m = red[0];
    __syncthreads();
    float e0 = expf(s0 - m), e1 = expf(s1 - m);
    red[tid] = e0 + e1; __syncthreads();
    for (int off = 128; off > 0; off >>= 1) {
        if (tid < off) red[tid] += red[tid + off];
        __syncthreads();
    }
    float inv = 1.f / red[0];
    size_t base = ((size_t)h * Sm + i) * Sm;
    if (j0 < row_end) split_store(e0 * inv, ph, pl, base + j0);
    if (j1 < row_end) split_store(e1 * inv, ph, pl, base + j1);
}

__global__ void router_kernel(const float* __restrict__ x2, const float* __restrict__ rw,
                              int* __restrict__ topidx, float* __restrict__ topscore) {
    int t = blockIdx.x;
    int w = threadIdx.x >> 5, lane = threadIdx.x & 31;
    float s = 0.f;
    for (int d = lane; d < Dm; d += 32)
        s += x2[(size_t)t * Dm + d] * rw[d * En + w];
    for (int off = 16; off; off >>= 1) s += __shfl_down_sync(0xffffffff, s, off);
    __shared__ float logits[En];
    if (lane == 0) logits[w] = s;
    __syncthreads();
    if (threadIdx.x == 0) {
        int best = 0; float bv = logits[0];
        for (int e = 1; e < En; e++) if (logits[e] > bv) { bv = logits[e]; best = e; }
        topidx[t] = best;
        topscore[t] = 1.f / (1.f + expf(-bv));
    }
}

__global__ void dispatch_kernel(const int* __restrict__ topidx) {
    int t = threadIdx.x;
    if (t < En) g_cnt[t] = 0;
    __syncthreads();
    int e = topidx[t];
    int pos = atomicAdd(&g_cnt[e], 1);
    g_list[e * Sm + pos] = t;
}

// combined silu-mul for expert gu and shared sgu
__global__ void silumul2_kernel(const float* __restrict__ gu, const float* __restrict__ sgu,
                                __half* __restrict__ ah, __half* __restrict__ al,
                                __half* __restrict__ sh, __half* __restrict__ sl) {
    int i = blockIdx.x * 256 + threadIdx.x;
    const float* src = gu;
    __half* oh = ah;
    __half* ol = al;
    int j = i;
    if (i >= Sm * Dm) {
        j = i - Sm * Dm;
        src = sgu; oh = sh; ol = sl;
    }
    int t = j >> 11, c = j & 2047;
    float g = src[(size_t)t * 4096 + c];
    float u = src[(size_t)t * 4096 + 2048 + c];
    float a = (g / (1.f + expf(-g))) * u;
    split_store(a, oh, ol, (size_t)j);
}

__global__ void add3_kernel(const float* __restrict__ a, const float* __restrict__ b,
                            const float* __restrict__ c, float* __restrict__ out) {
    int i = blockIdx.x * 256 + threadIdx.x;
    out[i] = a[i] + b[i] + c[i];
}

// ---------------- launch ----------------
#define GSYM(p, s) cudaGetSymbolAddress((void**)&p, s)
#define NSBIG 0x40000000

extern "C" void kernel_launch(void* const* d_in, const int* in_sizes, int n_in,
                              void* d_out, int out_size) {
    const float* hidden   = (const float*)d_in[0];
    const int*   amask    = (const int*)  d_in[1];
    const int*   pos      = (const int*)  d_in[2];
    const float* attn_nw  = (const float*)d_in[3];
    const float* wq       = (const float*)d_in[4];
    const float* wk       = (const float*)d_in[5];
    const float* wv       = (const float*)d_in[6];
    const float* wo       = (const float*)d_in[7];
    const float* ffn_nw   = (const float*)d_in[8];
    const float* router_w = (const float*)d_in[9];
    const float* w_gate   = (const float*)d_in[10];
    const float* w_up     = (const float*)d_in[11];
    const float* w_down   = (const float*)d_in[12];
    const float* ws_gate  = (const float*)d_in[13];
    const float* ws_up    = (const float*)d_in[14];
    const float* ws_down  = (const float*)d_in[15];
    float* out = (float*)d_out;

    float *pqkv, *psc, *phf, *px2f, *pgu, *psgu, *prouted, *pshared, *pts;
    int *pti;
    __half *pxh, *pxl, *path, *patl, *px2h, *px2l, *pach, *pacl, *psah, *psal;
    __half *pqh, *pql, *pkh, *pvh, *pph, *ppl;
    GSYM(pqkv, g_qkv); GSYM(psc, g_scores); GSYM(phf, g_h); GSYM(px2f, g_x2f);
    GSYM(pgu, g_gu); GSYM(psgu, g_sgu); GSYM(prouted, g_routed); GSYM(pshared, g_shared);
    GSYM(pti, g_topidx); GSYM(pts, g_topscore);
    GSYM(pxh, x_h); GSYM(pxl, x_l); GSYM(path, at_h); GSYM(patl, at_l);
    GSYM(px2h, x2_h); GSYM(px2l, x2_l); GSYM(pach, ac_h); GSYM(pacl, ac_l);
    GSYM(psah, sa_h); GSYM(psal, sa_l);
    GSYM(pqh, q_h); GSYM(pql, q_l); GSYM(pkh, k_h);
    GSYM(pvh, v_h); GSYM(pph, p_h); GSYM(ppl, p_l);

    cudaFuncSetAttribute(tgemm_kernel, cudaFuncAttributeMaxDynamicSharedMemorySize, TG_SMEM);
    cudaFuncSetAttribute(scores_mma_kernel, cudaFuncAttributeMaxDynamicSharedMemorySize, SC_SMEM);
    cudaFuncSetAttribute(pv_mma_kernel, cudaFuncAttributeMaxDynamicSharedMemorySize, PV_SMEM);

    // --- attention block ---
    rmsnorm_kernel<<<Sm, 256>>>(hidden, attn_nw, nullptr, pxh, pxl);
    tgemm_kernel<<<dim3(24, 8), 256, TG_SMEM>>>(pxh, pxl, wq, wk, wv,
                                                2048, 512, 512, 2048, 2560,
                                                pqkv, 3072, nullptr, nullptr, 0,
                                                nullptr, nullptr, nullptr, nullptr, nullptr);
    rope_planes_kernel<<<Sm, 256>>>(pqkv, pos, pqh, pql, pkh, pvh);
    scores_mma_kernel<<<dim3(4, 8, Hn), 256, SC_SMEM>>>(pqh, pql, pkh, psc);
    softmax_kernel<<<dim3(Sm, Hn), 256>>>(psc, amask, pph, ppl);
    pv_mma_kernel<<<dim3(8, Hn), 256, PV_SMEM>>>(pph, ppl, pvh, path, patl);
    tgemm_kernel<<<dim3(16, 8), 256, TG_SMEM>>>(path, patl, wo, nullptr, nullptr,
                                                2048, 0, 0, NSBIG, NSBIG,
                                                phf, 2048, hidden, nullptr, 0,
                                                nullptr, nullptr, nullptr, nullptr, nullptr);

    // --- MoE block ---
    rmsnorm_kernel<<<Sm, 256>>>(phf, ffn_nw, px2f, px2h, px2l);
    router_kernel<<<Sm, 256>>>(px2f, router_w, pti, pts);
    dispatch_kernel<<<1, Sm>>>(pti);
    tgemm_kernel<<<dim3(32, 8, En + 1), 256, TG_SMEM>>>(px2h, px2l, w_gate, w_up, nullptr,
                                                        2048, 2048, 0, 2048, NSBIG,
                                                        pgu, 4096, nullptr, pts, 1,
                                                        px2h, px2l, ws_gate, ws_up, psgu);
    silumul2_kernel<<<(2 * Sm * Dm) / 256, 256>>>(pgu, psgu, pach, pacl, psah, psal);
    tgemm_kernel<<<dim3(16, 8, En + 1), 256, TG_SMEM>>>(pach, pacl, w_down, nullptr, nullptr,
                                                        2048, 0, 0, NSBIG, NSBIG,
                                                        prouted, 2048, nullptr, nullptr, 1,
                                                        psah, psal, ws_down, nullptr, pshared);

    // final: out = h + routed + shared
    add3_kernel<<<(Sm * Dm) / 256, 256>>>(phf, prouted, pshared, out);
}

// round 15
// speedup vs baseline: 1.8039x; 1.1808x over previous
#include <cuda_runtime.h>
#include <cuda_fp16.h>
#include <stdint.h>
#include <math.h>

#define Dm   2048
#define Sm   512
#define Hn   16
#define HKVn 4
#define DHn  128
#define Fn   2048
#define En   8
#define QKVP 3072

// ---------------- scratch (device globals) ----------------
__device__ float g_qkv[Sm*QKVP];
__device__ float g_scores[Hn*Sm*Sm];
__device__ float g_h[Sm*Dm];
__device__ float g_x2f[Sm*Dm];
__device__ float g_gu[Sm*4096];
__device__ float g_sgu[Sm*4096];
__device__ float g_routed[Sm*Dm];
__device__ float g_shared[Sm*Dm];
__device__ int   g_topidx[Sm];
__device__ float g_topscore[Sm];
__device__ int   g_cnt[En];
__device__ int   g_list[En*Sm];

// activation fp16 planes (single hi plane everywhere)
__device__ __half x_h[Sm*Dm];
__device__ __half at_h[Sm*Dm];
__device__ __half x2_h[Sm*Dm];
__device__ __half ac_h[Sm*Dm];
__device__ __half sa_h[Sm*Dm];
__device__ __half q_h[Sm*Dm];
__device__ __half k_h[Sm*512];
__device__ __half v_h[Sm*512];
__device__ __half p_h[Hn*Sm*Sm];

// ---------------- helpers ----------------
__device__ __forceinline__ uint32_t smem_u32(const void* p) {
    uint32_t a;
    asm("{ .reg .u64 t; cvta.to.shared.u64 t, %1; cvt.u32.u64 %0, t; }" : "=r"(a) : "l"(p));
    return a;
}
// a -> low element, b -> high element
__device__ __forceinline__ uint32_t pack_f16x2(float a, float b) {
    __half2 h = __floats2half2_rn(a, b);
    return *(uint32_t*)&h;
}
__device__ __forceinline__ void mma16816(float c[4], const uint32_t a[4], const uint32_t b[2]) {
    asm volatile(
        "mma.sync.aligned.m16n8k16.row.col.f32.f16.f16.f32 "
        "{%0,%1,%2,%3}, {%4,%5,%6,%7}, {%8,%9}, {%0,%1,%2,%3};"
        : "+f"(c[0]), "+f"(c[1]), "+f"(c[2]), "+f"(c[3])
        : "r"(a[0]), "r"(a[1]), "r"(a[2]), "r"(a[3]), "r"(b[0]), "r"(b[1]));
}
__device__ __forceinline__ void cpa16(uint32_t d, const void* s) {
    asm volatile("cp.async.cg.shared.global [%0], [%1], 16;" :: "r"(d), "l"(s));
}
#define CPA_COMMIT() asm volatile("cp.async.commit_group;" ::: "memory")
#define CPA_WAIT1()  asm volatile("cp.async.wait_group 1;" ::: "memory")
#define CPA_WAIT0()  asm volatile("cp.async.wait_group 0;" ::: "memory")
__device__ __forceinline__ void ldm_x4(uint32_t r[4], uint32_t a) {
    asm volatile("ldmatrix.sync.aligned.m8n8.x4.shared.b16 {%0,%1,%2,%3}, [%4];"
        : "=r"(r[0]), "=r"(r[1]), "=r"(r[2]), "=r"(r[3]) : "r"(a));
}
__device__ __forceinline__ void ldm_x4t(uint32_t r[4], uint32_t a) {
    asm volatile("ldmatrix.sync.aligned.m8n8.x4.trans.shared.b16 {%0,%1,%2,%3}, [%4];"
        : "=r"(r[0]), "=r"(r[1]), "=r"(r[2]), "=r"(r[3]) : "r"(a));
}

// =============== fp16 1-pass HMMA GEMM, 64x128 tile, K=2048 ===============
// B: LDG fp32 -> regs (1-stage prefetch) -> convert -> STS fp16 (double buf)
// A: cp.async fp16 plane (triple buf). ONE barrier per 32-k stage.
#define KST 32
#define A_PITCH 40
#define A_PLANE_B (64*A_PITCH*2)      // 5120
#define BB_PITCH 136
#define BB_PLANE_B (KST*BB_PITCH*2)   // 8704
#define OFF_BB (3*A_PLANE_B)          // 15360
#define TG_SMEM (OFF_BB + 2*BB_PLANE_B)  // 32768

__global__ void __launch_bounds__(256, 2) tgemm_kernel(
    const __half* __restrict__ aH,
    const float* __restrict__ B0, const float* __restrict__ B1, const float* __restrict__ B2,
    int ldb0, int ldb1, int ldb2, int ns1, int ns2,
    float* __restrict__ C, int ldc,
    const float* __restrict__ res, const float* __restrict__ rowscale, int mode,
    const __half* __restrict__ sAh,
    const float* __restrict__ sB0, const float* __restrict__ sB1,
    float* __restrict__ sC)
{
    extern __shared__ char smc[];
    __shared__ int   tok[64];
    __shared__ float scl[64];
    int row0 = blockIdx.y * 64;
    int n0   = blockIdx.x * 128;
    int tid  = threadIdx.x;

    int gather = mode;
    if (mode == 1 && blockIdx.z == En) {
        aH = sAh; B0 = sB0; B1 = sB1; C = sC;
        rowscale = nullptr;
        gather = 0;
    }

    const float* Bsel; int ldbs; int ncol;
    if (n0 < ns1)      { Bsel = B0; ldbs = ldb0; ncol = n0; }
    else if (n0 < ns2) { Bsel = B1; ldbs = ldb1; ncol = n0 - ns1; }
    else               { Bsel = B2; ldbs = ldb2; ncol = n0 - ns2; }

    if (gather) {
        int e = blockIdx.z;
        int count = g_cnt[e];
        if (row0 >= count) return;
        Bsel += (size_t)e * 2048 * ldbs;
        if (tid < 64) {
            int r = row0 + tid;
            int t = (r < count) ? g_list[e * Sm + r] : -1;
            tok[tid] = t;
            scl[tid] = (t >= 0 && rowscale) ? rowscale[t] : 1.0f;
        }
    } else {
        if (tid < 64) { tok[tid] = row0 + tid; scl[tid] = 1.0f; }
    }
    __syncthreads();

    uint32_t smbase = smem_u32(smc);
    int lane = tid & 31, wid = tid >> 5;
    int gr = lane >> 2, tg = lane & 3;
    int wm = wid >> 2, wn = wid & 3;

    float acc[2][4][4];
#pragma unroll
    for (int i = 0; i < 2; i++)
#pragma unroll
        for (int j = 0; j < 4; j++)
#pragma unroll
            for (int r = 0; r < 4; r++) acc[i][j][r] = 0.f;

    int arow = tid >> 2, ach = tid & 3;
    int at = tok[arow];
    int agrow = at < 0 ? 0 : at;

    int bk[4], bc[4];
#pragma unroll
    for (int it = 0; it < 4; it++) {
        int chunk = it * 256 + tid;
        bk[it] = chunk >> 5;
        bc[it] = (chunk & 31) * 4;
    }

    auto copy_A = [&](int st) {
        uint32_t ab = smbase + (uint32_t)(st % 3) * A_PLANE_B;
        int k0 = st * KST;
        cpa16(ab + (uint32_t)(arow * A_PITCH + ach * 8) * 2,
              aH + (size_t)agrow * 2048 + k0 + ach * 8);
        CPA_COMMIT();
    };

    float4 va[4];
    auto ldg_B = [&](int st) {
        int k0 = st * KST;
#pragma unroll
        for (int it = 0; it < 4; it++)
            va[it] = *(const float4*)(Bsel + (size_t)(k0 + bk[it]) * ldbs + ncol + bc[it]);
    };

    ldg_B(0);
    copy_A(0);

    int lr = lane & 15;
    int lc8 = (lane & 16) >> 1;

    for (int st = 0; st < 64; st++) {
        // convert B(st) from regs -> BB[st&1]
        {
            __half* bh = (__half*)(smc + OFF_BB + (st & 1) * BB_PLANE_B);
#pragma unroll
            for (int it = 0; it < 4; it++) {
                float4 v = va[it];
                uint32_t h01 = pack_f16x2(v.x, v.y);
                uint32_t h23 = pack_f16x2(v.z, v.w);
                int o = bk[it] * BB_PITCH + bc[it];
                *(uint2*)(bh + o) = make_uint2(h01, h23);
            }
        }
        if (st < 63) {
            ldg_B(st + 1);
            copy_A(st + 1);
            CPA_WAIT1();
        } else {
            CPA_WAIT0();
        }
        __syncthreads();

        // ---- MMA: 2 k16 steps, 1 pass ----
        uint32_t AHb = smbase + (uint32_t)(st % 3) * A_PLANE_B;
        uint32_t BHb = smbase + OFF_BB + (uint32_t)(st & 1) * BB_PLANE_B;
#pragma unroll
        for (int ks = 0; ks < 2; ks++) {
            uint32_t fAH[2][4], fBH[4][2];
#pragma unroll
            for (int mt = 0; mt < 2; mt++) {
                uint32_t ao = (uint32_t)((wm * 32 + mt * 16 + lr) * A_PITCH + ks * 16 + lc8) * 2;
                ldm_x4(fAH[mt], AHb + ao);
            }
#pragma unroll
            for (int half = 0; half < 2; half++) {
                int brow = ks * 16 + lr;
                int bcol = wn * 32 + half * 16 + lc8;
                uint32_t bo = (uint32_t)(brow * BB_PITCH + bcol) * 2;
                uint32_t rH[4];
                ldm_x4t(rH, BHb + bo);
                fBH[half*2][0] = rH[0]; fBH[half*2][1] = rH[1];
                fBH[half*2+1][0] = rH[2]; fBH[half*2+1][1] = rH[3];
            }
#pragma unroll
            for (int mt = 0; mt < 2; mt++)
#pragma unroll
                for (int nt = 0; nt < 4; nt++)
                    mma16816(acc[mt][nt], fAH[mt], fBH[nt]);
        }
    }

    // ---- epilogue ----
#pragma unroll
    for (int mt = 0; mt < 2; mt++) {
        int r1 = wm * 32 + mt * 16 + gr;
        int r2 = r1 + 8;
        int t1 = tok[r1], t2 = tok[r2];
        float s1 = scl[r1], s2 = scl[r2];
#pragma unroll
        for (int nt = 0; nt < 4; nt++) {
            int col = n0 + wn * 32 + nt * 8 + tg * 2;
            if (t1 >= 0) {
                float2 o = make_float2(acc[mt][nt][0] * s1, acc[mt][nt][1] * s1);
                if (res) {
                    float2 rv = *(const float2*)(res + (size_t)t1 * ldc + col);
                    o.x += rv.x; o.y += rv.y;
                }
                *(float2*)(C + (size_t)t1 * ldc + col) = o;
            }
            if (t2 >= 0) {
                float2 o = make_float2(acc[mt][nt][2] * s2, acc[mt][nt][3] * s2);
                if (res) {
                    float2 rv = *(const float2*)(res + (size_t)t2 * ldc + col);
                    o.x += rv.x; o.y += rv.y;
                }
                *(float2*)(C + (size_t)t2 * ldc + col) = o;
            }
        }
    }
}

// =============== attention scores via HMMA (causal-skip, fp16 1-pass) ===============
// smem elems: QH[64][136]@0, KH[128][136]@8704 ; total 26112 elems
#define SC_SMEM (26112*2)

__global__ void __launch_bounds__(256, 2) scores_mma_kernel(
    const __half* __restrict__ qh, const __half* __restrict__ kh,
    float* __restrict__ sc)
{
    extern __shared__ __half smb[];
    int h = blockIdx.z;
    int row0 = blockIdx.y * 64;
    int n0 = blockIdx.x * 128;
    if (n0 >= row0 + 64) return;
    int tid = threadIdx.x, lane = tid & 31, wid = tid >> 5;
    int gr = lane >> 2, tg = lane & 3;
    int wm = wid >> 2, wn = wid & 3;
    uint32_t base = smem_u32(smb);

    {
#pragma unroll
        for (int it = 0; it < 4; it++) {
            int idx = it * 256 + tid;
            int r = idx >> 4, ch = idx & 15;
            cpa16(base + (uint32_t)(r * 136 + ch * 8) * 2,
                  qh + (size_t)(row0 + r) * 2048 + h * 128 + ch * 8);
        }
    }
    {
        uint32_t d0 = base + 8704u * 2;
#pragma unroll
        for (int it = 0; it < 8; it++) {
            int idx = it * 256 + tid;
            int r = idx >> 4, ch = idx & 15;
            cpa16(d0 + (uint32_t)(r * 136 + ch * 8) * 2,
                  kh + (size_t)(n0 + r) * 512 + (h >> 2) * 128 + ch * 8);
        }
    }
    CPA_COMMIT(); CPA_WAIT0();
    __syncthreads();

    float acc[2][4][4];
#pragma unroll
    for (int i = 0; i < 2; i++)
#pragma unroll
        for (int j = 0; j < 4; j++)
#pragma unroll
            for (int r = 0; r < 4; r++) acc[i][j][r] = 0.f;

    int lr = lane & 15, lc8 = (lane & 16) >> 1;
    uint32_t QHb = base;
    uint32_t KHb = base + 17408;

#pragma unroll
    for (int ks = 0; ks < 8; ks++) {
        uint32_t fAH[2][4], fBH[4][2];
#pragma unroll
        for (int mt = 0; mt < 2; mt++) {
            uint32_t ao = (uint32_t)((wm * 32 + mt * 16 + lr) * 136 + ks * 16 + lc8) * 2;
            ldm_x4(fAH[mt], QHb + ao);
        }
#pragma unroll
        for (int half = 0; half < 2; half++) {
            uint32_t bo = (uint32_t)((wn * 32 + half * 16 + lr) * 136 + ks * 16 + lc8) * 2;
            uint32_t rH[4];
            ldm_x4(rH, KHb + bo);
            fBH[half*2][0] = rH[0]; fBH[half*2][1] = rH[2];
            fBH[half*2+1][0] = rH[1]; fBH[half*2+1][1] = rH[3];
        }
#pragma unroll
        for (int mt = 0; mt < 2; mt++)
#pragma unroll
            for (int nt = 0; nt < 4; nt++)
                mma16816(acc[mt][nt], fAH[mt], fBH[nt]);
    }

    const float scale = 0.0883883476483184405f;
    float* out = sc + (size_t)h * Sm * Sm;
#pragma unroll
    for (int mt = 0; mt < 2; mt++) {
        int r1 = row0 + wm * 32 + mt * 16 + gr;
        int r2 = r1 + 8;
#pragma unroll
        for (int nt = 0; nt < 4; nt++) {
            int col = n0 + wn * 32 + nt * 8 + tg * 2;
            *(float2*)(out + (size_t)r1 * Sm + col) =
                make_float2(acc[mt][nt][0] * scale, acc[mt][nt][1] * scale);
            *(float2*)(out + (size_t)r2 * Sm + col) =
                make_float2(acc[mt][nt][2] * scale, acc[mt][nt][3] * scale);
        }
    }
}

// =============== PV via HMMA (causal-truncated, fp16 1-pass) ===============
// stage elems: PH[64][72]@0, VH[64][136]@4608 ; 13312 elems = 26624 B
#define PV_STAGE_B (13312*2)
#define PV_SMEM (2*PV_STAGE_B)

__global__ void __launch_bounds__(256, 2) pv_mma_kernel(
    const __half* __restrict__ ph_, const __half* __restrict__ vh,
    __half* __restrict__ outh)
{
    extern __shared__ __half smb[];
    int h = blockIdx.y;
    int row0 = blockIdx.x * 64;
    int nst = blockIdx.x + 1;
    int kvoff = (h >> 2) * 128;
    int tid = threadIdx.x, lane = tid & 31, wid = tid >> 5;
    int gr = lane >> 2, tg = lane & 3;
    int wm = wid >> 2, wn = wid & 3;
    uint32_t smbase = smem_u32(smb);

    float acc[2][4][4];
#pragma unroll
    for (int i = 0; i < 2; i++)
#pragma unroll
        for (int j = 0; j < 4; j++)
#pragma unroll
            for (int r = 0; r < 4; r++) acc[i][j][r] = 0.f;

    auto copy_stage = [&](int st) {
        uint32_t base = smbase + (uint32_t)(st & 1) * PV_STAGE_B;
        int k0 = st * 64;
#pragma unroll
        for (int it = 0; it < 2; it++) {
            int idx = it * 256 + tid;
            int row = idx >> 3, ch = idx & 7;
            cpa16(base + (uint32_t)(row * 72 + ch * 8) * 2,
                  ph_ + ((size_t)h * Sm + row0 + row) * Sm + k0 + ch * 8);
        }
        {
            uint32_t d0 = base + 4608 * 2;
#pragma unroll
            for (int it = 0; it < 4; it++) {
                int idx = it * 256 + tid;
                int row = idx >> 4, ch = idx & 15;
                cpa16(d0 + (uint32_t)(row * 136 + ch * 8) * 2,
                      vh + (size_t)(k0 + row) * 512 + kvoff + ch * 8);
            }
        }
        CPA_COMMIT();
    };

    copy_stage(0);
    int lr = lane & 15, lc8 = (lane & 16) >> 1;

    for (int st = 0; st < nst; st++) {
        if (st + 1 < nst) { copy_stage(st + 1); CPA_WAIT1(); }
        else              { CPA_WAIT0(); }
        __syncthreads();
        uint32_t base = smbase + (uint32_t)(st & 1) * PV_STAGE_B;
        uint32_t AHb = base;
        uint32_t BHb = base + 9216;
#pragma unroll
        for (int ks = 0; ks < 4; ks++) {
            uint32_t fAH[2][4], fBH[4][2];
#pragma unroll
            for (int mt = 0; mt < 2; mt++) {
                uint32_t ao = (uint32_t)((wm * 32 + mt * 16 + lr) * 72 + ks * 16 + lc8) * 2;
                ldm_x4(fAH[mt], AHb + ao);
            }
#pragma unroll
            for (int half = 0; half < 2; half++) {
                uint32_t bo = (uint32_t)((ks * 16 + lr) * 136 + wn * 32 + half * 16 + lc8) * 2;
                uint32_t rH[4];
                ldm_x4t(rH, BHb + bo);
                fBH[half*2][0] = rH[0]; fBH[half*2][1] = rH[1];
                fBH[half*2+1][0] = rH[2]; fBH[half*2+1][1] = rH[3];
            }
#pragma unroll
            for (int mt = 0; mt < 2; mt++)
#pragma unroll
                for (int nt = 0; nt < 4; nt++)
                    mma16816(acc[mt][nt], fAH[mt], fBH[nt]);
        }
        __syncthreads();
    }

#pragma unroll
    for (int mt = 0; mt < 2; mt++) {
        int r1 = row0 + wm * 32 + mt * 16 + gr;
        int r2 = r1 + 8;
#pragma unroll
        for (int nt = 0; nt < 4; nt++) {
            int col = h * 128 + wn * 32 + nt * 8 + tg * 2;
            __half2 hh1 = __floats2half2_rn(acc[mt][nt][0], acc[mt][nt][1]);
            __half2 hh2 = __floats2half2_rn(acc[mt][nt][2], acc[mt][nt][3]);
            *(__half2*)(outh + (size_t)r1 * 2048 + col) = hh1;
            *(__half2*)(outh + (size_t)r2 * 2048 + col) = hh2;
        }
    }
}

// ---------------- small kernels ----------------
__global__ void rmsnorm_kernel(const float* __restrict__ in, const float* __restrict__ w,
                               float* __restrict__ outf, __half* __restrict__ outh) {
    int t = blockIdx.x;
    const float* row = in + (size_t)t * Dm;
    float s = 0.f;
    for (int d = threadIdx.x; d < Dm; d += 256) { float v = row[d]; s += v * v; }
    __shared__ float red[256];
    red[threadIdx.x] = s; __syncthreads();
    for (int off = 128; off > 0; off >>= 1) {
        if (threadIdx.x < off) red[threadIdx.x] += red[threadIdx.x + off];
        __syncthreads();
    }
    float r = rsqrtf(red[0] / (float)Dm + 1e-5f);
    for (int d = threadIdx.x; d < Dm; d += 256) {
        float v = row[d] * r * w[d];
        if (outf) outf[(size_t)t * Dm + d] = v;
        outh[(size_t)t * Dm + d] = __float2half_rn(v);
    }
}

// log2(500000)/64
#define ROPE_C 0.29580575889569022f

__global__ void rope_planes_kernel(const float* __restrict__ qkv, const int* __restrict__ pos_ids,
                                   __half* qh, __half* kh, __half* vh) {
    int t = blockIdx.x;
    float p = (float)pos_ids[t];
    for (int idx = threadIdx.x; idx < (Hn + HKVn) * 64; idx += blockDim.x) {
        int head = idx >> 6;
        int i = idx & 63;
        float inv = exp2f(-(float)i * ROPE_C);
        float f = p * inv;
        float sn, cs;
        sincosf(f, &sn, &cs);
        if (head < Hn) {
            const float* src = qkv + (size_t)t * QKVP + head * DHn;
            float x1 = src[i], x2 = src[i + 64];
            size_t d = (size_t)t * Dm + head * DHn + i;
            qh[d]      = __float2half_rn(x1 * cs - x2 * sn);
            qh[d + 64] = __float2half_rn(x2 * cs + x1 * sn);
        } else {
            int kvh = head - Hn;
            const float* src = qkv + (size_t)t * QKVP + 2048 + kvh * DHn;
            float x1 = src[i], x2 = src[i + 64];
            size_t d = (size_t)t * 512 + kvh * DHn + i;
            kh[d]      = __float2half_rn(x1 * cs - x2 * sn);
            kh[d + 64] = __float2half_rn(x2 * cs + x1 * sn);
        }
    }
    for (int idx = threadIdx.x; idx < 512; idx += blockDim.x) {
        vh[(size_t)t * 512 + idx] = __float2half_rn(qkv[(size_t)t * QKVP + 2560 + idx]);
    }
}

__global__ void softmax_kernel(const float* __restrict__ sc, const int* __restrict__ mask,
                               __half* __restrict__ ph) {
    int i = blockIdx.x;
    int h = blockIdx.y;
    int row_end = (i & ~63) + 64;
    const float* row = sc + ((size_t)h * Sm + i) * Sm;
    int tid = threadIdx.x;
    int j0 = tid, j1 = tid + 256;
    float s0 = (j0 <= i && mask[j0] > 0) ? row[j0] : -1e9f;
    float s1 = (j1 <= i && mask[j1] > 0) ? row[j1] : -1e9f;
    __shared__ float red[256];
    red[tid] = fmaxf(s0, s1); __syncthreads();
    for (int off = 128; off > 0; off >>= 1) {
        if (tid < off) red[tid] = fmaxf(red[tid], red[tid + off]);
        __syncthreads();
    }
    float m = red[0];
    __syncthreads();
    float e0 = expf(s0 - m), e1 = expf(s1 - m);
    red[tid] = e0 + e1; __syncthreads();
    for (int off = 128; off > 0; off >>= 1) {
        if (tid < off) red[tid] += red[tid + off];
        __syncthreads();
    }
    float inv = 1.f / red[0];
    size_t base = ((size_t)h * Sm + i) * Sm;
    if (j0 < row_end) ph[base + j0] = __float2half_rn(e0 * inv);
    if (j1 < row_end) ph[base + j1] = __float2half_rn(e1 * inv);
}

__global__ void router_kernel(const float* __restrict__ x2, const float* __restrict__ rw,
                              int* __restrict__ topidx, float* __restrict__ topscore) {
    int t = blockIdx.x;
    int w = threadIdx.x >> 5, lane = threadIdx.x & 31;
    float s = 0.f;
    for (int d = lane; d < Dm; d += 32)
        s += x2[(size_t)t * Dm + d] * rw[d * En + w];
    for (int off = 16; off; off >>= 1) s += __shfl_down_sync(0xffffffff, s, off);
    __shared__ float logits[En];
    if (lane == 0) logits[w] = s;
    __syncthreads();
    if (threadIdx.x == 0) {
        int best = 0; float bv = logits[0];
        for (int e = 1; e < En; e++) if (logits[e] > bv) { bv = logits[e]; best = e; }
        topidx[t] = best;
        topscore[t] = 1.f / (1.f + expf(-bv));
    }
}

__global__ void dispatch_kernel(const int* __restrict__ topidx) {
    int t = threadIdx.x;
    if (t < En) g_cnt[t] = 0;
    __syncthreads();
    int e = topidx[t];
    int pos = atomicAdd(&g_cnt[e], 1);
    g_list[e * Sm + pos] = t;
}

// combined silu-mul for expert gu and shared sgu
__global__ void silumul2_kernel(const float* __restrict__ gu, const float* __restrict__ sgu,
                                __half* __restrict__ ah, __half* __restrict__ sh) {
    int i = blockIdx.x * 256 + threadIdx.x;
    const float* src = gu;
    __half* oh = ah;
    int j = i;
    if (i >= Sm * Dm) {
        j = i - Sm * Dm;
        src = sgu; oh = sh;
    }
    int t = j >> 11, c = j & 2047;
    float g = src[(size_t)t * 4096 + c];
    float u = src[(size_t)t * 4096 + 2048 + c];
    float a = (g / (1.f + expf(-g))) * u;
    oh[j] = __float2half_rn(a);
}

__global__ void add3_kernel(const float* __restrict__ a, const float* __restrict__ b,
                            const float* __restrict__ c, float* __restrict__ out) {
    int i = blockIdx.x * 256 + threadIdx.x;
    out[i] = a[i] + b[i] + c[i];
}

// ---------------- launch ----------------
#define GSYM(p, s) cudaGetSymbolAddress((void**)&p, s)
#define NSBIG 0x40000000

extern "C" void kernel_launch(void* const* d_in, const int* in_sizes, int n_in,
                              void* d_out, int out_size) {
    const float* hidden   = (const float*)d_in[0];
    const int*   amask    = (const int*)  d_in[1];
    const int*   pos      = (const int*)  d_in[2];
    const float* attn_nw  = (const float*)d_in[3];
    const float* wq       = (const float*)d_in[4];
    const float* wk       = (const float*)d_in[5];
    const float* wv       = (const float*)d_in[6];
    const float* wo       = (const float*)d_in[7];
    const float* ffn_nw   = (const float*)d_in[8];
    const float* router_w = (const float*)d_in[9];
    const float* w_gate   = (const float*)d_in[10];
    const float* w_up     = (const float*)d_in[11];
    const float* w_down   = (const float*)d_in[12];
    const float* ws_gate  = (const float*)d_in[13];
    const float* ws_up    = (const float*)d_in[14];
    const float* ws_down  = (const float*)d_in[15];
    float* out = (float*)d_out;

    float *pqkv, *psc, *phf, *px2f, *pgu, *psgu, *prouted, *pshared, *pts;
    int *pti;
    __half *pxh, *path, *px2h, *pach, *psah, *pqh, *pkh, *pvh, *pph;
    GSYM(pqkv, g_qkv); GSYM(psc, g_scores); GSYM(phf, g_h); GSYM(px2f, g_x2f);
    GSYM(pgu, g_gu); GSYM(psgu, g_sgu); GSYM(prouted, g_routed); GSYM(pshared, g_shared);
    GSYM(pti, g_topidx); GSYM(pts, g_topscore);
    GSYM(pxh, x_h); GSYM(path, at_h); GSYM(px2h, x2_h); GSYM(pach, ac_h); GSYM(psah, sa_h);
    GSYM(pqh, q_h); GSYM(pkh, k_h); GSYM(pvh, v_h); GSYM(pph, p_h);

    cudaFuncSetAttribute(tgemm_kernel, cudaFuncAttributeMaxDynamicSharedMemorySize, TG_SMEM);
    cudaFuncSetAttribute(scores_mma_kernel, cudaFuncAttributeMaxDynamicSharedMemorySize, SC_SMEM);
    cudaFuncSetAttribute(pv_mma_kernel, cudaFuncAttributeMaxDynamicSharedMemorySize, PV_SMEM);

    // --- attention block ---
    rmsnorm_kernel<<<Sm, 256>>>(hidden, attn_nw, nullptr, pxh);
    tgemm_kernel<<<dim3(24, 8), 256, TG_SMEM>>>(pxh, wq, wk, wv,
                                                2048, 512, 512, 2048, 2560,
                                                pqkv, 3072, nullptr, nullptr, 0,
                                                nullptr, nullptr, nullptr, nullptr);
    rope_planes_kernel<<<Sm, 256>>>(pqkv, pos, pqh, pkh, pvh);
    scores_mma_kernel<<<dim3(4, 8, Hn), 256, SC_SMEM>>>(pqh, pkh, psc);
    softmax_kernel<<<dim3(Sm, Hn), 256>>>(psc, amask, pph);
    pv_mma_kernel<<<dim3(8, Hn), 256, PV_SMEM>>>(pph, pvh, path);
    tgemm_kernel<<<dim3(16, 8), 256, TG_SMEM>>>(path, wo, nullptr, nullptr,
                                                2048, 0, 0, NSBIG, NSBIG,
                                                phf, 2048, hidden, nullptr, 0,
                                                nullptr, nullptr, nullptr, nullptr);

    // --- MoE block ---
    rmsnorm_kernel<<<Sm, 256>>>(phf, ffn_nw, px2f, px2h);
    router_kernel<<<Sm, 256>>>(px2f, router_w, pti, pts);
    dispatch_kernel<<<1, Sm>>>(pti);
    tgemm_kernel<<<dim3(32, 8, En + 1), 256, TG_SMEM>>>(px2h, w_gate, w_up, nullptr,
                                                        2048, 2048, 0, 2048, NSBIG,
                                                        pgu, 4096, nullptr, pts, 1,
                                                        px2h, ws_gate, ws_up, psgu);
    silumul2_kernel<<<(2 * Sm * Dm) / 256, 256>>>(pgu, psgu, pach, psah);
    tgemm_kernel<<<dim3(16, 8, En + 1), 256, TG_SMEM>>>(pach, w_down, nullptr, nullptr,
                                                        2048, 0, 0, NSBIG, NSBIG,
                                                        prouted, 2048, nullptr, nullptr, 1,
                                                        psah, ws_down, nullptr, pshared);

    // final: out = h + routed + shared
    add3_kernel<<<(Sm * Dm) / 256, 256>>>(phf, prouted, pshared, out);
}

// round 16
// speedup vs baseline: 2.0392x; 1.1305x over previous
#include <cuda_runtime.h>
#include <cuda_fp16.h>
#include <stdint.h>
#include <math.h>

#define Dm   2048
#define Sm   512
#define Hn   16
#define HKVn 4
#define DHn  128
#define Fn   2048
#define En   8
#define QKVP 3072

// ---------------- scratch (device globals) ----------------
__device__ float g_qkv[Sm*QKVP];
__device__ float g_scores[Hn*Sm*Sm];
__device__ float g_h[Sm*Dm];
__device__ float g_x2f[Sm*Dm];
__device__ float g_gu[Sm*4096];
__device__ float g_sgu[Sm*4096];
__device__ float g_routed[Sm*Dm];
__device__ float g_shared[Sm*Dm];
__device__ int   g_topidx[Sm];
__device__ float g_topscore[Sm];
__device__ int   g_cnt[En];
__device__ int   g_list[En*Sm];

// activation fp16 planes (single hi plane everywhere)
__device__ __half x_h[Sm*Dm];
__device__ __half at_h[Sm*Dm];
__device__ __half x2_h[Sm*Dm];
__device__ __half ac_h[Sm*Dm];
__device__ __half sa_h[Sm*Dm];
__device__ __half q_h[Sm*Dm];
__device__ __half k_h[Sm*512];
__device__ __half v_h[Sm*512];
__device__ __half p_h[Hn*Sm*Sm];

// ---------------- helpers ----------------
__device__ __forceinline__ uint32_t smem_u32(const void* p) {
    uint32_t a;
    asm("{ .reg .u64 t; cvta.to.shared.u64 t, %1; cvt.u32.u64 %0, t; }" : "=r"(a) : "l"(p));
    return a;
}
// a -> low element, b -> high element
__device__ __forceinline__ uint32_t pack_f16x2(float a, float b) {
    __half2 h = __floats2half2_rn(a, b);
    return *(uint32_t*)&h;
}
__device__ __forceinline__ void mma16816(float c[4], const uint32_t a[4], const uint32_t b[2]) {
    asm volatile(
        "mma.sync.aligned.m16n8k16.row.col.f32.f16.f16.f32 "
        "{%0,%1,%2,%3}, {%4,%5,%6,%7}, {%8,%9}, {%0,%1,%2,%3};"
        : "+f"(c[0]), "+f"(c[1]), "+f"(c[2]), "+f"(c[3])
        : "r"(a[0]), "r"(a[1]), "r"(a[2]), "r"(a[3]), "r"(b[0]), "r"(b[1]));
}
__device__ __forceinline__ void cpa16(uint32_t d, const void* s) {
    asm volatile("cp.async.cg.shared.global [%0], [%1], 16;" :: "r"(d), "l"(s));
}
#define CPA_COMMIT() asm volatile("cp.async.commit_group;" ::: "memory")
#define CPA_WAIT1()  asm volatile("cp.async.wait_group 1;" ::: "memory")
#define CPA_WAIT0()  asm volatile("cp.async.wait_group 0;" ::: "memory")
__device__ __forceinline__ void ldm_x4(uint32_t r[4], uint32_t a) {
    asm volatile("ldmatrix.sync.aligned.m8n8.x4.shared.b16 {%0,%1,%2,%3}, [%4];"
        : "=r"(r[0]), "=r"(r[1]), "=r"(r[2]), "=r"(r[3]) : "r"(a));
}
__device__ __forceinline__ void ldm_x4t(uint32_t r[4], uint32_t a) {
    asm volatile("ldmatrix.sync.aligned.m8n8.x4.trans.shared.b16 {%0,%1,%2,%3}, [%4];"
        : "=r"(r[0]), "=r"(r[1]), "=r"(r[2]), "=r"(r[3]) : "r"(a));
}

// =============== fp16 1-pass HMMA GEMM, 64x128 tile, K=2048, KST=64 ===============
// B: LDG fp32 -> regs (1-stage prefetch) -> convert -> STS fp16 (double buf)
// A: cp.async fp16 plane (triple buf). ONE barrier per 64-k stage (32 stages).
#define KST 64
#define A_PITCH 72
#define A_PLANE_B (64*A_PITCH*2)      // 9216
#define BB_PITCH 136
#define BB_PLANE_B (KST*BB_PITCH*2)   // 17408
#define OFF_BB (3*A_PLANE_B)          // 27648
#define TG_SMEM (OFF_BB + 2*BB_PLANE_B)  // 62464

__global__ void __launch_bounds__(256, 2) tgemm_kernel(
    const __half* __restrict__ aH,
    const float* __restrict__ B0, const float* __restrict__ B1, const float* __restrict__ B2,
    int ldb0, int ldb1, int ldb2, int ns1, int ns2,
    float* __restrict__ C, int ldc,
    const float* __restrict__ res, const float* __restrict__ rowscale, int mode,
    const __half* __restrict__ sAh,
    const float* __restrict__ sB0, const float* __restrict__ sB1,
    float* __restrict__ sC)
{
    extern __shared__ char smc[];
    __shared__ int   tok[64];
    __shared__ float scl[64];
    int row0 = blockIdx.y * 64;
    int n0   = blockIdx.x * 128;
    int tid  = threadIdx.x;

    int gather = mode;
    if (mode == 1 && blockIdx.z == En) {
        aH = sAh; B0 = sB0; B1 = sB1; C = sC;
        rowscale = nullptr;
        gather = 0;
    }

    const float* Bsel; int ldbs; int ncol;
    if (n0 < ns1)      { Bsel = B0; ldbs = ldb0; ncol = n0; }
    else if (n0 < ns2) { Bsel = B1; ldbs = ldb1; ncol = n0 - ns1; }
    else               { Bsel = B2; ldbs = ldb2; ncol = n0 - ns2; }

    if (gather) {
        int e = blockIdx.z;
        int count = g_cnt[e];
        if (row0 >= count) return;
        Bsel += (size_t)e * 2048 * ldbs;
        if (tid < 64) {
            int r = row0 + tid;
            int t = (r < count) ? g_list[e * Sm + r] : -1;
            tok[tid] = t;
            scl[tid] = (t >= 0 && rowscale) ? rowscale[t] : 1.0f;
        }
    } else {
        if (tid < 64) { tok[tid] = row0 + tid; scl[tid] = 1.0f; }
    }
    __syncthreads();

    uint32_t smbase = smem_u32(smc);
    int lane = tid & 31, wid = tid >> 5;
    int gr = lane >> 2, tg = lane & 3;
    int wm = wid >> 2, wn = wid & 3;

    float acc[2][4][4];
#pragma unroll
    for (int i = 0; i < 2; i++)
#pragma unroll
        for (int j = 0; j < 4; j++)
#pragma unroll
            for (int r = 0; r < 4; r++) acc[i][j][r] = 0.f;

    int arow = tid >> 2, ach = tid & 3;
    int at = tok[arow];
    int agrow = at < 0 ? 0 : at;

    int bk[8], bc[8];
#pragma unroll
    for (int it = 0; it < 8; it++) {
        int chunk = it * 256 + tid;
        bk[it] = chunk >> 5;
        bc[it] = (chunk & 31) * 4;
    }

    auto copy_A = [&](int st) {
        uint32_t ab = smbase + (uint32_t)(st % 3) * A_PLANE_B;
        int k0 = st * KST;
        cpa16(ab + (uint32_t)(arow * A_PITCH + ach * 16) * 2,
              aH + (size_t)agrow * 2048 + k0 + ach * 16);
        cpa16(ab + (uint32_t)(arow * A_PITCH + ach * 16 + 8) * 2,
              aH + (size_t)agrow * 2048 + k0 + ach * 16 + 8);
        CPA_COMMIT();
    };

    float4 va[8];
    auto ldg_B = [&](int st) {
        int k0 = st * KST;
#pragma unroll
        for (int it = 0; it < 8; it++)
            va[it] = *(const float4*)(Bsel + (size_t)(k0 + bk[it]) * ldbs + ncol + bc[it]);
    };

    ldg_B(0);
    copy_A(0);

    int lr = lane & 15;
    int lc8 = (lane & 16) >> 1;

    for (int st = 0; st < 32; st++) {
        // convert B(st) from regs -> BB[st&1]
        {
            __half* bh = (__half*)(smc + OFF_BB + (st & 1) * BB_PLANE_B);
#pragma unroll
            for (int it = 0; it < 8; it++) {
                float4 v = va[it];
                uint32_t h01 = pack_f16x2(v.x, v.y);
                uint32_t h23 = pack_f16x2(v.z, v.w);
                int o = bk[it] * BB_PITCH + bc[it];
                *(uint2*)(bh + o) = make_uint2(h01, h23);
            }
        }
        if (st < 31) {
            ldg_B(st + 1);
            copy_A(st + 1);
            CPA_WAIT1();
        } else {
            CPA_WAIT0();
        }
        __syncthreads();

        // ---- MMA: 4 k16 steps, 1 pass ----
        uint32_t AHb = smbase + (uint32_t)(st % 3) * A_PLANE_B;
        uint32_t BHb = smbase + OFF_BB + (uint32_t)(st & 1) * BB_PLANE_B;
#pragma unroll
        for (int ks = 0; ks < 4; ks++) {
            uint32_t fAH[2][4], fBH[4][2];
#pragma unroll
            for (int mt = 0; mt < 2; mt++) {
                uint32_t ao = (uint32_t)((wm * 32 + mt * 16 + lr) * A_PITCH + ks * 16 + lc8) * 2;
                ldm_x4(fAH[mt], AHb + ao);
            }
#pragma unroll
            for (int half = 0; half < 2; half++) {
                int brow = ks * 16 + lr;
                int bcol = wn * 32 + half * 16 + lc8;
                uint32_t bo = (uint32_t)(brow * BB_PITCH + bcol) * 2;
                uint32_t rH[4];
                ldm_x4t(rH, BHb + bo);
                fBH[half*2][0] = rH[0]; fBH[half*2][1] = rH[1];
                fBH[half*2+1][0] = rH[2]; fBH[half*2+1][1] = rH[3];
            }
#pragma unroll
            for (int mt = 0; mt < 2; mt++)
#pragma unroll
                for (int nt = 0; nt < 4; nt++)
                    mma16816(acc[mt][nt], fAH[mt], fBH[nt]);
        }
    }

    // ---- epilogue ----
#pragma unroll
    for (int mt = 0; mt < 2; mt++) {
        int r1 = wm * 32 + mt * 16 + gr;
        int r2 = r1 + 8;
        int t1 = tok[r1], t2 = tok[r2];
        float s1 = scl[r1], s2 = scl[r2];
#pragma unroll
        for (int nt = 0; nt < 4; nt++) {
            int col = n0 + wn * 32 + nt * 8 + tg * 2;
            if (t1 >= 0) {
                float2 o = make_float2(acc[mt][nt][0] * s1, acc[mt][nt][1] * s1);
                if (res) {
                    float2 rv = *(const float2*)(res + (size_t)t1 * ldc + col);
                    o.x += rv.x; o.y += rv.y;
                }
                *(float2*)(C + (size_t)t1 * ldc + col) = o;
            }
            if (t2 >= 0) {
                float2 o = make_float2(acc[mt][nt][2] * s2, acc[mt][nt][3] * s2);
                if (res) {
                    float2 rv = *(const float2*)(res + (size_t)t2 * ldc + col);
                    o.x += rv.x; o.y += rv.y;
                }
                *(float2*)(C + (size_t)t2 * ldc + col) = o;
            }
        }
    }
}

// =============== attention scores via HMMA (causal-skip, fp16 1-pass) ===============
// smem elems: QH[64][136]@0, KH[128][136]@8704 ; total 26112 elems
#define SC_SMEM (26112*2)

__global__ void __launch_bounds__(256, 2) scores_mma_kernel(
    const __half* __restrict__ qh, const __half* __restrict__ kh,
    float* __restrict__ sc)
{
    extern __shared__ __half smb[];
    int h = blockIdx.z;
    int row0 = blockIdx.y * 64;
    int n0 = blockIdx.x * 128;
    if (n0 >= row0 + 64) return;
    int tid = threadIdx.x, lane = tid & 31, wid = tid >> 5;
    int gr = lane >> 2, tg = lane & 3;
    int wm = wid >> 2, wn = wid & 3;
    uint32_t base = smem_u32(smb);

    {
#pragma unroll
        for (int it = 0; it < 4; it++) {
            int idx = it * 256 + tid;
            int r = idx >> 4, ch = idx & 15;
            cpa16(base + (uint32_t)(r * 136 + ch * 8) * 2,
                  qh + (size_t)(row0 + r) * 2048 + h * 128 + ch * 8);
        }
    }
    {
        uint32_t d0 = base + 8704u * 2;
#pragma unroll
        for (int it = 0; it < 8; it++) {
            int idx = it * 256 + tid;
            int r = idx >> 4, ch = idx & 15;
            cpa16(d0 + (uint32_t)(r * 136 + ch * 8) * 2,
                  kh + (size_t)(n0 + r) * 512 + (h >> 2) * 128 + ch * 8);
        }
    }
    CPA_COMMIT(); CPA_WAIT0();
    __syncthreads();

    float acc[2][4][4];
#pragma unroll
    for (int i = 0; i < 2; i++)
#pragma unroll
        for (int j = 0; j < 4; j++)
#pragma unroll
            for (int r = 0; r < 4; r++) acc[i][j][r] = 0.f;

    int lr = lane & 15, lc8 = (lane & 16) >> 1;
    uint32_t QHb = base;
    uint32_t KHb = base + 17408;

#pragma unroll
    for (int ks = 0; ks < 8; ks++) {
        uint32_t fAH[2][4], fBH[4][2];
#pragma unroll
        for (int mt = 0; mt < 2; mt++) {
            uint32_t ao = (uint32_t)((wm * 32 + mt * 16 + lr) * 136 + ks * 16 + lc8) * 2;
            ldm_x4(fAH[mt], QHb + ao);
        }
#pragma unroll
        for (int half = 0; half < 2; half++) {
            uint32_t bo = (uint32_t)((wn * 32 + half * 16 + lr) * 136 + ks * 16 + lc8) * 2;
            uint32_t rH[4];
            ldm_x4(rH, KHb + bo);
            fBH[half*2][0] = rH[0]; fBH[half*2][1] = rH[2];
            fBH[half*2+1][0] = rH[1]; fBH[half*2+1][1] = rH[3];
        }
#pragma unroll
        for (int mt = 0; mt < 2; mt++)
#pragma unroll
            for (int nt = 0; nt < 4; nt++)
                mma16816(acc[mt][nt], fAH[mt], fBH[nt]);
    }

    const float scale = 0.0883883476483184405f;
    float* out = sc + (size_t)h * Sm * Sm;
#pragma unroll
    for (int mt = 0; mt < 2; mt++) {
        int r1 = row0 + wm * 32 + mt * 16 + gr;
        int r2 = r1 + 8;
#pragma unroll
        for (int nt = 0; nt < 4; nt++) {
            int col = n0 + wn * 32 + nt * 8 + tg * 2;
            *(float2*)(out + (size_t)r1 * Sm + col) =
                make_float2(acc[mt][nt][0] * scale, acc[mt][nt][1] * scale);
            *(float2*)(out + (size_t)r2 * Sm + col) =
                make_float2(acc[mt][nt][2] * scale, acc[mt][nt][3] * scale);
        }
    }
}

// =============== PV via HMMA (causal-truncated, fp16 1-pass) ===============
// stage elems: PH[64][72]@0, VH[64][136]@4608 ; 13312 elems = 26624 B
#define PV_STAGE_B (13312*2)
#define PV_SMEM (2*PV_STAGE_B)

__global__ void __launch_bounds__(256, 2) pv_mma_kernel(
    const __half* __restrict__ ph_, const __half* __restrict__ vh,
    __half* __restrict__ outh)
{
    extern __shared__ __half smb[];
    int h = blockIdx.y;
    int row0 = blockIdx.x * 64;
    int nst = blockIdx.x + 1;
    int kvoff = (h >> 2) * 128;
    int tid = threadIdx.x, lane = tid & 31, wid = tid >> 5;
    int gr = lane >> 2, tg = lane & 3;
    int wm = wid >> 2, wn = wid & 3;
    uint32_t smbase = smem_u32(smb);

    float acc[2][4][4];
#pragma unroll
    for (int i = 0; i < 2; i++)
#pragma unroll
        for (int j = 0; j < 4; j++)
#pragma unroll
            for (int r = 0; r < 4; r++) acc[i][j][r] = 0.f;

    auto copy_stage = [&](int st) {
        uint32_t base = smbase + (uint32_t)(st & 1) * PV_STAGE_B;
        int k0 = st * 64;
#pragma unroll
        for (int it = 0; it < 2; it++) {
            int idx = it * 256 + tid;
            int row = idx >> 3, ch = idx & 7;
            cpa16(base + (uint32_t)(row * 72 + ch * 8) * 2,
                  ph_ + ((size_t)h * Sm + row0 + row) * Sm + k0 + ch * 8);
        }
        {
            uint32_t d0 = base + 4608 * 2;
#pragma unroll
            for (int it = 0; it < 4; it++) {
                int idx = it * 256 + tid;
                int row = idx >> 4, ch = idx & 15;
                cpa16(d0 + (uint32_t)(row * 136 + ch * 8) * 2,
                      vh + (size_t)(k0 + row) * 512 + kvoff + ch * 8);
            }
        }
        CPA_COMMIT();
    };

    copy_stage(0);
    int lr = lane & 15, lc8 = (lane & 16) >> 1;

    for (int st = 0; st < nst; st++) {
        if (st + 1 < nst) { copy_stage(st + 1); CPA_WAIT1(); }
        else              { CPA_WAIT0(); }
        __syncthreads();
        uint32_t base = smbase + (uint32_t)(st & 1) * PV_STAGE_B;
        uint32_t AHb = base;
        uint32_t BHb = base + 9216;
#pragma unroll
        for (int ks = 0; ks < 4; ks++) {
            uint32_t fAH[2][4], fBH[4][2];
#pragma unroll
            for (int mt = 0; mt < 2; mt++) {
                uint32_t ao = (uint32_t)((wm * 32 + mt * 16 + lr) * 72 + ks * 16 + lc8) * 2;
                ldm_x4(fAH[mt], AHb + ao);
            }
#pragma unroll
            for (int half = 0; half < 2; half++) {
                uint32_t bo = (uint32_t)((ks * 16 + lr) * 136 + wn * 32 + half * 16 + lc8) * 2;
                uint32_t rH[4];
                ldm_x4t(rH, BHb + bo);
                fBH[half*2][0] = rH[0]; fBH[half*2][1] = rH[1];
                fBH[half*2+1][0] = rH[2]; fBH[half*2+1][1] = rH[3];
            }
#pragma unroll
            for (int mt = 0; mt < 2; mt++)
#pragma unroll
                for (int nt = 0; nt < 4; nt++)
                    mma16816(acc[mt][nt], fAH[mt], fBH[nt]);
        }
        __syncthreads();
    }

#pragma unroll
    for (int mt = 0; mt < 2; mt++) {
        int r1 = row0 + wm * 32 + mt * 16 + gr;
        int r2 = r1 + 8;
#pragma unroll
        for (int nt = 0; nt < 4; nt++) {
            int col = h * 128 + wn * 32 + nt * 8 + tg * 2;
            __half2 hh1 = __floats2half2_rn(acc[mt][nt][0], acc[mt][nt][1]);
            __half2 hh2 = __floats2half2_rn(acc[mt][nt][2], acc[mt][nt][3]);
            *(__half2*)(outh + (size_t)r1 * 2048 + col) = hh1;
            *(__half2*)(outh + (size_t)r2 * 2048 + col) = hh2;
        }
    }
}

// ---------------- small kernels ----------------
__global__ void rmsnorm_kernel(const float* __restrict__ in, const float* __restrict__ w,
                               float* __restrict__ outf, __half* __restrict__ outh) {
    int t = blockIdx.x;
    const float* row = in + (size_t)t * Dm;
    float s = 0.f;
    for (int d = threadIdx.x; d < Dm; d += 256) { float v = row[d]; s += v * v; }
    __shared__ float red[256];
    red[threadIdx.x] = s; __syncthreads();
    for (int off = 128; off > 0; off >>= 1) {
        if (threadIdx.x < off) red[threadIdx.x] += red[threadIdx.x + off];
        __syncthreads();
    }
    float r = rsqrtf(red[0] / (float)Dm + 1e-5f);
    for (int d = threadIdx.x; d < Dm; d += 256) {
        float v = row[d] * r * w[d];
        if (outf) outf[(size_t)t * Dm + d] = v;
        outh[(size_t)t * Dm + d] = __float2half_rn(v);
    }
}

// log2(500000)/64
#define ROPE_C 0.29580575889569022f

__global__ void rope_planes_kernel(const float* __restrict__ qkv, const int* __restrict__ pos_ids,
                                   __half* qh, __half* kh, __half* vh) {
    int t = blockIdx.x;
    float p = (float)pos_ids[t];
    for (int idx = threadIdx.x; idx < (Hn + HKVn) * 64; idx += blockDim.x) {
        int head = idx >> 6;
        int i = idx & 63;
        float inv = exp2f(-(float)i * ROPE_C);
        float f = p * inv;
        float sn, cs;
        sincosf(f, &sn, &cs);
        if (head < Hn) {
            const float* src = qkv + (size_t)t * QKVP + head * DHn;
            float x1 = src[i], x2 = src[i + 64];
            size_t d = (size_t)t * Dm + head * DHn + i;
            qh[d]      = __float2half_rn(x1 * cs - x2 * sn);
            qh[d + 64] = __float2half_rn(x2 * cs + x1 * sn);
        } else {
            int kvh = head - Hn;
            const float* src = qkv + (size_t)t * QKVP + 2048 + kvh * DHn;
            float x1 = src[i], x2 = src[i + 64];
            size_t d = (size_t)t * 512 + kvh * DHn + i;
            kh[d]      = __float2half_rn(x1 * cs - x2 * sn);
            kh[d + 64] = __float2half_rn(x2 * cs + x1 * sn);
        }
    }
    for (int idx = threadIdx.x; idx < 512; idx += blockDim.x) {
        vh[(size_t)t * 512 + idx] = __float2half_rn(qkv[(size_t)t * QKVP + 2560 + idx]);
    }
}

__global__ void softmax_kernel(const float* __restrict__ sc, const int* __restrict__ mask,
                               __half* __restrict__ ph) {
    int i = blockIdx.x;
    int h = blockIdx.y;
    int row_end = (i & ~63) + 64;
    const float* row = sc + ((size_t)h * Sm + i) * Sm;
    int tid = threadIdx.x;
    int j0 = tid, j1 = tid + 256;
    float s0 = (j0 <= i && mask[j0] > 0) ? row[j0] : -1e9f;
    float s1 = (j1 <= i && mask[j1] > 0) ? row[j1] : -1e9f;
    __shared__ float red[256];
    red[tid] = fmaxf(s0, s1); __syncthreads();
    for (int off = 128; off > 0; off >>= 1) {
        if (tid < off) red[tid] = fmaxf(red[tid], red[tid + off]);
        __syncthreads();
    }
    float m = red[0];
    __syncthreads();
    float e0 = expf(s0 - m), e1 = expf(s1 - m);
    red[tid] = e0 + e1; __syncthreads();
    for (int off = 128; off > 0; off >>= 1) {
        if (tid < off) red[tid] += red[tid + off];
        __syncthreads();
    }
    float inv = 1.f / red[0];
    size_t base = ((size_t)h * Sm + i) * Sm;
    if (j0 < row_end) ph[base + j0] = __float2half_rn(e0 * inv);
    if (j1 < row_end) ph[base + j1] = __float2half_rn(e1 * inv);
}

__global__ void router_kernel(const float* __restrict__ x2, const float* __restrict__ rw,
                              int* __restrict__ topidx, float* __restrict__ topscore) {
    int t = blockIdx.x;
    int w = threadIdx.x >> 5, lane = threadIdx.x & 31;
    float s = 0.f;
    for (int d = lane; d < Dm; d += 32)
        s += x2[(size_t)t * Dm + d] * rw[d * En + w];
    for (int off = 16; off; off >>= 1) s += __shfl_down_sync(0xffffffff, s, off);
    __shared__ float logits[En];
    if (lane == 0) logits[w] = s;
    __syncthreads();
    if (threadIdx.x == 0) {
        int best = 0; float bv = logits[0];
        for (int e = 1; e < En; e++) if (logits[e] > bv) { bv = logits[e]; best = e; }
        topidx[t] = best;
        topscore[t] = 1.f / (1.f + expf(-bv));
    }
}

__global__ void dispatch_kernel(const int* __restrict__ topidx) {
    int t = threadIdx.x;
    if (t < En) g_cnt[t] = 0;
    __syncthreads();
    int e = topidx[t];
    int pos = atomicAdd(&g_cnt[e], 1);
    g_list[e * Sm + pos] = t;
}

// combined silu-mul for expert gu and shared sgu
__global__ void silumul2_kernel(const float* __restrict__ gu, const float* __restrict__ sgu,
                                __half* __restrict__ ah, __half* __restrict__ sh) {
    int i = blockIdx.x * 256 + threadIdx.x;
    const float* src = gu;
    __half* oh = ah;
    int j = i;
    if (i >= Sm * Dm) {
        j = i - Sm * Dm;
        src = sgu; oh = sh;
    }
    int t = j >> 11, c = j & 2047;
    float g = src[(size_t)t * 4096 + c];
    float u = src[(size_t)t * 4096 + 2048 + c];
    float a = (g / (1.f + expf(-g))) * u;
    oh[j] = __float2half_rn(a);
}

__global__ void add3_kernel(const float* __restrict__ a, const float* __restrict__ b,
                            const float* __restrict__ c, float* __restrict__ out) {
    int i = blockIdx.x * 256 + threadIdx.x;
    out[i] = a[i] + b[i] + c[i];
}

// ---------------- launch ----------------
#define GSYM(p, s) cudaGetSymbolAddress((void**)&p, s)
#define NSBIG 0x40000000

extern "C" void kernel_launch(void* const* d_in, const int* in_sizes, int n_in,
                              void* d_out, int out_size) {
    const float* hidden   = (const float*)d_in[0];
    const int*   amask    = (const int*)  d_in[1];
    const int*   pos      = (const int*)  d_in[2];
    const float* attn_nw  = (const float*)d_in[3];
    const float* wq       = (const float*)d_in[4];
    const float* wk       = (const float*)d_in[5];
    const float* wv       = (const float*)d_in[6];
    const float* wo       = (const float*)d_in[7];
    const float* ffn_nw   = (const float*)d_in[8];
    const float* router_w = (const float*)d_in[9];
    const float* w_gate   = (const float*)d_in[10];
    const float* w_up     = (const float*)d_in[11];
    const float* w_down   = (const float*)d_in[12];
    const float* ws_gate  = (const float*)d_in[13];
    const float* ws_up    = (const float*)d_in[14];
    const float* ws_down  = (const float*)d_in[15];
    float* out = (float*)d_out;

    float *pqkv, *psc, *phf, *px2f, *pgu, *psgu, *prouted, *pshared, *pts;
    int *pti;
    __half *pxh, *path, *px2h, *pach, *psah, *pqh, *pkh, *pvh, *pph;
    GSYM(pqkv, g_qkv); GSYM(psc, g_scores); GSYM(phf, g_h); GSYM(px2f, g_x2f);
    GSYM(pgu, g_gu); GSYM(psgu, g_sgu); GSYM(prouted, g_routed); GSYM(pshared, g_shared);
    GSYM(pti, g_topidx); GSYM(pts, g_topscore);
    GSYM(pxh, x_h); GSYM(path, at_h); GSYM(px2h, x2_h); GSYM(pach, ac_h); GSYM(psah, sa_h);
    GSYM(pqh, q_h); GSYM(pkh, k_h); GSYM(pvh, v_h); GSYM(pph, p_h);

    cudaFuncSetAttribute(tgemm_kernel, cudaFuncAttributeMaxDynamicSharedMemorySize, TG_SMEM);
    cudaFuncSetAttribute(scores_mma_kernel, cudaFuncAttributeMaxDynamicSharedMemorySize, SC_SMEM);
    cudaFuncSetAttribute(pv_mma_kernel, cudaFuncAttributeMaxDynamicSharedMemorySize, PV_SMEM);

    // --- attention block ---
    rmsnorm_kernel<<<Sm, 256>>>(hidden, attn_nw, nullptr, pxh);
    tgemm_kernel<<<dim3(24, 8), 256, TG_SMEM>>>(pxh, wq, wk, wv,
                                                2048, 512, 512, 2048, 2560,
                                                pqkv, 3072, nullptr, nullptr, 0,
                                                nullptr, nullptr, nullptr, nullptr);
    rope_planes_kernel<<<Sm, 256>>>(pqkv, pos, pqh, pkh, pvh);
    scores_mma_kernel<<<dim3(4, 8, Hn), 256, SC_SMEM>>>(pqh, pkh, psc);
    softmax_kernel<<<dim3(Sm, Hn), 256>>>(psc, amask, pph);
    pv_mma_kernel<<<dim3(8, Hn), 256, PV_SMEM>>>(pph, pvh, path);
    tgemm_kernel<<<dim3(16, 8), 256, TG_SMEM>>>(path, wo, nullptr, nullptr,
                                                2048, 0, 0, NSBIG, NSBIG,
                                                phf, 2048, hidden, nullptr, 0,
                                                nullptr, nullptr, nullptr, nullptr);

    // --- MoE block ---
    rmsnorm_kernel<<<Sm, 256>>>(phf, ffn_nw, px2f, px2h);
    router_kernel<<<Sm, 256>>>(px2f, router_w, pti, pts);
    dispatch_kernel<<<1, Sm>>>(pti);
    tgemm_kernel<<<dim3(32, 8, En + 1), 256, TG_SMEM>>>(px2h, w_gate, w_up, nullptr,
                                                        2048, 2048, 0, 2048, NSBIG,
                                                        pgu, 4096, nullptr, pts, 1,
                                                        px2h, ws_gate, ws_up, psgu);
    silumul2_kernel<<<(2 * Sm * Dm) / 256, 256>>>(pgu, psgu, pach, psah);
    tgemm_kernel<<<dim3(16, 8, En + 1), 256, TG_SMEM>>>(pach, w_down, nullptr, nullptr,
                                                        2048, 0, 0, NSBIG, NSBIG,
                                                        prouted, 2048, nullptr, nullptr, 1,
                                                        psah, ws_down, nullptr, pshared);

    // final: out = h + routed + shared
    add3_kernel<<<(Sm * Dm) / 256, 256>>>(phf, prouted, pshared, out);
}